// round 1
// baseline (speedup 1.0000x reference)
#include <cuda_runtime.h>

#define NN 89250
#define NE 899756
#define F0 500
#define HID 256
#define NC  7

// ---------------- scratch (device globals; no allocation allowed) ----------
__device__ float g_agg1[(size_t)NN * F0];   // 178.5 MB
__device__ float g_x1[(size_t)NN * HID];
__device__ float g_agg2[(size_t)NN * HID];  // reused for layer 3
__device__ float g_x2[(size_t)NN * HID];
__device__ float g_x3[(size_t)NN * HID];
__device__ float g_cnt[NN];
__device__ float g_inv[NN];

// ---------------- utility: zero a float buffer (float4, grid-stride) -------
__global__ void zero_f4(float4* p, int n4) {
    int i = blockIdx.x * blockDim.x + threadIdx.x;
    int stride = gridDim.x * blockDim.x;
    float4 z = make_float4(0.f, 0.f, 0.f, 0.f);
    for (; i < n4; i += stride) p[i] = z;
}

// ---------------- in-degree counts --------------------------------------
__global__ void count_kernel(const int* __restrict__ dst) {
    int e = blockIdx.x * blockDim.x + threadIdx.x;
    if (e < NE) atomicAdd(&g_cnt[dst[e]], 1.0f);   // no return use -> RED
}

__global__ void inv_kernel() {
    int i = blockIdx.x * blockDim.x + threadIdx.x;
    if (i < NN) g_inv[i] = 1.0f / fmaxf(g_cnt[i], 1.0f);
}

// ---------------- edge scatter: agg[dst] += x[src] * w ---------------------
// One warp per edge; vectorized global reductions (red.global.add.v4.f32).
__global__ void scatter_kernel(const float* __restrict__ X, int F4,
                               const int* __restrict__ src,
                               const int* __restrict__ dst,
                               const float* __restrict__ ew,
                               float* __restrict__ agg) {
    int gw   = (blockIdx.x * blockDim.x + threadIdx.x) >> 5;
    int lane = threadIdx.x & 31;
    if (gw >= NE) return;
    int s = src[gw], d = dst[gw];
    float w = ew[gw];
    const float4* xs = (const float4*)X + (size_t)s * F4;
    float4*       ag = (float4*)agg     + (size_t)d * F4;
    for (int i = lane; i < F4; i += 32) {
        float4 v = xs[i];
        v.x *= w; v.y *= w; v.z *= w; v.w *= w;
        asm volatile("red.global.add.v4.f32 [%0], {%1, %2, %3, %4};"
                     :: "l"(ag + i), "f"(v.x), "f"(v.y), "f"(v.z), "f"(v.w)
                     : "memory");
    }
}

// ---------------- fused SAGE GEMM ------------------------------------------
// OUT[m, 0:256] = act( [X[m,:K1] | AGG[m,:K2]*inv_cnt[m]] @ W[(K1+K2)x256] + b )
// Tile 64x64x16, 256 threads, 4x4 per-thread microtile.
__global__ __launch_bounds__(256)
void sage_gemm(const float* __restrict__ X, int K1,
               const float* __restrict__ AGG, int K2,
               const float* __restrict__ W,
               const float* __restrict__ bias,
               float* __restrict__ OUT, int do_relu) {
    const int KT = K1 + K2;
    __shared__ float As[16][65];   // pad to kill bank conflicts
    __shared__ float Bs[16][64];

    int tid = threadIdx.x;
    int tx = tid & 15;        // 0..15 -> 4 output cols each
    int ty = tid >> 4;        // 0..15 -> 4 output rows each
    int bm = blockIdx.y * 64;
    int bn = blockIdx.x * 64;

    // A-load mapping: k = tid%16 (coalesced within row), m = tid/16 (+16*i)
    int la_k = tid & 15;
    int la_m = tid >> 4;
    // B-load mapping: n = tid%64 (coalesced), k = tid/64 (+4*i)
    int lb_n = tid & 63;
    int lb_k = tid >> 6;

    float acc[4][4];
#pragma unroll
    for (int i = 0; i < 4; i++)
#pragma unroll
        for (int j = 0; j < 4; j++) acc[i][j] = 0.f;

    for (int k0 = 0; k0 < KT; k0 += 16) {
#pragma unroll
        for (int i = 0; i < 4; i++) {
            int m = bm + la_m + i * 16;
            int k = k0 + la_k;
            float v = 0.f;
            if (m < NN && k < KT) {
                if (k < K1) v = X[(size_t)m * K1 + k];
                else        v = AGG[(size_t)m * K2 + (k - K1)] * g_inv[m];
            }
            As[la_k][la_m + i * 16] = v;
        }
#pragma unroll
        for (int i = 0; i < 4; i++) {
            int k = k0 + lb_k + i * 4;
            Bs[lb_k + i * 4][lb_n] = (k < KT) ? W[(size_t)k * 256 + bn + lb_n] : 0.f;
        }
        __syncthreads();
#pragma unroll
        for (int kk = 0; kk < 16; kk++) {
            float a[4], b[4];
#pragma unroll
            for (int i = 0; i < 4; i++) a[i] = As[kk][ty * 4 + i];
#pragma unroll
            for (int j = 0; j < 4; j++) b[j] = Bs[kk][tx * 4 + j];
#pragma unroll
            for (int i = 0; i < 4; i++)
#pragma unroll
                for (int j = 0; j < 4; j++) acc[i][j] += a[i] * b[j];
        }
        __syncthreads();
    }

#pragma unroll
    for (int i = 0; i < 4; i++) {
        int m = bm + ty * 4 + i;
        if (m >= NN) continue;
#pragma unroll
        for (int j = 0; j < 4; j++) {
            int n = bn + tx * 4 + j;
            float v = acc[i][j] + bias[n];
            if (do_relu) v = fmaxf(v, 0.f);
            OUT[(size_t)m * 256 + n] = v;
        }
    }
}

// ---------------- head: logits = [x1|x2|x3] @ Wl + bl, log_softmax ---------
// One warp per node; Wl staged in smem.
__global__ __launch_bounds__(256)
void head_kernel(const float* __restrict__ Wl, const float* __restrict__ bl,
                 float* __restrict__ out) {
    __shared__ float sW[768 * NC];
    int tid = threadIdx.x;
    for (int i = tid; i < 768 * NC; i += blockDim.x) sW[i] = Wl[i];
    __syncthreads();

    int lane = tid & 31;
    int node = blockIdx.x * (blockDim.x >> 5) + (tid >> 5);
    if (node >= NN) return;

    const float* h1 = g_x1 + (size_t)node * HID;
    const float* h2 = g_x2 + (size_t)node * HID;
    const float* h3 = g_x3 + (size_t)node * HID;

    float acc[NC];
#pragma unroll
    for (int c = 0; c < NC; c++) acc[c] = 0.f;

    for (int k = lane; k < HID; k += 32) {
        float v1 = h1[k], v2 = h2[k], v3 = h3[k];
#pragma unroll
        for (int c = 0; c < NC; c++)
            acc[c] += v1 * sW[k * NC + c]
                    + v2 * sW[(HID + k) * NC + c]
                    + v3 * sW[(2 * HID + k) * NC + c];
    }
#pragma unroll
    for (int c = 0; c < NC; c++)
        for (int off = 16; off > 0; off >>= 1)
            acc[c] += __shfl_down_sync(0xffffffffu, acc[c], off);

    if (lane == 0) {
        float lg[NC], mx = -1e30f;
#pragma unroll
        for (int c = 0; c < NC; c++) { lg[c] = acc[c] + bl[c]; mx = fmaxf(mx, lg[c]); }
        float s = 0.f;
#pragma unroll
        for (int c = 0; c < NC; c++) s += expf(lg[c] - mx);
        float lse = mx + logf(s);
#pragma unroll
        for (int c = 0; c < NC; c++) out[(size_t)node * NC + c] = lg[c] - lse;
    }
}

// ---------------------------------------------------------------------------
extern "C" void kernel_launch(void* const* d_in, const int* in_sizes, int n_in,
                              void* d_out, int out_size) {
    const float* x  = (const float*)d_in[0];
    const int*   ei = (const int*)d_in[1];          // [2, E]: src then dst
    const float* ew = (const float*)d_in[2];
    const float* W1 = (const float*)d_in[3];
    const float* b1 = (const float*)d_in[4];
    const float* W2 = (const float*)d_in[5];
    const float* b2 = (const float*)d_in[6];
    const float* W3 = (const float*)d_in[7];
    const float* b3 = (const float*)d_in[8];
    const float* Wl = (const float*)d_in[9];
    const float* bl = (const float*)d_in[10];
    float* out = (float*)d_out;

    const int* src = ei;
    const int* dst = ei + NE;

    float *agg1, *x1, *agg2, *x2, *x3, *cnt;
    cudaGetSymbolAddress((void**)&agg1, g_agg1);
    cudaGetSymbolAddress((void**)&x1,   g_x1);
    cudaGetSymbolAddress((void**)&agg2, g_agg2);
    cudaGetSymbolAddress((void**)&x2,   g_x2);
    cudaGetSymbolAddress((void**)&x3,   g_x3);
    cudaGetSymbolAddress((void**)&cnt,  g_cnt);

    const int ZB = 4096, ZT = 256;
    const int scat_blocks = (NE + 7) / 8;      // 8 warps/block, 1 warp/edge
    dim3 gemm_grid(4, (NN + 63) / 64);

    // degree counts (recomputed every launch; determinism requirement)
    zero_f4<<<(NN / 4 + ZT) / ZT, ZT>>>((float4*)cnt, NN / 2);   // NN not /4-exact: zero via scalar-safe count below
    // NN=89250 is not divisible by 4 for float4; zero exactly with a scalar pass:
    // (cheap; NN floats)
    {
        // scalar zero for cnt
        // reuse zero_f4 on the 89248 aligned part then fix tail is overkill; NN*4 bytes = 357KB
    }
    // NOTE: zero cnt precisely using a dedicated launch:
    // (implemented below with zero_f4 over padded even length is unsafe; use memset-style kernel)
    // -- replaced: see zero_tail usage.

    // exact zero of cnt: NN floats -> 22312 float4 covers 89248, plus 2 tail floats.
    // g_cnt is followed by g_inv in no guaranteed order, so do a clean scalar kernel:
    extern __global__ void zero_scalar(float*, int);
    zero_scalar<<<(NN + ZT - 1) / ZT, ZT>>>(cnt, NN);
    count_kernel<<<(NE + ZT - 1) / ZT, ZT>>>(dst);
    inv_kernel<<<(NN + ZT - 1) / ZT, ZT>>>();

    // ---- layer 1 ----
    zero_f4<<<ZB, ZT>>>((float4*)agg1, NN * F0 / 4);
    scatter_kernel<<<scat_blocks, 256>>>(x, F0 / 4, src, dst, ew, agg1);
    sage_gemm<<<gemm_grid, 256>>>(x, F0, agg1, F0, W1, b1, x1, 1);

    // ---- layer 2 ----
    zero_f4<<<ZB, ZT>>>((float4*)agg2, NN * HID / 4);
    scatter_kernel<<<scat_blocks, 256>>>(x1, HID / 4, src, dst, ew, agg2);
    sage_gemm<<<gemm_grid, 256>>>(x1, HID, agg2, HID, W2, b2, x2, 1);

    // ---- layer 3 (reuse agg2) ----
    zero_f4<<<ZB, ZT>>>((float4*)agg2, NN * HID / 4);
    scatter_kernel<<<scat_blocks, 256>>>(x2, HID / 4, src, dst, ew, agg2);
    sage_gemm<<<gemm_grid, 256>>>(x2, HID, agg2, HID, W3, b3, x3, 1);

    // ---- head ----
    head_kernel<<<(NN + 7) / 8, 256>>>(Wl, bl, out);
}

// scalar zero helper (declared above with C++ linkage via extern decl)
__global__ void zero_scalar(float* p, int n) {
    int i = blockIdx.x * blockDim.x + threadIdx.x;
    if (i < n) p[i] = 0.f;
}

// round 2
// speedup vs baseline: 3.1036x; 3.1036x over previous
#include <cuda_runtime.h>
#include <cstdint>

#define NN 89250
#define NE 899756
#define F0 500
#define HID 256
#define NC  7

// ---------------- scratch (device globals) ---------------------------------
__device__ float g_h1[(size_t)NN * HID];   // pre-relu layer outputs
__device__ float g_h2[(size_t)NN * HID];
__device__ float g_h3[(size_t)NN * HID];
__device__ float g_q [(size_t)NN * HID];   // Q = act(x) @ W_bot (reused per layer)
__device__ float g_cnt[NN];
__device__ float g_inv[NN];
__device__ float g_wp[NE];                 // w' = ew * inv_cnt[dst]

// ---------------- small prep kernels ----------------------------------------
__global__ void zero_scalar(float* p, int n) {
    int i = blockIdx.x * blockDim.x + threadIdx.x;
    if (i < n) p[i] = 0.f;
}
__global__ void count_kernel(const int* __restrict__ dst) {
    int e = blockIdx.x * blockDim.x + threadIdx.x;
    if (e < NE) atomicAdd(&g_cnt[dst[e]], 1.0f);
}
__global__ void inv_kernel() {
    int i = blockIdx.x * blockDim.x + threadIdx.x;
    if (i < NN) g_inv[i] = 1.0f / fmaxf(g_cnt[i], 1.0f);
}
__global__ void wp_kernel(const float* __restrict__ ew, const int* __restrict__ dst) {
    int e = blockIdx.x * blockDim.x + threadIdx.x;
    if (e < NE) g_wp[e] = ew[e] * g_inv[dst[e]];
}

// ---------------- TF32 MMA helpers ------------------------------------------
__device__ __forceinline__ uint32_t f2tf(float f) {
    uint32_t r;
    asm("cvt.rna.tf32.f32 %0, %1;" : "=r"(r) : "f"(f));
    return r;
}
__device__ __forceinline__ void mma_tf32(float c[4], const uint32_t a[4], const uint32_t b[2]) {
    asm volatile(
        "mma.sync.aligned.m16n8k8.row.col.f32.tf32.tf32.f32 "
        "{%0,%1,%2,%3}, {%4,%5,%6,%7}, {%8,%9}, {%0,%1,%2,%3};"
        : "+f"(c[0]), "+f"(c[1]), "+f"(c[2]), "+f"(c[3])
        : "r"(a[0]), "r"(a[1]), "r"(a[2]), "r"(a[3]), "r"(b[0]), "r"(b[1]));
}

// ---------------- fused SAGE GEMM (tf32 tensor cores) -----------------------
// grid.x = 4 (two 128-col blocks of P, two of Q), grid.y = ceil(NN/128).
// P path: ACC[m, 0:256] = act_in(A)[m,:] @ W[0:K, :] + bias
// Q path: Q  [m, 0:256] = act_in(A)[m,:] @ W[K:2K, :]
// Block tile 128x128x16, 8 warps, warp tile 64x32 (4x4 m16n8k8 tiles).
__global__ __launch_bounds__(256)
void gemm_sage(const float* __restrict__ A, int K, int lda, int relu_in,
               const float* __restrict__ W, const float* __restrict__ bias,
               float* __restrict__ ACC, float* __restrict__ Q)
{
    __shared__ uint32_t As[2][128][20];   // [m][k], stride 20 -> conflict-free frags
    __shared__ uint32_t Bs[2][16][136];   // [k][n], stride 136 -> conflict-free frags

    const int bx = blockIdx.x;
    const int bm = blockIdx.y * 128;
    const bool accPath = (bx < 2);
    const int nb = (bx & 1) * 128;                     // col offset within 256
    const float* Wbase = accPath ? W : W + (size_t)K * 256;

    const int tid  = threadIdx.x;
    const int wid  = tid >> 5;
    const int lane = tid & 31;
    const int wm = (wid >> 2) * 64;                    // 0, 64
    const int wn = (wid & 3) * 32;                     // 0,32,64,96
    const int r0 = lane >> 2, c0 = lane & 3;

    // gmem load mapping (float4 granularity)
    const int a_r = tid >> 2;                          // 0..63 (+64 on 2nd)
    const int a_c = (tid & 3) * 4;
    const int b_k = tid >> 5;                          // 0..7 (+8 on 2nd)
    const int b_n = (tid & 31) * 4;

    const int KT = (K + 15) / 16;

    float acc[4][4][4];
#pragma unroll
    for (int mi = 0; mi < 4; mi++)
#pragma unroll
        for (int ni = 0; ni < 4; ni++)
#pragma unroll
            for (int c = 0; c < 4; c++) acc[mi][ni][c] = 0.f;

    float4 ra[2], rb[2];

    // ---- prologue: load tile 0 ----
#pragma unroll
    for (int p = 0; p < 2; p++) {
        int row = bm + a_r + p * 64;
        float4 v = make_float4(0.f, 0.f, 0.f, 0.f);
        if (row < NN && a_c < K) v = *(const float4*)(A + (size_t)row * lda + a_c);
        if (relu_in) { v.x = fmaxf(v.x, 0.f); v.y = fmaxf(v.y, 0.f);
                       v.z = fmaxf(v.z, 0.f); v.w = fmaxf(v.w, 0.f); }
        ra[p] = v;
        int kk = b_k + p * 8;
        float4 w = make_float4(0.f, 0.f, 0.f, 0.f);
        if (kk < K) w = *(const float4*)(Wbase + (size_t)kk * 256 + nb + b_n);
        rb[p] = w;
    }
#pragma unroll
    for (int p = 0; p < 2; p++) {
        int row = a_r + p * 64;
        As[0][row][a_c + 0] = f2tf(ra[p].x); As[0][row][a_c + 1] = f2tf(ra[p].y);
        As[0][row][a_c + 2] = f2tf(ra[p].z); As[0][row][a_c + 3] = f2tf(ra[p].w);
        int k = b_k + p * 8;
        Bs[0][k][b_n + 0] = f2tf(rb[p].x); Bs[0][k][b_n + 1] = f2tf(rb[p].y);
        Bs[0][k][b_n + 2] = f2tf(rb[p].z); Bs[0][k][b_n + 3] = f2tf(rb[p].w);
    }
    __syncthreads();

    int buf = 0;
    for (int kt = 0; kt < KT; kt++) {
        // prefetch next tile into regs
        if (kt + 1 < KT) {
            int k0 = (kt + 1) * 16;
#pragma unroll
            for (int p = 0; p < 2; p++) {
                int row = bm + a_r + p * 64;
                int col = k0 + a_c;
                float4 v = make_float4(0.f, 0.f, 0.f, 0.f);
                if (row < NN && col < K) v = *(const float4*)(A + (size_t)row * lda + col);
                if (relu_in) { v.x = fmaxf(v.x, 0.f); v.y = fmaxf(v.y, 0.f);
                               v.z = fmaxf(v.z, 0.f); v.w = fmaxf(v.w, 0.f); }
                ra[p] = v;
                int kk = k0 + b_k + p * 8;
                float4 w = make_float4(0.f, 0.f, 0.f, 0.f);
                if (kk < K) w = *(const float4*)(Wbase + (size_t)kk * 256 + nb + b_n);
                rb[p] = w;
            }
        }
        // compute on smem[buf]
#pragma unroll
        for (int ks = 0; ks < 2; ks++) {
            const int k8 = ks * 8;
            uint32_t af[4][4], bf[4][2];
#pragma unroll
            for (int mi = 0; mi < 4; mi++) {
                int row = wm + mi * 16 + r0;
                af[mi][0] = As[buf][row    ][k8 + c0    ];
                af[mi][1] = As[buf][row + 8][k8 + c0    ];
                af[mi][2] = As[buf][row    ][k8 + c0 + 4];
                af[mi][3] = As[buf][row + 8][k8 + c0 + 4];
            }
#pragma unroll
            for (int ni = 0; ni < 4; ni++) {
                int col = wn + ni * 8 + r0;
                bf[ni][0] = Bs[buf][k8 + c0    ][col];
                bf[ni][1] = Bs[buf][k8 + c0 + 4][col];
            }
#pragma unroll
            for (int mi = 0; mi < 4; mi++)
#pragma unroll
                for (int ni = 0; ni < 4; ni++)
                    mma_tf32(acc[mi][ni], af[mi], bf[ni]);
        }
        // commit prefetched tile
        if (kt + 1 < KT) {
            int nbuf = buf ^ 1;
#pragma unroll
            for (int p = 0; p < 2; p++) {
                int row = a_r + p * 64;
                As[nbuf][row][a_c + 0] = f2tf(ra[p].x); As[nbuf][row][a_c + 1] = f2tf(ra[p].y);
                As[nbuf][row][a_c + 2] = f2tf(ra[p].z); As[nbuf][row][a_c + 3] = f2tf(ra[p].w);
                int k = b_k + p * 8;
                Bs[nbuf][k][b_n + 0] = f2tf(rb[p].x); Bs[nbuf][k][b_n + 1] = f2tf(rb[p].y);
                Bs[nbuf][k][b_n + 2] = f2tf(rb[p].z); Bs[nbuf][k][b_n + 3] = f2tf(rb[p].w);
            }
            __syncthreads();
            buf = nbuf;
        }
    }

    // ---- epilogue ----
#pragma unroll
    for (int mi = 0; mi < 4; mi++) {
#pragma unroll
        for (int ci = 0; ci < 2; ci++) {
            int row = bm + wm + mi * 16 + r0 + ci * 8;
            if (row >= NN) continue;
#pragma unroll
            for (int ni = 0; ni < 4; ni++) {
                int col = nb + wn + ni * 8 + c0 * 2;
                float2 v;
                v.x = acc[mi][ni][ci * 2 + 0];
                v.y = acc[mi][ni][ci * 2 + 1];
                if (accPath) {
                    v.x += bias[col]; v.y += bias[col + 1];
                    *(float2*)(ACC + (size_t)row * 256 + col) = v;
                } else {
                    *(float2*)(Q + (size_t)row * 256 + col) = v;
                }
            }
        }
    }
}

// ---------------- edge scatter: ACC[dst] += Q[src] * w' ---------------------
__global__ __launch_bounds__(256)
void scatter256(const float* __restrict__ Q,
                const int* __restrict__ src, const int* __restrict__ dst,
                float* __restrict__ ACC) {
    int gw   = (blockIdx.x * blockDim.x + threadIdx.x) >> 5;
    int lane = threadIdx.x & 31;
    if (gw >= NE) return;
    int s = src[gw], d = dst[gw];
    float w = g_wp[gw];
    const float4* qs = (const float4*)Q + (size_t)s * 64;
    float4*       ac = (float4*)ACC     + (size_t)d * 64;
#pragma unroll
    for (int i = 0; i < 2; i++) {
        float4 v = qs[lane + i * 32];
        v.x *= w; v.y *= w; v.z *= w; v.w *= w;
        asm volatile("red.global.add.v4.f32 [%0], {%1, %2, %3, %4};"
                     :: "l"(ac + lane + i * 32), "f"(v.x), "f"(v.y), "f"(v.z), "f"(v.w)
                     : "memory");
    }
}

// ---------------- head: logits = [relu(h1)|relu(h2)|relu(h3)] @ Wl + bl -----
__global__ __launch_bounds__(256)
void head_kernel(const float* __restrict__ Wl, const float* __restrict__ bl,
                 float* __restrict__ out) {
    __shared__ float sW[768 * NC];
    int tid = threadIdx.x;
    for (int i = tid; i < 768 * NC; i += blockDim.x) sW[i] = Wl[i];
    __syncthreads();

    int lane = tid & 31;
    int node = blockIdx.x * (blockDim.x >> 5) + (tid >> 5);
    if (node >= NN) return;

    const float* h1 = g_h1 + (size_t)node * HID;
    const float* h2 = g_h2 + (size_t)node * HID;
    const float* h3 = g_h3 + (size_t)node * HID;

    float acc[NC];
#pragma unroll
    for (int c = 0; c < NC; c++) acc[c] = 0.f;

    for (int k = lane; k < HID; k += 32) {
        float v1 = fmaxf(h1[k], 0.f), v2 = fmaxf(h2[k], 0.f), v3 = fmaxf(h3[k], 0.f);
#pragma unroll
        for (int c = 0; c < NC; c++)
            acc[c] += v1 * sW[k * NC + c]
                    + v2 * sW[(HID + k) * NC + c]
                    + v3 * sW[(2 * HID + k) * NC + c];
    }
#pragma unroll
    for (int c = 0; c < NC; c++)
        for (int off = 16; off > 0; off >>= 1)
            acc[c] += __shfl_down_sync(0xffffffffu, acc[c], off);

    if (lane == 0) {
        float lg[NC], mx = -1e30f;
#pragma unroll
        for (int c = 0; c < NC; c++) { lg[c] = acc[c] + bl[c]; mx = fmaxf(mx, lg[c]); }
        float s = 0.f;
#pragma unroll
        for (int c = 0; c < NC; c++) s += expf(lg[c] - mx);
        float lse = mx + logf(s);
#pragma unroll
        for (int c = 0; c < NC; c++) out[(size_t)node * NC + c] = lg[c] - lse;
    }
}

// ---------------------------------------------------------------------------
extern "C" void kernel_launch(void* const* d_in, const int* in_sizes, int n_in,
                              void* d_out, int out_size) {
    const float* x  = (const float*)d_in[0];
    const int*   ei = (const int*)d_in[1];          // [2, E]: src then dst
    const float* ew = (const float*)d_in[2];
    const float* W1 = (const float*)d_in[3];
    const float* b1 = (const float*)d_in[4];
    const float* W2 = (const float*)d_in[5];
    const float* b2 = (const float*)d_in[6];
    const float* W3 = (const float*)d_in[7];
    const float* b3 = (const float*)d_in[8];
    const float* Wl = (const float*)d_in[9];
    const float* bl = (const float*)d_in[10];
    float* out = (float*)d_out;

    const int* src = ei;
    const int* dst = ei + NE;

    float *h1, *h2, *h3, *q, *cnt;
    cudaGetSymbolAddress((void**)&h1,  g_h1);
    cudaGetSymbolAddress((void**)&h2,  g_h2);
    cudaGetSymbolAddress((void**)&h3,  g_h3);
    cudaGetSymbolAddress((void**)&q,   g_q);
    cudaGetSymbolAddress((void**)&cnt, g_cnt);

    const int T = 256;
    const int scat_blocks = (NE + 7) / 8;          // 1 warp/edge, 8 warps/block
    dim3 gemm_grid(4, (NN + 127) / 128);

    // edge-weight prep (w' = ew / max(cnt,1) at dst)
    zero_scalar<<<(NN + T - 1) / T, T>>>(cnt, NN);
    count_kernel<<<(NE + T - 1) / T, T>>>(dst);
    inv_kernel<<<(NN + T - 1) / T, T>>>();
    wp_kernel<<<(NE + T - 1) / T, T>>>(ew, dst);

    // layer 1: [P|Q] = x @ [W1_top|W1_bot]; ACC=h1 init P+b1; scatter Q
    gemm_sage<<<gemm_grid, T>>>(x, F0, F0, 0, W1, b1, h1, q);
    scatter256<<<scat_blocks, T>>>(q, src, dst, h1);

    // layer 2: A = relu(h1)
    gemm_sage<<<gemm_grid, T>>>(h1, HID, HID, 1, W2, b2, h2, q);
    scatter256<<<scat_blocks, T>>>(q, src, dst, h2);

    // layer 3: A = relu(h2)
    gemm_sage<<<gemm_grid, T>>>(h2, HID, HID, 1, W3, b3, h3, q);
    scatter256<<<scat_blocks, T>>>(q, src, dst, h3);

    // head
    head_kernel<<<(NN + 7) / 8, T>>>(Wl, bl, out);
}

// round 3
// speedup vs baseline: 4.1209x; 1.3278x over previous
#include <cuda_runtime.h>
#include <cstdint>

#define NN 89250
#define NE 899756
#define F0 500
#define HID 256
#define NC  7
#define SCAN_T 256
#define NBLK ((NN + SCAN_T - 1) / SCAN_T)   // 349

// ---------------- scratch (device globals) ---------------------------------
__device__ float g_h1[(size_t)NN * HID];
__device__ float g_h2[(size_t)NN * HID];
__device__ float g_h3[(size_t)NN * HID];
__device__ float g_q [(size_t)NN * HID];
__device__ int   g_cnt[NN];
__device__ int   g_row_start[NN];
__device__ int   g_row_fill[NN];
__device__ int   g_bsum[NBLK];
__device__ int   g_csr_src[NE];
__device__ float g_csr_w[NE];

// ---------------- CSR build kernels -----------------------------------------
__global__ void zero_cnt() {
    int i = blockIdx.x * blockDim.x + threadIdx.x;
    if (i < NN) g_cnt[i] = 0;
}
__global__ void count_kernel(const int* __restrict__ dst) {
    int e = blockIdx.x * blockDim.x + threadIdx.x;
    if (e < NE) atomicAdd(&g_cnt[dst[e]], 1);
}
// per-block sums of cnt
__global__ void scanA() {
    __shared__ int s[SCAN_T];
    int t = threadIdx.x;
    int i = blockIdx.x * SCAN_T + t;
    s[t] = (i < NN) ? g_cnt[i] : 0;
    __syncthreads();
#pragma unroll
    for (int off = SCAN_T / 2; off > 0; off >>= 1) {
        if (t < off) s[t] += s[t + off];
        __syncthreads();
    }
    if (t == 0) g_bsum[blockIdx.x] = s[0];
}
// exclusive scan of block sums (single block, 512 threads >= NBLK)
__global__ void scanB() {
    __shared__ int s[512];
    int t = threadIdx.x;
    int v = (t < NBLK) ? g_bsum[t] : 0;
    s[t] = v;
    __syncthreads();
#pragma unroll
    for (int off = 1; off < 512; off <<= 1) {
        int x = (t >= off) ? s[t - off] : 0;
        __syncthreads();
        s[t] += x;
        __syncthreads();
    }
    if (t < NBLK) g_bsum[t] = s[t] - v;   // exclusive
}
// per-element exclusive scan + block offset -> row_start, row_fill
__global__ void scanC() {
    __shared__ int s[SCAN_T];
    int t = threadIdx.x;
    int i = blockIdx.x * SCAN_T + t;
    int v = (i < NN) ? g_cnt[i] : 0;
    s[t] = v;
    __syncthreads();
#pragma unroll
    for (int off = 1; off < SCAN_T; off <<= 1) {
        int x = (t >= off) ? s[t - off] : 0;
        __syncthreads();
        s[t] += x;
        __syncthreads();
    }
    if (i < NN) {
        int excl = s[t] - v + g_bsum[blockIdx.x];
        g_row_start[i] = excl;
        g_row_fill[i]  = excl;
    }
}
// place edges into CSR slots; fold 1/deg into edge weight
__global__ void place_kernel(const int* __restrict__ src, const int* __restrict__ dst,
                             const float* __restrict__ ew) {
    int e = blockIdx.x * blockDim.x + threadIdx.x;
    if (e >= NE) return;
    int d = dst[e];
    int slot = atomicAdd(&g_row_fill[d], 1);
    g_csr_src[slot] = src[e];
    g_csr_w[slot]   = ew[e] / fmaxf((float)g_cnt[d], 1.0f);
}

// ---------------- TF32 MMA helpers ------------------------------------------
__device__ __forceinline__ uint32_t f2tf(float f) {
    uint32_t r;
    asm("cvt.rna.tf32.f32 %0, %1;" : "=r"(r) : "f"(f));
    return r;
}
__device__ __forceinline__ void mma_tf32(float c[4], const uint32_t a[4], const uint32_t b[2]) {
    asm volatile(
        "mma.sync.aligned.m16n8k8.row.col.f32.tf32.tf32.f32 "
        "{%0,%1,%2,%3}, {%4,%5,%6,%7}, {%8,%9}, {%0,%1,%2,%3};"
        : "+f"(c[0]), "+f"(c[1]), "+f"(c[2]), "+f"(c[3])
        : "r"(a[0]), "r"(a[1]), "r"(a[2]), "r"(a[3]), "r"(b[0]), "r"(b[1]));
}

// ---------------- fused SAGE GEMM (tf32 tensor cores) -----------------------
__global__ __launch_bounds__(256)
void gemm_sage(const float* __restrict__ A, int K, int lda, int relu_in,
               const float* __restrict__ W, const float* __restrict__ bias,
               float* __restrict__ ACC, float* __restrict__ Q)
{
    __shared__ uint32_t As[2][128][20];
    __shared__ uint32_t Bs[2][16][136];

    const int bx = blockIdx.x;
    const int bm = blockIdx.y * 128;
    const bool accPath = (bx < 2);
    const int nb = (bx & 1) * 128;
    const float* Wbase = accPath ? W : W + (size_t)K * 256;

    const int tid  = threadIdx.x;
    const int wid  = tid >> 5;
    const int lane = tid & 31;
    const int wm = (wid >> 2) * 64;
    const int wn = (wid & 3) * 32;
    const int r0 = lane >> 2, c0 = lane & 3;

    const int a_r = tid >> 2;
    const int a_c = (tid & 3) * 4;
    const int b_k = tid >> 5;
    const int b_n = (tid & 31) * 4;

    const int KT = (K + 15) / 16;

    float acc[4][4][4];
#pragma unroll
    for (int mi = 0; mi < 4; mi++)
#pragma unroll
        for (int ni = 0; ni < 4; ni++)
#pragma unroll
            for (int c = 0; c < 4; c++) acc[mi][ni][c] = 0.f;

    float4 ra[2], rb[2];

#pragma unroll
    for (int p = 0; p < 2; p++) {
        int row = bm + a_r + p * 64;
        float4 v = make_float4(0.f, 0.f, 0.f, 0.f);
        if (row < NN && a_c < K) v = *(const float4*)(A + (size_t)row * lda + a_c);
        if (relu_in) { v.x = fmaxf(v.x, 0.f); v.y = fmaxf(v.y, 0.f);
                       v.z = fmaxf(v.z, 0.f); v.w = fmaxf(v.w, 0.f); }
        ra[p] = v;
        int kk = b_k + p * 8;
        float4 w = make_float4(0.f, 0.f, 0.f, 0.f);
        if (kk < K) w = *(const float4*)(Wbase + (size_t)kk * 256 + nb + b_n);
        rb[p] = w;
    }
#pragma unroll
    for (int p = 0; p < 2; p++) {
        int row = a_r + p * 64;
        As[0][row][a_c + 0] = f2tf(ra[p].x); As[0][row][a_c + 1] = f2tf(ra[p].y);
        As[0][row][a_c + 2] = f2tf(ra[p].z); As[0][row][a_c + 3] = f2tf(ra[p].w);
        int k = b_k + p * 8;
        Bs[0][k][b_n + 0] = f2tf(rb[p].x); Bs[0][k][b_n + 1] = f2tf(rb[p].y);
        Bs[0][k][b_n + 2] = f2tf(rb[p].z); Bs[0][k][b_n + 3] = f2tf(rb[p].w);
    }
    __syncthreads();

    int buf = 0;
    for (int kt = 0; kt < KT; kt++) {
        if (kt + 1 < KT) {
            int k0 = (kt + 1) * 16;
#pragma unroll
            for (int p = 0; p < 2; p++) {
                int row = bm + a_r + p * 64;
                int col = k0 + a_c;
                float4 v = make_float4(0.f, 0.f, 0.f, 0.f);
                if (row < NN && col < K) v = *(const float4*)(A + (size_t)row * lda + col);
                if (relu_in) { v.x = fmaxf(v.x, 0.f); v.y = fmaxf(v.y, 0.f);
                               v.z = fmaxf(v.z, 0.f); v.w = fmaxf(v.w, 0.f); }
                ra[p] = v;
                int kk = k0 + b_k + p * 8;
                float4 w = make_float4(0.f, 0.f, 0.f, 0.f);
                if (kk < K) w = *(const float4*)(Wbase + (size_t)kk * 256 + nb + b_n);
                rb[p] = w;
            }
        }
#pragma unroll
        for (int ks = 0; ks < 2; ks++) {
            const int k8 = ks * 8;
            uint32_t af[4][4], bf[4][2];
#pragma unroll
            for (int mi = 0; mi < 4; mi++) {
                int row = wm + mi * 16 + r0;
                af[mi][0] = As[buf][row    ][k8 + c0    ];
                af[mi][1] = As[buf][row + 8][k8 + c0    ];
                af[mi][2] = As[buf][row    ][k8 + c0 + 4];
                af[mi][3] = As[buf][row + 8][k8 + c0 + 4];
            }
#pragma unroll
            for (int ni = 0; ni < 4; ni++) {
                int col = wn + ni * 8 + r0;
                bf[ni][0] = Bs[buf][k8 + c0    ][col];
                bf[ni][1] = Bs[buf][k8 + c0 + 4][col];
            }
#pragma unroll
            for (int mi = 0; mi < 4; mi++)
#pragma unroll
                for (int ni = 0; ni < 4; ni++)
                    mma_tf32(acc[mi][ni], af[mi], bf[ni]);
        }
        if (kt + 1 < KT) {
            int nbuf = buf ^ 1;
#pragma unroll
            for (int p = 0; p < 2; p++) {
                int row = a_r + p * 64;
                As[nbuf][row][a_c + 0] = f2tf(ra[p].x); As[nbuf][row][a_c + 1] = f2tf(ra[p].y);
                As[nbuf][row][a_c + 2] = f2tf(ra[p].z); As[nbuf][row][a_c + 3] = f2tf(ra[p].w);
                int k = b_k + p * 8;
                Bs[nbuf][k][b_n + 0] = f2tf(rb[p].x); Bs[nbuf][k][b_n + 1] = f2tf(rb[p].y);
                Bs[nbuf][k][b_n + 2] = f2tf(rb[p].z); Bs[nbuf][k][b_n + 3] = f2tf(rb[p].w);
            }
            __syncthreads();
            buf = nbuf;
        }
    }

#pragma unroll
    for (int mi = 0; mi < 4; mi++) {
#pragma unroll
        for (int ci = 0; ci < 2; ci++) {
            int row = bm + wm + mi * 16 + r0 + ci * 8;
            if (row >= NN) continue;
#pragma unroll
            for (int ni = 0; ni < 4; ni++) {
                int col = nb + wn + ni * 8 + c0 * 2;
                float2 v;
                v.x = acc[mi][ni][ci * 2 + 0];
                v.y = acc[mi][ni][ci * 2 + 1];
                if (accPath) {
                    v.x += bias[col]; v.y += bias[col + 1];
                    *(float2*)(ACC + (size_t)row * 256 + col) = v;
                } else {
                    *(float2*)(Q + (size_t)row * 256 + col) = v;
                }
            }
        }
    }
}

// ---------------- gather SpMM: H[n] += sum_j w_j * Q[src_j] -----------------
// One warp per node; lane owns 8 floats (2 float4). Unroll-2 over neighbors.
__global__ __launch_bounds__(256)
void spmm_kernel(const float* __restrict__ Q, float* __restrict__ H) {
    int gw   = (blockIdx.x * blockDim.x + threadIdx.x) >> 5;
    int lane = threadIdx.x & 31;
    if (gw >= NN) return;
    int beg = g_row_start[gw];
    int end = beg + g_cnt[gw];

    const float4* Q4 = (const float4*)Q;
    float4 acc0 = make_float4(0.f, 0.f, 0.f, 0.f);
    float4 acc1 = make_float4(0.f, 0.f, 0.f, 0.f);

    int j = beg;
    for (; j + 2 <= end; j += 2) {
        int   s0 = g_csr_src[j],   s1 = g_csr_src[j + 1];
        float w0 = g_csr_w[j],     w1 = g_csr_w[j + 1];
        float4 a0 = Q4[(size_t)s0 * 64 + lane];
        float4 b0 = Q4[(size_t)s0 * 64 + 32 + lane];
        float4 a1 = Q4[(size_t)s1 * 64 + lane];
        float4 b1 = Q4[(size_t)s1 * 64 + 32 + lane];
        acc0.x += w0 * a0.x + w1 * a1.x; acc0.y += w0 * a0.y + w1 * a1.y;
        acc0.z += w0 * a0.z + w1 * a1.z; acc0.w += w0 * a0.w + w1 * a1.w;
        acc1.x += w0 * b0.x + w1 * b1.x; acc1.y += w0 * b0.y + w1 * b1.y;
        acc1.z += w0 * b0.z + w1 * b1.z; acc1.w += w0 * b0.w + w1 * b1.w;
    }
    if (j < end) {
        int   s0 = g_csr_src[j];
        float w0 = g_csr_w[j];
        float4 a0 = Q4[(size_t)s0 * 64 + lane];
        float4 b0 = Q4[(size_t)s0 * 64 + 32 + lane];
        acc0.x += w0 * a0.x; acc0.y += w0 * a0.y; acc0.z += w0 * a0.z; acc0.w += w0 * a0.w;
        acc1.x += w0 * b0.x; acc1.y += w0 * b0.y; acc1.z += w0 * b0.z; acc1.w += w0 * b0.w;
    }

    float4* H4 = (float4*)H;
    size_t base = (size_t)gw * 64;
    float4 h0 = H4[base + lane];
    float4 h1 = H4[base + 32 + lane];
    h0.x += acc0.x; h0.y += acc0.y; h0.z += acc0.z; h0.w += acc0.w;
    h1.x += acc1.x; h1.y += acc1.y; h1.z += acc1.z; h1.w += acc1.w;
    H4[base + lane] = h0;
    H4[base + 32 + lane] = h1;
}

// ---------------- head ------------------------------------------------------
__global__ __launch_bounds__(256)
void head_kernel(const float* __restrict__ Wl, const float* __restrict__ bl,
                 float* __restrict__ out) {
    __shared__ float sW[768 * NC];
    int tid = threadIdx.x;
    for (int i = tid; i < 768 * NC; i += blockDim.x) sW[i] = Wl[i];
    __syncthreads();

    int lane = tid & 31;
    int node = blockIdx.x * (blockDim.x >> 5) + (tid >> 5);
    if (node >= NN) return;

    const float* h1 = g_h1 + (size_t)node * HID;
    const float* h2 = g_h2 + (size_t)node * HID;
    const float* h3 = g_h3 + (size_t)node * HID;

    float acc[NC];
#pragma unroll
    for (int c = 0; c < NC; c++) acc[c] = 0.f;

    for (int k = lane; k < HID; k += 32) {
        float v1 = fmaxf(h1[k], 0.f), v2 = fmaxf(h2[k], 0.f), v3 = fmaxf(h3[k], 0.f);
#pragma unroll
        for (int c = 0; c < NC; c++)
            acc[c] += v1 * sW[k * NC + c]
                    + v2 * sW[(HID + k) * NC + c]
                    + v3 * sW[(2 * HID + k) * NC + c];
    }
#pragma unroll
    for (int c = 0; c < NC; c++)
        for (int off = 16; off > 0; off >>= 1)
            acc[c] += __shfl_down_sync(0xffffffffu, acc[c], off);

    if (lane == 0) {
        float lg[NC], mx = -1e30f;
#pragma unroll
        for (int c = 0; c < NC; c++) { lg[c] = acc[c] + bl[c]; mx = fmaxf(mx, lg[c]); }
        float s = 0.f;
#pragma unroll
        for (int c = 0; c < NC; c++) s += expf(lg[c] - mx);
        float lse = mx + logf(s);
#pragma unroll
        for (int c = 0; c < NC; c++) out[(size_t)node * NC + c] = lg[c] - lse;
    }
}

// ---------------------------------------------------------------------------
extern "C" void kernel_launch(void* const* d_in, const int* in_sizes, int n_in,
                              void* d_out, int out_size) {
    const float* x  = (const float*)d_in[0];
    const int*   ei = (const int*)d_in[1];
    const float* ew = (const float*)d_in[2];
    const float* W1 = (const float*)d_in[3];
    const float* b1 = (const float*)d_in[4];
    const float* W2 = (const float*)d_in[5];
    const float* b2 = (const float*)d_in[6];
    const float* W3 = (const float*)d_in[7];
    const float* b3 = (const float*)d_in[8];
    const float* Wl = (const float*)d_in[9];
    const float* bl = (const float*)d_in[10];
    float* out = (float*)d_out;

    const int* src = ei;
    const int* dst = ei + NE;

    float *h1, *h2, *h3, *q;
    cudaGetSymbolAddress((void**)&h1, g_h1);
    cudaGetSymbolAddress((void**)&h2, g_h2);
    cudaGetSymbolAddress((void**)&h3, g_h3);
    cudaGetSymbolAddress((void**)&q,  g_q);

    const int T = 256;
    dim3 gemm_grid(4, (NN + 127) / 128);
    const int node_warps = (NN + 7) / 8;   // 8 warps/block, 1 warp/node

    // CSR build interleaved with gemm1 (gemm1 has no CSR dependency;
    // placed at launch index 3 = the ncu-captured slot)
    zero_cnt<<<NBLK, SCAN_T>>>();                              // 0
    count_kernel<<<(NE + T - 1) / T, T>>>(dst);                // 1
    scanA<<<NBLK, SCAN_T>>>();                                 // 2
    gemm_sage<<<gemm_grid, T>>>(x, F0, F0, 0, W1, b1, h1, q);  // 3 <- profiled
    scanB<<<1, 512>>>();                                       // 4
    scanC<<<NBLK, SCAN_T>>>();                                 // 5
    place_kernel<<<(NE + T - 1) / T, T>>>(src, dst, ew);       // 6

    spmm_kernel<<<node_warps, T>>>(q, h1);                     // 7

    gemm_sage<<<gemm_grid, T>>>(h1, HID, HID, 1, W2, b2, h2, q);
    spmm_kernel<<<node_warps, T>>>(q, h2);

    gemm_sage<<<gemm_grid, T>>>(h2, HID, HID, 1, W3, b3, h3, q);
    spmm_kernel<<<node_warps, T>>>(q, h3);

    head_kernel<<<(NN + 7) / 8, T>>>(Wl, bl, out);
}

// round 6
// speedup vs baseline: 4.4272x; 1.0743x over previous
#include <cuda_runtime.h>
#include <cstdint>

#define NN 89250
#define NE 899756
#define F0 500
#define HID 256
#define NC  7
#define SCAN_T 256
#define NBLK ((NN + SCAN_T - 1) / SCAN_T)   // 349

// ---------------- scratch (device globals) ---------------------------------
__device__ __align__(256) float g_h1[(size_t)NN * HID];
__device__ __align__(256) float g_h2[(size_t)NN * HID];
__device__ __align__(256) float g_h3[(size_t)NN * HID];
__device__ __align__(256) float g_q [(size_t)NN * HID];
__device__ __align__(256) float g_w1r[2 * F0  * 256];   // tf32-rounded weights
__device__ __align__(256) float g_w2r[2 * HID * 256];
__device__ __align__(256) float g_w3r[2 * HID * 256];
__device__ int   g_cnt[NN];
__device__ int   g_row_start[NN];
__device__ int   g_row_fill[NN];
__device__ int   g_bsum[NBLK];
__device__ int   g_csr_src[NE];
__device__ float g_csr_w[NE];

#define W1N (2 * F0  * 256)   // 256000
#define W2N (2 * HID * 256)   // 131072

// ---------------- CSR build kernels -----------------------------------------
__global__ void zero_cnt() {
    int i = blockIdx.x * blockDim.x + threadIdx.x;
    if (i < NN) g_cnt[i] = 0;
}
__global__ void count_kernel(const int* __restrict__ dst) {
    int e = blockIdx.x * blockDim.x + threadIdx.x;
    if (e < NE) atomicAdd(&g_cnt[dst[e]], 1);
}
__global__ void scanA() {
    __shared__ int s[SCAN_T];
    int t = threadIdx.x;
    int i = blockIdx.x * SCAN_T + t;
    s[t] = (i < NN) ? g_cnt[i] : 0;
    __syncthreads();
#pragma unroll
    for (int off = SCAN_T / 2; off > 0; off >>= 1) {
        if (t < off) s[t] += s[t + off];
        __syncthreads();
    }
    if (t == 0) g_bsum[blockIdx.x] = s[0];
}
__global__ void scanB() {
    __shared__ int s[512];
    int t = threadIdx.x;
    int v = (t < NBLK) ? g_bsum[t] : 0;
    s[t] = v;
    __syncthreads();
#pragma unroll
    for (int off = 1; off < 512; off <<= 1) {
        int x = (t >= off) ? s[t - off] : 0;
        __syncthreads();
        s[t] += x;
        __syncthreads();
    }
    if (t < NBLK) g_bsum[t] = s[t] - v;   // exclusive
}
__global__ void scanC() {
    __shared__ int s[SCAN_T];
    int t = threadIdx.x;
    int i = blockIdx.x * SCAN_T + t;
    int v = (i < NN) ? g_cnt[i] : 0;
    s[t] = v;
    __syncthreads();
#pragma unroll
    for (int off = 1; off < SCAN_T; off <<= 1) {
        int x = (t >= off) ? s[t - off] : 0;
        __syncthreads();
        s[t] += x;
        __syncthreads();
    }
    if (i < NN) {
        int excl = s[t] - v + g_bsum[blockIdx.x];
        g_row_start[i] = excl;
        g_row_fill[i]  = excl;
    }
}
__global__ void place_kernel(const int* __restrict__ src, const int* __restrict__ dst,
                             const float* __restrict__ ew) {
    int e = blockIdx.x * blockDim.x + threadIdx.x;
    if (e >= NE) return;
    int d = dst[e];
    int slot = atomicAdd(&g_row_fill[d], 1);
    g_csr_src[slot] = src[e];
    g_csr_w[slot]   = ew[e] / fmaxf((float)g_cnt[d], 1.0f);
}

// ---------------- tf32 helpers ------------------------------------------------
__device__ __forceinline__ uint32_t f2tf(float f) {
    uint32_t r;
    asm("cvt.rna.tf32.f32 %0, %1;" : "=r"(r) : "f"(f));
    return r;
}
__device__ __forceinline__ void mma_tf32(float c[4], const uint32_t a[4], const uint32_t b[2]) {
    asm volatile(
        "mma.sync.aligned.m16n8k8.row.col.f32.tf32.tf32.f32 "
        "{%0,%1,%2,%3}, {%4,%5,%6,%7}, {%8,%9}, {%0,%1,%2,%3};"
        : "+f"(c[0]), "+f"(c[1]), "+f"(c[2]), "+f"(c[3])
        : "r"(a[0]), "r"(a[1]), "r"(a[2]), "r"(a[3]), "r"(b[0]), "r"(b[1]));
}
__device__ __forceinline__ void cp16(uint32_t dst, const void* src) {
    asm volatile("cp.async.cg.shared.global [%0], [%1], 16;" :: "r"(dst), "l"(src));
}
__device__ __forceinline__ uint32_t smem_u32(const void* p) {
    uint32_t a;
    asm("{ .reg .u64 t; cvta.to.shared.u64 t, %1; cvt.u32.u64 %0, t; }" : "=r"(a) : "l"(p));
    return a;
}

// pre-round all weights to tf32 bit patterns (read raw by MMA later)
__global__ void cvt_w(const float* __restrict__ W1, const float* __restrict__ W2,
                      const float* __restrict__ W3) {
    int i = blockIdx.x * blockDim.x + threadIdx.x;
    if (i < W1N) {
        ((uint32_t*)g_w1r)[i] = f2tf(W1[i]);
    } else if (i < W1N + W2N) {
        ((uint32_t*)g_w2r)[i - W1N] = f2tf(W2[i - W1N]);
    } else if (i < W1N + 2 * W2N) {
        ((uint32_t*)g_w3r)[i - W1N - W2N] = f2tf(W3[i - W1N - W2N]);
    }
}

// ---------------- tf32 SAGE GEMM: block 128x256, warp 64x64 -----------------
// grid = (2, ceil(NN/128)). bx=0: OUT = A@Wtop + bias -> H; bx=1: OUT = A@Wbot -> Q
// A: 2 stage buffers (register-staged stores, hazard-free).
// B: 3 stage buffers (cp.async prefetch distance 2 -> must not alias live stage).
#define AS_STRIDE 20    // words per A row (16 data + 4 pad)
#define BS_STRIDE 264   // words per B k-row (256 data + 8 pad)
#define AS_STAGE  (128 * AS_STRIDE)     // 2560 words
#define BS_STAGE  (16  * BS_STRIDE)     // 4224 words
#define SMEM_WORDS (2 * AS_STAGE + 3 * BS_STAGE)   // 17792 words = 71168 B

__global__ __launch_bounds__(256, 1)
void gemm_tc(const float* __restrict__ A, int K, int lda,
             const float* __restrict__ Wr,   // tf32-rounded, [2K,256]
             const float* __restrict__ bias,
             float* __restrict__ H, float* __restrict__ Qb)
{
    extern __shared__ uint32_t sm[];
    uint32_t* As = sm;                       // [2][128][AS_STRIDE]
    uint32_t* Bs = sm + 2 * AS_STAGE;        // [3][16][BS_STRIDE]
    const uint32_t bs_u32 = smem_u32(Bs);

    const int bx = blockIdx.x;               // 0 = P path, 1 = Q path
    const int bm = blockIdx.y * 128;
    const float* Wsel = Wr + (size_t)bx * K * 256;

    const int tid  = threadIdx.x;
    const int wid  = tid >> 5;
    const int lane = tid & 31;
    const int wm = (wid >> 2) * 64;          // 0,64
    const int wn = (wid & 3) * 64;           // 0,64,128,192
    const int r0 = lane >> 2, c0 = lane & 3;

    const int a_row = tid >> 2;              // 0..63? no: 256/4 = 0..63 -> need 128 rows
    const int a_kq  = (tid & 3) * 4;
    const int KT = (K + 15) / 16;

    float acc[4][8][4];
#pragma unroll
    for (int mi = 0; mi < 4; mi++)
#pragma unroll
        for (int ni = 0; ni < 8; ni++)
#pragma unroll
            for (int c = 0; c < 4; c++) acc[mi][ni][c] = 0.f;

    // ---- B loader (cp.async, 3-stage ring) ----
    auto loadB = [&](int s) {
        const int buf = s % 3;
        const int k0  = s * 16;
#pragma unroll
        for (int i = 0; i < 4; i++) {
            int chunk = tid + i * 256;
            int k = chunk >> 6, n4 = (chunk & 63) * 4;
            uint32_t dst = bs_u32 + (buf * BS_STAGE + k * BS_STRIDE + n4) * 4;
            int gk = k0 + k;
            if (gk < K) cp16(dst, Wsel + (size_t)gk * 256 + n4);
            else {
                uint4 z = make_uint4(0, 0, 0, 0);
                *(uint4*)(Bs + buf * BS_STAGE + k * BS_STRIDE + n4) = z;
            }
        }
    };
    // ---- A: gmem -> regs (two rows per thread: a_row and a_row+64) ----
    float4 rA0, rA1;
    auto ldgA = [&](int s) {
        int gk = s * 16 + a_kq;
        rA0 = make_float4(0.f, 0.f, 0.f, 0.f);
        rA1 = make_float4(0.f, 0.f, 0.f, 0.f);
        int gr0 = bm + a_row, gr1 = bm + a_row + 64;
        if (gr0 < NN && gk < K) rA0 = *(const float4*)(A + (size_t)gr0 * lda + gk);
        if (gr1 < NN && gk < K) rA1 = *(const float4*)(A + (size_t)gr1 * lda + gk);
    };
    // ---- A: regs -> smem (rna tf32 rounding) ----
    auto stsA = [&](int s) {
        uint32_t* base = As + (s & 1) * AS_STAGE;
        uint4 v0, v1;
        v0.x = f2tf(rA0.x); v0.y = f2tf(rA0.y); v0.z = f2tf(rA0.z); v0.w = f2tf(rA0.w);
        v1.x = f2tf(rA1.x); v1.y = f2tf(rA1.y); v1.z = f2tf(rA1.z); v1.w = f2tf(rA1.w);
        *(uint4*)(base + a_row * AS_STRIDE + a_kq) = v0;
        *(uint4*)(base + (a_row + 64) * AS_STRIDE + a_kq) = v1;
    };

    // ---- prologue ----
    loadB(0); asm volatile("cp.async.commit_group;" ::: "memory");
    loadB(1); asm volatile("cp.async.commit_group;" ::: "memory");
    ldgA(0); stsA(0);
    ldgA(1);
    asm volatile("cp.async.wait_group 1;" ::: "memory");   // B0 ready
    __syncthreads();

    for (int s = 0; s < KT; s++) {
        if (s + 1 < KT) stsA(s + 1);                       // A buf (s+1)&1: free
        if (s + 2 < KT) { ldgA(s + 2); loadB(s + 2); }     // B buf (s+2)%3: free
        asm volatile("cp.async.commit_group;" ::: "memory");

        const uint32_t* Ab = As + (s & 1) * AS_STAGE;
        const uint32_t* Bb = Bs + (s % 3) * BS_STAGE;
#pragma unroll
        for (int ks = 0; ks < 2; ks++) {
            const int k8 = ks * 8;
            uint32_t af[4][4], bf[8][2];
#pragma unroll
            for (int mi = 0; mi < 4; mi++) {
                int row = wm + mi * 16 + r0;
                af[mi][0] = Ab[(row    ) * AS_STRIDE + k8 + c0    ];
                af[mi][1] = Ab[(row + 8) * AS_STRIDE + k8 + c0    ];
                af[mi][2] = Ab[(row    ) * AS_STRIDE + k8 + c0 + 4];
                af[mi][3] = Ab[(row + 8) * AS_STRIDE + k8 + c0 + 4];
            }
#pragma unroll
            for (int ni = 0; ni < 8; ni++) {
                int col = wn + ni * 8 + r0;
                bf[ni][0] = Bb[(k8 + c0    ) * BS_STRIDE + col];
                bf[ni][1] = Bb[(k8 + c0 + 4) * BS_STRIDE + col];
            }
#pragma unroll
            for (int mi = 0; mi < 4; mi++)
#pragma unroll
                for (int ni = 0; ni < 8; ni++)
                    mma_tf32(acc[mi][ni], af[mi], bf[ni]);
        }

        if (s + 1 < KT) asm volatile("cp.async.wait_group 1;" ::: "memory"); // B(s+1) landed
        __syncthreads();
    }

    // ---- epilogue ----
    float2 b2[8];
    if (bx == 0) {
#pragma unroll
        for (int ni = 0; ni < 8; ni++) {
            int col = wn + ni * 8 + c0 * 2;
            b2[ni].x = bias[col]; b2[ni].y = bias[col + 1];
        }
    }
    float* OUT = (bx == 0) ? H : Qb;
#pragma unroll
    for (int mi = 0; mi < 4; mi++) {
#pragma unroll
        for (int ci = 0; ci < 2; ci++) {
            int row = bm + wm + mi * 16 + r0 + ci * 8;
            if (row >= NN) continue;
#pragma unroll
            for (int ni = 0; ni < 8; ni++) {
                int col = wn + ni * 8 + c0 * 2;
                float2 v;
                v.x = acc[mi][ni][ci * 2 + 0];
                v.y = acc[mi][ni][ci * 2 + 1];
                if (bx == 0) { v.x += b2[ni].x; v.y += b2[ni].y; }
                *(float2*)(OUT + (size_t)row * 256 + col) = v;
            }
        }
    }
}

// ---------------- gather SpMM: H[n] = relu(H[n] + sum_j w_j * Q[src_j]) -----
__global__ __launch_bounds__(256)
void spmm_kernel(const float* __restrict__ Q, float* __restrict__ H) {
    int gw   = (blockIdx.x * blockDim.x + threadIdx.x) >> 5;
    int lane = threadIdx.x & 31;
    if (gw >= NN) return;
    int beg = g_row_start[gw];
    int end = beg + g_cnt[gw];

    const float4* Q4 = (const float4*)Q;
    float4 acc0 = make_float4(0.f, 0.f, 0.f, 0.f);
    float4 acc1 = make_float4(0.f, 0.f, 0.f, 0.f);

    int j = beg;
    for (; j + 2 <= end; j += 2) {
        int   s0 = g_csr_src[j],   s1 = g_csr_src[j + 1];
        float w0 = g_csr_w[j],     w1 = g_csr_w[j + 1];
        float4 a0 = Q4[(size_t)s0 * 64 + lane];
        float4 b0 = Q4[(size_t)s0 * 64 + 32 + lane];
        float4 a1 = Q4[(size_t)s1 * 64 + lane];
        float4 b1 = Q4[(size_t)s1 * 64 + 32 + lane];
        acc0.x += w0 * a0.x + w1 * a1.x; acc0.y += w0 * a0.y + w1 * a1.y;
        acc0.z += w0 * a0.z + w1 * a1.z; acc0.w += w0 * a0.w + w1 * a1.w;
        acc1.x += w0 * b0.x + w1 * b1.x; acc1.y += w0 * b0.y + w1 * b1.y;
        acc1.z += w0 * b0.z + w1 * b1.z; acc1.w += w0 * b0.w + w1 * b1.w;
    }
    if (j < end) {
        int   s0 = g_csr_src[j];
        float w0 = g_csr_w[j];
        float4 a0 = Q4[(size_t)s0 * 64 + lane];
        float4 b0 = Q4[(size_t)s0 * 64 + 32 + lane];
        acc0.x += w0 * a0.x; acc0.y += w0 * a0.y; acc0.z += w0 * a0.z; acc0.w += w0 * a0.w;
        acc1.x += w0 * b0.x; acc1.y += w0 * b0.y; acc1.z += w0 * b0.z; acc1.w += w0 * b0.w;
    }

    float4* H4 = (float4*)H;
    size_t base = (size_t)gw * 64;
    float4 h0 = H4[base + lane];
    float4 h1 = H4[base + 32 + lane];
    h0.x = fmaxf(h0.x + acc0.x, 0.f); h0.y = fmaxf(h0.y + acc0.y, 0.f);
    h0.z = fmaxf(h0.z + acc0.z, 0.f); h0.w = fmaxf(h0.w + acc0.w, 0.f);
    h1.x = fmaxf(h1.x + acc1.x, 0.f); h1.y = fmaxf(h1.y + acc1.y, 0.f);
    h1.z = fmaxf(h1.z + acc1.z, 0.f); h1.w = fmaxf(h1.w + acc1.w, 0.f);
    H4[base + lane] = h0;
    H4[base + 32 + lane] = h1;
}

// ---------------- head (inputs already relu'd) ------------------------------
__global__ __launch_bounds__(256)
void head_kernel(const float* __restrict__ Wl, const float* __restrict__ bl,
                 float* __restrict__ out) {
    __shared__ float sW[768 * NC];
    int tid = threadIdx.x;
    for (int i = tid; i < 768 * NC; i += blockDim.x) sW[i] = Wl[i];
    __syncthreads();

    int lane = tid & 31;
    int node = blockIdx.x * (blockDim.x >> 5) + (tid >> 5);
    if (node >= NN) return;

    const float* h1 = g_h1 + (size_t)node * HID;
    const float* h2 = g_h2 + (size_t)node * HID;
    const float* h3 = g_h3 + (size_t)node * HID;

    float acc[NC];
#pragma unroll
    for (int c = 0; c < NC; c++) acc[c] = 0.f;

    for (int k = lane; k < HID; k += 32) {
        float v1 = h1[k], v2 = h2[k], v3 = h3[k];
#pragma unroll
        for (int c = 0; c < NC; c++)
            acc[c] += v1 * sW[k * NC + c]
                    + v2 * sW[(HID + k) * NC + c]
                    + v3 * sW[(2 * HID + k) * NC + c];
    }
#pragma unroll
    for (int c = 0; c < NC; c++)
        for (int off = 16; off > 0; off >>= 1)
            acc[c] += __shfl_down_sync(0xffffffffu, acc[c], off);

    if (lane == 0) {
        float lg[NC], mx = -1e30f;
#pragma unroll
        for (int c = 0; c < NC; c++) { lg[c] = acc[c] + bl[c]; mx = fmaxf(mx, lg[c]); }
        float s = 0.f;
#pragma unroll
        for (int c = 0; c < NC; c++) s += expf(lg[c] - mx);
        float lse = mx + logf(s);
#pragma unroll
        for (int c = 0; c < NC; c++) out[(size_t)node * NC + c] = lg[c] - lse;
    }
}

// ---------------------------------------------------------------------------
extern "C" void kernel_launch(void* const* d_in, const int* in_sizes, int n_in,
                              void* d_out, int out_size) {
    const float* x  = (const float*)d_in[0];
    const int*   ei = (const int*)d_in[1];
    const float* ew = (const float*)d_in[2];
    const float* W1 = (const float*)d_in[3];
    const float* b1 = (const float*)d_in[4];
    const float* W2 = (const float*)d_in[5];
    const float* b2 = (const float*)d_in[6];
    const float* W3 = (const float*)d_in[7];
    const float* b3 = (const float*)d_in[8];
    const float* Wl = (const float*)d_in[9];
    const float* bl = (const float*)d_in[10];
    float* out = (float*)d_out;

    const int* src = ei;
    const int* dst = ei + NE;

    float *h1, *h2, *h3, *q, *w1r, *w2r, *w3r;
    cudaGetSymbolAddress((void**)&h1,  g_h1);
    cudaGetSymbolAddress((void**)&h2,  g_h2);
    cudaGetSymbolAddress((void**)&h3,  g_h3);
    cudaGetSymbolAddress((void**)&q,   g_q);
    cudaGetSymbolAddress((void**)&w1r, g_w1r);
    cudaGetSymbolAddress((void**)&w2r, g_w2r);
    cudaGetSymbolAddress((void**)&w3r, g_w3r);

    const int SMEM_B = SMEM_WORDS * 4;
    cudaFuncSetAttribute(gemm_tc, cudaFuncAttributeMaxDynamicSharedMemorySize, SMEM_B);

    const int T = 256;
    dim3 gemm_grid(2, (NN + 127) / 128);
    const int node_warps = (NN + 7) / 8;
    const int wtot = W1N + 2 * W2N;

    zero_cnt<<<NBLK, SCAN_T>>>();                                    // 0
    count_kernel<<<(NE + T - 1) / T, T>>>(dst);                      // 1
    cvt_w<<<(wtot + T - 1) / T, T>>>(W1, W2, W3);                    // 2
    gemm_tc<<<gemm_grid, T, SMEM_B>>>(x, F0, F0, w1r, b1, h1, q);    // 3 <- profiled
    scanA<<<NBLK, SCAN_T>>>();                                       // 4
    scanB<<<1, 512>>>();                                             // 5
    scanC<<<NBLK, SCAN_T>>>();                                       // 6
    place_kernel<<<(NE + T - 1) / T, T>>>(src, dst, ew);             // 7

    spmm_kernel<<<node_warps, T>>>(q, h1);                           // 8

    gemm_tc<<<gemm_grid, T, SMEM_B>>>(h1, HID, HID, w2r, b2, h2, q);
    spmm_kernel<<<node_warps, T>>>(q, h2);

    gemm_tc<<<gemm_grid, T, SMEM_B>>>(h2, HID, HID, w3r, b3, h3, q);
    spmm_kernel<<<node_warps, T>>>(q, h3);

    head_kernel<<<(NN + 7) / 8, T>>>(Wl, bl, out);
}

// round 7
// speedup vs baseline: 4.7297x; 1.0683x over previous
#include <cuda_runtime.h>
#include <cstdint>

#define NN 89250
#define NE 899756
#define F0 500
#define HID 256
#define NC  7
#define SCAN_T 256
#define NBLK ((NN + SCAN_T - 1) / SCAN_T)   // 349

// ---------------- scratch (device globals) ---------------------------------
__device__ __align__(256) float g_h1[(size_t)NN * HID];
__device__ __align__(256) float g_h2[(size_t)NN * HID];
__device__ __align__(256) float g_h3[(size_t)NN * HID];
__device__ __align__(256) float g_q [(size_t)NN * HID];
__device__ __align__(256) float g_w1r[2 * F0  * 256];   // tf32-rounded weights
__device__ __align__(256) float g_w2r[2 * HID * 256];
__device__ __align__(256) float g_w3r[2 * HID * 256];
__device__ int   g_cnt[NN];
__device__ int   g_row_start[NN];
__device__ int   g_row_fill[NN];
__device__ int   g_bsum[NBLK];
__device__ int   g_csr_src[NE];
__device__ float g_csr_w[NE];

#define W1N (2 * F0  * 256)   // 256000
#define W2N (2 * HID * 256)   // 131072

// ---------------- CSR build kernels -----------------------------------------
__global__ void zero_cnt() {
    int i = blockIdx.x * blockDim.x + threadIdx.x;
    if (i < NN) g_cnt[i] = 0;
}
__global__ void count_kernel(const int* __restrict__ dst) {
    int e = blockIdx.x * blockDim.x + threadIdx.x;
    if (e < NE) atomicAdd(&g_cnt[dst[e]], 1);
}
__global__ void scanA() {
    __shared__ int s[SCAN_T];
    int t = threadIdx.x;
    int i = blockIdx.x * SCAN_T + t;
    s[t] = (i < NN) ? g_cnt[i] : 0;
    __syncthreads();
#pragma unroll
    for (int off = SCAN_T / 2; off > 0; off >>= 1) {
        if (t < off) s[t] += s[t + off];
        __syncthreads();
    }
    if (t == 0) g_bsum[blockIdx.x] = s[0];
}
__global__ void scanB() {
    __shared__ int s[512];
    int t = threadIdx.x;
    int v = (t < NBLK) ? g_bsum[t] : 0;
    s[t] = v;
    __syncthreads();
#pragma unroll
    for (int off = 1; off < 512; off <<= 1) {
        int x = (t >= off) ? s[t - off] : 0;
        __syncthreads();
        s[t] += x;
        __syncthreads();
    }
    if (t < NBLK) g_bsum[t] = s[t] - v;   // exclusive
}
__global__ void scanC() {
    __shared__ int s[SCAN_T];
    int t = threadIdx.x;
    int i = blockIdx.x * SCAN_T + t;
    int v = (i < NN) ? g_cnt[i] : 0;
    s[t] = v;
    __syncthreads();
#pragma unroll
    for (int off = 1; off < SCAN_T; off <<= 1) {
        int x = (t >= off) ? s[t - off] : 0;
        __syncthreads();
        s[t] += x;
        __syncthreads();
    }
    if (i < NN) {
        int excl = s[t] - v + g_bsum[blockIdx.x];
        g_row_start[i] = excl;
        g_row_fill[i]  = excl;
    }
}
__global__ void place_kernel(const int* __restrict__ src, const int* __restrict__ dst,
                             const float* __restrict__ ew) {
    int e = blockIdx.x * blockDim.x + threadIdx.x;
    if (e >= NE) return;
    int d = dst[e];
    int slot = atomicAdd(&g_row_fill[d], 1);
    g_csr_src[slot] = src[e];
    g_csr_w[slot]   = ew[e] / fmaxf((float)g_cnt[d], 1.0f);
}

// ---------------- tf32 helpers ------------------------------------------------
__device__ __forceinline__ uint32_t f2tf(float f) {
    uint32_t r;
    asm("cvt.rna.tf32.f32 %0, %1;" : "=r"(r) : "f"(f));
    return r;
}
__device__ __forceinline__ void mma_tf32(float c[4], const uint32_t a[4], const uint32_t b[2]) {
    asm volatile(
        "mma.sync.aligned.m16n8k8.row.col.f32.tf32.tf32.f32 "
        "{%0,%1,%2,%3}, {%4,%5,%6,%7}, {%8,%9}, {%0,%1,%2,%3};"
        : "+f"(c[0]), "+f"(c[1]), "+f"(c[2]), "+f"(c[3])
        : "r"(a[0]), "r"(a[1]), "r"(a[2]), "r"(a[3]), "r"(b[0]), "r"(b[1]));
}
__device__ __forceinline__ void cp16(uint32_t dst, const void* src) {
    asm volatile("cp.async.cg.shared.global [%0], [%1], 16;" :: "r"(dst), "l"(src));
}
__device__ __forceinline__ uint32_t smem_u32(const void* p) {
    uint32_t a;
    asm("{ .reg .u64 t; cvta.to.shared.u64 t, %1; cvt.u32.u64 %0, t; }" : "=r"(a) : "l"(p));
    return a;
}

// pre-round all weights to tf32 bit patterns (read raw by MMA later)
__global__ void cvt_w(const float* __restrict__ W1, const float* __restrict__ W2,
                      const float* __restrict__ W3) {
    int i = blockIdx.x * blockDim.x + threadIdx.x;
    if (i < W1N) {
        ((uint32_t*)g_w1r)[i] = f2tf(W1[i]);
    } else if (i < W1N + W2N) {
        ((uint32_t*)g_w2r)[i - W1N] = f2tf(W2[i - W1N]);
    } else if (i < W1N + 2 * W2N) {
        ((uint32_t*)g_w3r)[i - W1N - W2N] = f2tf(W3[i - W1N - W2N]);
    }
}

// ---------------- tf32 SAGE GEMM: block 128x256, warp 64x64, K-stage 32 -----
// grid = (2, ceil(NN/128)). bx=0: OUT = A@Wtop + bias -> H; bx=1: OUT = A@Wbot -> Q
// A: 2 stage buffers (register-staged stores, hazard-free).
// B: 3 stage buffers (cp.async prefetch distance 2).
#define AS_STRIDE 36    // words per A row (32 data + 4 pad)
#define BS_STRIDE 264   // words per B k-row (256 data + 8 pad)
#define AS_STAGE  (128 * AS_STRIDE)     // 4608 words
#define BS_STAGE  (32  * BS_STRIDE)     // 8448 words
#define SMEM_WORDS (2 * AS_STAGE + 3 * BS_STAGE)   // 34560 words = 138240 B

__global__ __launch_bounds__(256, 1)
void gemm_tc(const float* __restrict__ A, int K, int lda,
             const float* __restrict__ Wr,   // tf32-rounded, [2K,256]
             const float* __restrict__ bias,
             float* __restrict__ H, float* __restrict__ Qb)
{
    extern __shared__ uint32_t sm[];
    uint32_t* As = sm;                       // [2][128][AS_STRIDE]
    uint32_t* Bs = sm + 2 * AS_STAGE;        // [3][32][BS_STRIDE]
    const uint32_t bs_u32 = smem_u32(Bs);

    const int bx = blockIdx.x;               // 0 = P path, 1 = Q path
    const int bm = blockIdx.y * 128;
    const float* Wsel = Wr + (size_t)bx * K * 256;

    const int tid  = threadIdx.x;
    const int wid  = tid >> 5;
    const int lane = tid & 31;
    const int wm = (wid >> 2) * 64;          // 0,64
    const int wn = (wid & 3) * 64;           // 0,64,128,192
    const int r0 = lane >> 2, c0 = lane & 3;

    // A staging: 128 rows x 8 float4 chunks = 1024 chunks, 4 per thread
    const int a_row = tid >> 3;              // 0..31 (+32 per iter)
    const int a_kq  = (tid & 7) * 4;         // 0..28
    const int KT = (K + 31) / 32;

    float acc[4][8][4];
#pragma unroll
    for (int mi = 0; mi < 4; mi++)
#pragma unroll
        for (int ni = 0; ni < 8; ni++)
#pragma unroll
            for (int c = 0; c < 4; c++) acc[mi][ni][c] = 0.f;

    // ---- B loader (cp.async, 3-stage ring): 32 k-rows x 256 n ----
    auto loadB = [&](int s) {
        const int buf = s % 3;
        const int k0  = s * 32;
#pragma unroll
        for (int i = 0; i < 8; i++) {
            int chunk = tid + i * 256;
            int k = chunk >> 6, n4 = (chunk & 63) * 4;
            uint32_t dst = bs_u32 + (buf * BS_STAGE + k * BS_STRIDE + n4) * 4;
            int gk = k0 + k;
            if (gk < K) cp16(dst, Wsel + (size_t)gk * 256 + n4);
            else {
                uint4 z = make_uint4(0, 0, 0, 0);
                *(uint4*)(Bs + buf * BS_STAGE + k * BS_STRIDE + n4) = z;
            }
        }
    };
    // ---- A: gmem -> regs (4 float4 per thread) ----
    float4 rA[4];
    auto ldgA = [&](int s) {
        int gk = s * 32 + a_kq;
#pragma unroll
        for (int i = 0; i < 4; i++) {
            int gr = bm + a_row + i * 32;
            rA[i] = make_float4(0.f, 0.f, 0.f, 0.f);
            if (gr < NN && gk < K) rA[i] = *(const float4*)(A + (size_t)gr * lda + gk);
        }
    };
    // ---- A: regs -> smem (rna tf32 rounding) ----
    auto stsA = [&](int s) {
        uint32_t* base = As + (s & 1) * AS_STAGE;
#pragma unroll
        for (int i = 0; i < 4; i++) {
            uint4 v;
            v.x = f2tf(rA[i].x); v.y = f2tf(rA[i].y);
            v.z = f2tf(rA[i].z); v.w = f2tf(rA[i].w);
            *(uint4*)(base + (a_row + i * 32) * AS_STRIDE + a_kq) = v;
        }
    };

    // ---- prologue ----
    loadB(0); asm volatile("cp.async.commit_group;" ::: "memory");
    loadB(1); asm volatile("cp.async.commit_group;" ::: "memory");
    ldgA(0); stsA(0);
    ldgA(1);
    asm volatile("cp.async.wait_group 1;" ::: "memory");   // B0 ready
    __syncthreads();

    for (int s = 0; s < KT; s++) {
        if (s + 1 < KT) stsA(s + 1);                       // A buf (s+1)&1: free
        if (s + 2 < KT) { ldgA(s + 2); loadB(s + 2); }     // B buf (s+2)%3: free
        asm volatile("cp.async.commit_group;" ::: "memory");

        const uint32_t* Ab = As + (s & 1) * AS_STAGE;
        const uint32_t* Bb = Bs + (s % 3) * BS_STAGE;
#pragma unroll
        for (int ks = 0; ks < 4; ks++) {
            const int k8 = ks * 8;
            uint32_t af[4][4], bf[8][2];
#pragma unroll
            for (int mi = 0; mi < 4; mi++) {
                int row = wm + mi * 16 + r0;
                af[mi][0] = Ab[(row    ) * AS_STRIDE + k8 + c0    ];
                af[mi][1] = Ab[(row + 8) * AS_STRIDE + k8 + c0    ];
                af[mi][2] = Ab[(row    ) * AS_STRIDE + k8 + c0 + 4];
                af[mi][3] = Ab[(row + 8) * AS_STRIDE + k8 + c0 + 4];
            }
#pragma unroll
            for (int ni = 0; ni < 8; ni++) {
                int col = wn + ni * 8 + r0;
                bf[ni][0] = Bb[(k8 + c0    ) * BS_STRIDE + col];
                bf[ni][1] = Bb[(k8 + c0 + 4) * BS_STRIDE + col];
            }
#pragma unroll
            for (int mi = 0; mi < 4; mi++)
#pragma unroll
                for (int ni = 0; ni < 8; ni++)
                    mma_tf32(acc[mi][ni], af[mi], bf[ni]);
        }

        if (s + 1 < KT) asm volatile("cp.async.wait_group 1;" ::: "memory"); // B(s+1) landed
        __syncthreads();
    }

    // ---- epilogue ----
    float2 b2[8];
    if (bx == 0) {
#pragma unroll
        for (int ni = 0; ni < 8; ni++) {
            int col = wn + ni * 8 + c0 * 2;
            b2[ni].x = bias[col]; b2[ni].y = bias[col + 1];
        }
    }
    float* OUT = (bx == 0) ? H : Qb;
#pragma unroll
    for (int mi = 0; mi < 4; mi++) {
#pragma unroll
        for (int ci = 0; ci < 2; ci++) {
            int row = bm + wm + mi * 16 + r0 + ci * 8;
            if (row >= NN) continue;
#pragma unroll
            for (int ni = 0; ni < 8; ni++) {
                int col = wn + ni * 8 + c0 * 2;
                float2 v;
                v.x = acc[mi][ni][ci * 2 + 0];
                v.y = acc[mi][ni][ci * 2 + 1];
                if (bx == 0) { v.x += b2[ni].x; v.y += b2[ni].y; }
                *(float2*)(OUT + (size_t)row * 256 + col) = v;
            }
        }
    }
}

// ---------------- gather SpMM: H[n] = relu(H[n] + sum_j w_j * Q[src_j]) -----
__global__ __launch_bounds__(256)
void spmm_kernel(const float* __restrict__ Q, float* __restrict__ H) {
    int gw   = (blockIdx.x * blockDim.x + threadIdx.x) >> 5;
    int lane = threadIdx.x & 31;
    if (gw >= NN) return;
    int beg = g_row_start[gw];
    int end = beg + g_cnt[gw];

    const float4* Q4 = (const float4*)Q;
    float4 acc0 = make_float4(0.f, 0.f, 0.f, 0.f);
    float4 acc1 = make_float4(0.f, 0.f, 0.f, 0.f);

    int j = beg;
    for (; j + 2 <= end; j += 2) {
        int   s0 = g_csr_src[j],   s1 = g_csr_src[j + 1];
        float w0 = g_csr_w[j],     w1 = g_csr_w[j + 1];
        float4 a0 = Q4[(size_t)s0 * 64 + lane];
        float4 b0 = Q4[(size_t)s0 * 64 + 32 + lane];
        float4 a1 = Q4[(size_t)s1 * 64 + lane];
        float4 b1 = Q4[(size_t)s1 * 64 + 32 + lane];
        acc0.x += w0 * a0.x + w1 * a1.x; acc0.y += w0 * a0.y + w1 * a1.y;
        acc0.z += w0 * a0.z + w1 * a1.z; acc0.w += w0 * a0.w + w1 * a1.w;
        acc1.x += w0 * b0.x + w1 * b1.x; acc1.y += w0 * b0.y + w1 * b1.y;
        acc1.z += w0 * b0.z + w1 * b1.z; acc1.w += w0 * b0.w + w1 * b1.w;
    }
    if (j < end) {
        int   s0 = g_csr_src[j];
        float w0 = g_csr_w[j];
        float4 a0 = Q4[(size_t)s0 * 64 + lane];
        float4 b0 = Q4[(size_t)s0 * 64 + 32 + lane];
        acc0.x += w0 * a0.x; acc0.y += w0 * a0.y; acc0.z += w0 * a0.z; acc0.w += w0 * a0.w;
        acc1.x += w0 * b0.x; acc1.y += w0 * b0.y; acc1.z += w0 * b0.z; acc1.w += w0 * b0.w;
    }

    float4* H4 = (float4*)H;
    size_t base = (size_t)gw * 64;
    float4 h0 = H4[base + lane];
    float4 h1 = H4[base + 32 + lane];
    h0.x = fmaxf(h0.x + acc0.x, 0.f); h0.y = fmaxf(h0.y + acc0.y, 0.f);
    h0.z = fmaxf(h0.z + acc0.z, 0.f); h0.w = fmaxf(h0.w + acc0.w, 0.f);
    h1.x = fmaxf(h1.x + acc1.x, 0.f); h1.y = fmaxf(h1.y + acc1.y, 0.f);
    h1.z = fmaxf(h1.z + acc1.z, 0.f); h1.w = fmaxf(h1.w + acc1.w, 0.f);
    H4[base + lane] = h0;
    H4[base + 32 + lane] = h1;
}

// ---------------- head (inputs already relu'd) ------------------------------
__global__ __launch_bounds__(256)
void head_kernel(const float* __restrict__ Wl, const float* __restrict__ bl,
                 float* __restrict__ out) {
    __shared__ float sW[768 * NC];
    int tid = threadIdx.x;
    for (int i = tid; i < 768 * NC; i += blockDim.x) sW[i] = Wl[i];
    __syncthreads();

    int lane = tid & 31;
    int node = blockIdx.x * (blockDim.x >> 5) + (tid >> 5);
    if (node >= NN) return;

    const float* h1 = g_h1 + (size_t)node * HID;
    const float* h2 = g_h2 + (size_t)node * HID;
    const float* h3 = g_h3 + (size_t)node * HID;

    float acc[NC];
#pragma unroll
    for (int c = 0; c < NC; c++) acc[c] = 0.f;

    for (int k = lane; k < HID; k += 32) {
        float v1 = h1[k], v2 = h2[k], v3 = h3[k];
#pragma unroll
        for (int c = 0; c < NC; c++)
            acc[c] += v1 * sW[k * NC + c]
                    + v2 * sW[(HID + k) * NC + c]
                    + v3 * sW[(2 * HID + k) * NC + c];
    }
#pragma unroll
    for (int c = 0; c < NC; c++)
        for (int off = 16; off > 0; off >>= 1)
            acc[c] += __shfl_down_sync(0xffffffffu, acc[c], off);

    if (lane == 0) {
        float lg[NC], mx = -1e30f;
#pragma unroll
        for (int c = 0; c < NC; c++) { lg[c] = acc[c] + bl[c]; mx = fmaxf(mx, lg[c]); }
        float s = 0.f;
#pragma unroll
        for (int c = 0; c < NC; c++) s += expf(lg[c] - mx);
        float lse = mx + logf(s);
#pragma unroll
        for (int c = 0; c < NC; c++) out[(size_t)node * NC + c] = lg[c] - lse;
    }
}

// ---------------------------------------------------------------------------
extern "C" void kernel_launch(void* const* d_in, const int* in_sizes, int n_in,
                              void* d_out, int out_size) {
    const float* x  = (const float*)d_in[0];
    const int*   ei = (const int*)d_in[1];
    const float* ew = (const float*)d_in[2];
    const float* W1 = (const float*)d_in[3];
    const float* b1 = (const float*)d_in[4];
    const float* W2 = (const float*)d_in[5];
    const float* b2 = (const float*)d_in[6];
    const float* W3 = (const float*)d_in[7];
    const float* b3 = (const float*)d_in[8];
    const float* Wl = (const float*)d_in[9];
    const float* bl = (const float*)d_in[10];
    float* out = (float*)d_out;

    const int* src = ei;
    const int* dst = ei + NE;

    float *h1, *h2, *h3, *q, *w1r, *w2r, *w3r;
    cudaGetSymbolAddress((void**)&h1,  g_h1);
    cudaGetSymbolAddress((void**)&h2,  g_h2);
    cudaGetSymbolAddress((void**)&h3,  g_h3);
    cudaGetSymbolAddress((void**)&q,   g_q);
    cudaGetSymbolAddress((void**)&w1r, g_w1r);
    cudaGetSymbolAddress((void**)&w2r, g_w2r);
    cudaGetSymbolAddress((void**)&w3r, g_w3r);

    const int SMEM_B = SMEM_WORDS * 4;
    cudaFuncSetAttribute(gemm_tc, cudaFuncAttributeMaxDynamicSharedMemorySize, SMEM_B);

    const int T = 256;
    dim3 gemm_grid(2, (NN + 127) / 128);
    const int node_warps = (NN + 7) / 8;
    const int wtot = W1N + 2 * W2N;

    zero_cnt<<<NBLK, SCAN_T>>>();                                    // 0
    count_kernel<<<(NE + T - 1) / T, T>>>(dst);                      // 1
    cvt_w<<<(wtot + T - 1) / T, T>>>(W1, W2, W3);                    // 2
    gemm_tc<<<gemm_grid, T, SMEM_B>>>(x, F0, F0, w1r, b1, h1, q);    // 3 <- profiled
    scanA<<<NBLK, SCAN_T>>>();                                       // 4
    scanB<<<1, 512>>>();                                             // 5
    scanC<<<NBLK, SCAN_T>>>();                                       // 6
    place_kernel<<<(NE + T - 1) / T, T>>>(src, dst, ew);             // 7

    spmm_kernel<<<node_warps, T>>>(q, h1);                           // 8

    gemm_tc<<<gemm_grid, T, SMEM_B>>>(h1, HID, HID, w2r, b2, h2, q);
    spmm_kernel<<<node_warps, T>>>(q, h2);

    gemm_tc<<<gemm_grid, T, SMEM_B>>>(h2, HID, HID, w3r, b3, h3, q);
    spmm_kernel<<<node_warps, T>>>(q, h3);

    head_kernel<<<(NN + 7) / 8, T>>>(Wl, bl, out);
}

// round 8
// speedup vs baseline: 4.7472x; 1.0037x over previous
#include <cuda_runtime.h>
#include <cstdint>

#define NN 89250
#define NE 899756
#define F0 500
#define HID 256
#define NC  7
#define SCAN_T 256
#define NBLK ((NN + SCAN_T - 1) / SCAN_T)   // 349
#define KP1 512                              // layer-1 K padded
#define KP2 256

// ---------------- scratch (device globals) ---------------------------------
__device__ __align__(256) float g_h1[(size_t)NN * HID];
__device__ __align__(256) float g_h2[(size_t)NN * HID];
__device__ __align__(256) float g_h3[(size_t)NN * HID];
__device__ __align__(256) float g_q [(size_t)NN * HID];
// transposed tf32-rounded weights: [half(P/Q)][n 0..255][k 0..KP)
__device__ __align__(256) uint32_t g_w1t[2 * 256 * KP1];
__device__ __align__(256) uint32_t g_w2t[2 * 256 * KP2];
__device__ __align__(256) uint32_t g_w3t[2 * 256 * KP2];
__device__ int   g_cnt[NN];
__device__ int   g_row_start[NN];
__device__ int   g_row_fill[NN];
__device__ int   g_bsum[NBLK];
__device__ int   g_csr_src[NE];
__device__ float g_csr_w[NE];

#define W1TN (2 * 256 * KP1)   // 262144
#define W2TN (2 * 256 * KP2)   // 131072

// ---------------- CSR build kernels -----------------------------------------
__global__ void zero_cnt() {
    int i = blockIdx.x * blockDim.x + threadIdx.x;
    if (i < NN) g_cnt[i] = 0;
}
__global__ void count_kernel(const int* __restrict__ dst) {
    int e = blockIdx.x * blockDim.x + threadIdx.x;
    if (e < NE) atomicAdd(&g_cnt[dst[e]], 1);
}
__global__ void scanA() {
    __shared__ int s[SCAN_T];
    int t = threadIdx.x;
    int i = blockIdx.x * SCAN_T + t;
    s[t] = (i < NN) ? g_cnt[i] : 0;
    __syncthreads();
#pragma unroll
    for (int off = SCAN_T / 2; off > 0; off >>= 1) {
        if (t < off) s[t] += s[t + off];
        __syncthreads();
    }
    if (t == 0) g_bsum[blockIdx.x] = s[0];
}
__global__ void scanB() {
    __shared__ int s[512];
    int t = threadIdx.x;
    int v = (t < NBLK) ? g_bsum[t] : 0;
    s[t] = v;
    __syncthreads();
#pragma unroll
    for (int off = 1; off < 512; off <<= 1) {
        int x = (t >= off) ? s[t - off] : 0;
        __syncthreads();
        s[t] += x;
        __syncthreads();
    }
    if (t < NBLK) g_bsum[t] = s[t] - v;   // exclusive
}
__global__ void scanC() {
    __shared__ int s[SCAN_T];
    int t = threadIdx.x;
    int i = blockIdx.x * SCAN_T + t;
    int v = (i < NN) ? g_cnt[i] : 0;
    s[t] = v;
    __syncthreads();
#pragma unroll
    for (int off = 1; off < SCAN_T; off <<= 1) {
        int x = (t >= off) ? s[t - off] : 0;
        __syncthreads();
        s[t] += x;
        __syncthreads();
    }
    if (i < NN) {
        int excl = s[t] - v + g_bsum[blockIdx.x];
        g_row_start[i] = excl;
        g_row_fill[i]  = excl;
    }
}
__global__ void place_kernel(const int* __restrict__ src, const int* __restrict__ dst,
                             const float* __restrict__ ew) {
    int e = blockIdx.x * blockDim.x + threadIdx.x;
    if (e >= NE) return;
    int d = dst[e];
    int slot = atomicAdd(&g_row_fill[d], 1);
    g_csr_src[slot] = src[e];
    g_csr_w[slot]   = ew[e] / fmaxf((float)g_cnt[d], 1.0f);
}

// ---------------- tf32 helpers ------------------------------------------------
__device__ __forceinline__ uint32_t f2tf(float f) {
    uint32_t r;
    asm("cvt.rna.tf32.f32 %0, %1;" : "=r"(r) : "f"(f));
    return r;
}
__device__ __forceinline__ void mma_tf32(float c[4], const uint32_t a[4],
                                         uint32_t b0, uint32_t b1) {
    asm volatile(
        "mma.sync.aligned.m16n8k8.row.col.f32.tf32.tf32.f32 "
        "{%0,%1,%2,%3}, {%4,%5,%6,%7}, {%8,%9}, {%0,%1,%2,%3};"
        : "+f"(c[0]), "+f"(c[1]), "+f"(c[2]), "+f"(c[3])
        : "r"(a[0]), "r"(a[1]), "r"(a[2]), "r"(a[3]), "r"(b0), "r"(b1));
}
__device__ __forceinline__ void ldsm4(uint32_t r[4], uint32_t addr) {
    asm volatile("ldmatrix.sync.aligned.m8n8.x4.shared.b16 {%0,%1,%2,%3}, [%4];"
                 : "=r"(r[0]), "=r"(r[1]), "=r"(r[2]), "=r"(r[3]) : "r"(addr));
}
__device__ __forceinline__ void cp16(uint32_t dst, const void* src) {
    asm volatile("cp.async.cg.shared.global [%0], [%1], 16;" :: "r"(dst), "l"(src));
}
__device__ __forceinline__ uint32_t smem_u32(const void* p) {
    uint32_t a;
    asm("{ .reg .u64 t; cvta.to.shared.u64 t, %1; cvt.u32.u64 %0, t; }" : "=r"(a) : "l"(p));
    return a;
}

// transpose + tf32-round weights: Wt[half][n][k] = rna(W[half*K + k][n]); K-pad zeros
__global__ void cvt_wt(const float* __restrict__ W1, const float* __restrict__ W2,
                       const float* __restrict__ W3) {
    int i = blockIdx.x * blockDim.x + threadIdx.x;
    if (i < W1TN) {
        int half = i >> 17;                 // 256*512 = 131072 per half
        int rem  = i & 131071;
        int n = rem >> 9, k = rem & 511;
        g_w1t[i] = (k < F0) ? f2tf(W1[((size_t)half * F0 + k) * 256 + n]) : 0u;
    } else if (i < W1TN + W2TN) {
        int j = i - W1TN;
        int half = j >> 16;                 // 256*256 = 65536 per half
        int rem  = j & 65535;
        int n = rem >> 8, k = rem & 255;
        g_w2t[j] = f2tf(W2[((size_t)half * HID + k) * 256 + n]);
    } else if (i < W1TN + 2 * W2TN) {
        int j = i - W1TN - W2TN;
        int half = j >> 16;
        int rem  = j & 65535;
        int n = rem >> 8, k = rem & 255;
        g_w3t[j] = f2tf(W3[((size_t)half * HID + k) * 256 + n]);
    }
}

// ---------------- tf32 SAGE GEMM: block 128x256, warp 64x64, K-stage 32 -----
// grid = (2, ceil(NN/128)). bx=0: OUT = A@Wtop + bias -> H; bx=1: OUT = A@Wbot -> Q
// A: [2][128 m][36] k-major rows. B: [3][256 n][36] n-major rows (k contiguous).
// All fragment loads are LDSM.x4.
#define AS_STRIDE 36
#define BS_STRIDE 36
#define AS_STAGE  (128 * AS_STRIDE)     // 4608 words
#define BS_STAGE  (256 * BS_STRIDE)     // 9216 words
#define SMEM_WORDS (2 * AS_STAGE + 3 * BS_STAGE)   // 36864 words = 147456 B

__global__ __launch_bounds__(256, 1)
void gemm_tc(const float* __restrict__ A, int K, int lda, int KP,
             const uint32_t* __restrict__ Wt,   // [2][256][KP] transposed tf32
             const float* __restrict__ bias,
             float* __restrict__ H, float* __restrict__ Qb)
{
    extern __shared__ uint32_t sm[];
    uint32_t* As = sm;                       // [2][128][36]
    uint32_t* Bs = sm + 2 * AS_STAGE;        // [3][256][36]
    const uint32_t sb = smem_u32(sm);
    const uint32_t sbB = sb + 2 * AS_STAGE * 4;

    const int bx = blockIdx.x;               // 0 = P path, 1 = Q path
    const int bm = blockIdx.y * 128;
    const uint32_t* Wsel = Wt + (size_t)bx * 256 * KP;

    const int tid  = threadIdx.x;
    const int wid  = tid >> 5;
    const int lane = tid & 31;
    const int wm = (wid >> 2) * 64;          // 0,64
    const int wn = (wid & 3) * 64;           // 0,64,128,192
    const int r0 = lane >> 2, c0 = lane & 3;

    // LDSM lane address components
    const int al_row = lane & 15;
    const int al_w   = (lane >> 4) * 4;
    const int bl_n   = (lane & 7) + ((lane >> 4) & 1) * 8;
    const int bl_w   = ((lane >> 3) & 1) * 4;

    // A staging: 128 rows x 8 float4 chunks = 1024 chunks, 4 per thread
    const int a_row = tid >> 3;              // 0..31 (+32 per iter)
    const int a_kq  = (tid & 7) * 4;
    const int KT = KP / 32;

    float acc[4][8][4];
#pragma unroll
    for (int mi = 0; mi < 4; mi++)
#pragma unroll
        for (int ni = 0; ni < 8; ni++)
#pragma unroll
            for (int c = 0; c < 4; c++) acc[mi][ni][c] = 0.f;

    // ---- B loader (cp.async, 3-stage ring): 256 n-rows x 32 k-words ----
    auto loadB = [&](int s) {
        const int buf = s % 3;
        const int k0  = s * 32;
#pragma unroll
        for (int i = 0; i < 8; i++) {
            int c = tid + i * 256;
            int n = c >> 3, kc = (c & 7) * 4;
            uint32_t dst = sbB + (buf * BS_STAGE + n * BS_STRIDE + kc) * 4;
            cp16(dst, Wsel + (size_t)n * KP + k0 + kc);    // K padded: no bound
        }
    };
    // ---- A: gmem -> regs (4 float4 per thread) ----
    float4 rA[4];
    auto ldgA = [&](int s) {
        int gk = s * 32 + a_kq;
#pragma unroll
        for (int i = 0; i < 4; i++) {
            int gr = bm + a_row + i * 32;
            rA[i] = make_float4(0.f, 0.f, 0.f, 0.f);
            if (gr < NN && gk < K) rA[i] = *(const float4*)(A + (size_t)gr * lda + gk);
        }
    };
    // ---- A: regs -> smem (rna tf32 rounding) ----
    auto stsA = [&](int s) {
        uint32_t* base = As + (s & 1) * AS_STAGE;
#pragma unroll
        for (int i = 0; i < 4; i++) {
            uint4 v;
            v.x = f2tf(rA[i].x); v.y = f2tf(rA[i].y);
            v.z = f2tf(rA[i].z); v.w = f2tf(rA[i].w);
            *(uint4*)(base + (a_row + i * 32) * AS_STRIDE + a_kq) = v;
        }
    };

    // ---- prologue ----
    loadB(0); asm volatile("cp.async.commit_group;" ::: "memory");
    loadB(1); asm volatile("cp.async.commit_group;" ::: "memory");
    ldgA(0); stsA(0);
    ldgA(1);
    asm volatile("cp.async.wait_group 1;" ::: "memory");   // B0 ready
    __syncthreads();

    for (int s = 0; s < KT; s++) {
        if (s + 1 < KT) stsA(s + 1);
        if (s + 2 < KT) { ldgA(s + 2); loadB(s + 2); }
        asm volatile("cp.async.commit_group;" ::: "memory");

        const uint32_t aB = sb  + ((s & 1) * AS_STAGE) * 4;
        const uint32_t bB = sbB + ((s % 3) * BS_STAGE) * 4;
#pragma unroll
        for (int ks = 0; ks < 4; ks++) {
            const int k8 = ks * 8;
            uint32_t af[4][4], bfr[16];
#pragma unroll
            for (int mi = 0; mi < 4; mi++)
                ldsm4(af[mi], aB + ((wm + mi * 16 + al_row) * AS_STRIDE + k8 + al_w) * 4);
#pragma unroll
            for (int nip = 0; nip < 4; nip++)
                ldsm4(&bfr[nip * 4],
                      bB + ((wn + nip * 16 + bl_n) * BS_STRIDE + k8 + bl_w) * 4);
#pragma unroll
            for (int mi = 0; mi < 4; mi++)
#pragma unroll
                for (int ni = 0; ni < 8; ni++)
                    mma_tf32(acc[mi][ni], af[mi], bfr[ni * 2], bfr[ni * 2 + 1]);
        }

        if (s + 1 < KT) asm volatile("cp.async.wait_group 1;" ::: "memory");
        __syncthreads();
    }

    // ---- epilogue ----
    float2 b2[8];
    if (bx == 0) {
#pragma unroll
        for (int ni = 0; ni < 8; ni++) {
            int col = wn + ni * 8 + c0 * 2;
            b2[ni].x = bias[col]; b2[ni].y = bias[col + 1];
        }
    }
    float* OUT = (bx == 0) ? H : Qb;
#pragma unroll
    for (int mi = 0; mi < 4; mi++) {
#pragma unroll
        for (int ci = 0; ci < 2; ci++) {
            int row = bm + wm + mi * 16 + r0 + ci * 8;
            if (row >= NN) continue;
#pragma unroll
            for (int ni = 0; ni < 8; ni++) {
                int col = wn + ni * 8 + c0 * 2;
                float2 v;
                v.x = acc[mi][ni][ci * 2 + 0];
                v.y = acc[mi][ni][ci * 2 + 1];
                if (bx == 0) { v.x += b2[ni].x; v.y += b2[ni].y; }
                *(float2*)(OUT + (size_t)row * 256 + col) = v;
            }
        }
    }
}

// ---------------- gather SpMM: H[n] = relu(H[n] + sum_j w_j * Q[src_j]) -----
__global__ __launch_bounds__(256)
void spmm_kernel(const float* __restrict__ Q, float* __restrict__ H) {
    int gw   = (blockIdx.x * blockDim.x + threadIdx.x) >> 5;
    int lane = threadIdx.x & 31;
    if (gw >= NN) return;
    int beg = g_row_start[gw];
    int end = beg + g_cnt[gw];

    const float4* Q4 = (const float4*)Q;
    float4 acc0 = make_float4(0.f, 0.f, 0.f, 0.f);
    float4 acc1 = make_float4(0.f, 0.f, 0.f, 0.f);

    int j = beg;
    for (; j + 2 <= end; j += 2) {
        int   s0 = g_csr_src[j],   s1 = g_csr_src[j + 1];
        float w0 = g_csr_w[j],     w1 = g_csr_w[j + 1];
        float4 a0 = Q4[(size_t)s0 * 64 + lane];
        float4 b0 = Q4[(size_t)s0 * 64 + 32 + lane];
        float4 a1 = Q4[(size_t)s1 * 64 + lane];
        float4 b1 = Q4[(size_t)s1 * 64 + 32 + lane];
        acc0.x += w0 * a0.x + w1 * a1.x; acc0.y += w0 * a0.y + w1 * a1.y;
        acc0.z += w0 * a0.z + w1 * a1.z; acc0.w += w0 * a0.w + w1 * a1.w;
        acc1.x += w0 * b0.x + w1 * b1.x; acc1.y += w0 * b0.y + w1 * b1.y;
        acc1.z += w0 * b0.z + w1 * b1.z; acc1.w += w0 * b0.w + w1 * b1.w;
    }
    if (j < end) {
        int   s0 = g_csr_src[j];
        float w0 = g_csr_w[j];
        float4 a0 = Q4[(size_t)s0 * 64 + lane];
        float4 b0 = Q4[(size_t)s0 * 64 + 32 + lane];
        acc0.x += w0 * a0.x; acc0.y += w0 * a0.y; acc0.z += w0 * a0.z; acc0.w += w0 * a0.w;
        acc1.x += w0 * b0.x; acc1.y += w0 * b0.y; acc1.z += w0 * b0.z; acc1.w += w0 * b0.w;
    }

    float4* H4 = (float4*)H;
    size_t base = (size_t)gw * 64;
    float4 h0 = H4[base + lane];
    float4 h1 = H4[base + 32 + lane];
    h0.x = fmaxf(h0.x + acc0.x, 0.f); h0.y = fmaxf(h0.y + acc0.y, 0.f);
    h0.z = fmaxf(h0.z + acc0.z, 0.f); h0.w = fmaxf(h0.w + acc0.w, 0.f);
    h1.x = fmaxf(h1.x + acc1.x, 0.f); h1.y = fmaxf(h1.y + acc1.y, 0.f);
    h1.z = fmaxf(h1.z + acc1.z, 0.f); h1.w = fmaxf(h1.w + acc1.w, 0.f);
    H4[base + lane] = h0;
    H4[base + 32 + lane] = h1;
}

// ---------------- head (inputs already relu'd) ------------------------------
__global__ __launch_bounds__(256)
void head_kernel(const float* __restrict__ Wl, const float* __restrict__ bl,
                 float* __restrict__ out) {
    __shared__ float sW[768 * NC];
    int tid = threadIdx.x;
    for (int i = tid; i < 768 * NC; i += blockDim.x) sW[i] = Wl[i];
    __syncthreads();

    int lane = tid & 31;
    int node = blockIdx.x * (blockDim.x >> 5) + (tid >> 5);
    if (node >= NN) return;

    const float* h1 = g_h1 + (size_t)node * HID;
    const float* h2 = g_h2 + (size_t)node * HID;
    const float* h3 = g_h3 + (size_t)node * HID;

    float acc[NC];
#pragma unroll
    for (int c = 0; c < NC; c++) acc[c] = 0.f;

    for (int k = lane; k < HID; k += 32) {
        float v1 = h1[k], v2 = h2[k], v3 = h3[k];
#pragma unroll
        for (int c = 0; c < NC; c++)
            acc[c] += v1 * sW[k * NC + c]
                    + v2 * sW[(HID + k) * NC + c]
                    + v3 * sW[(2 * HID + k) * NC + c];
    }
#pragma unroll
    for (int c = 0; c < NC; c++)
        for (int off = 16; off > 0; off >>= 1)
            acc[c] += __shfl_down_sync(0xffffffffu, acc[c], off);

    if (lane == 0) {
        float lg[NC], mx = -1e30f;
#pragma unroll
        for (int c = 0; c < NC; c++) { lg[c] = acc[c] + bl[c]; mx = fmaxf(mx, lg[c]); }
        float s = 0.f;
#pragma unroll
        for (int c = 0; c < NC; c++) s += expf(lg[c] - mx);
        float lse = mx + logf(s);
#pragma unroll
        for (int c = 0; c < NC; c++) out[(size_t)node * NC + c] = lg[c] - lse;
    }
}

// ---------------------------------------------------------------------------
extern "C" void kernel_launch(void* const* d_in, const int* in_sizes, int n_in,
                              void* d_out, int out_size) {
    const float* x  = (const float*)d_in[0];
    const int*   ei = (const int*)d_in[1];
    const float* ew = (const float*)d_in[2];
    const float* W1 = (const float*)d_in[3];
    const float* b1 = (const float*)d_in[4];
    const float* W2 = (const float*)d_in[5];
    const float* b2 = (const float*)d_in[6];
    const float* W3 = (const float*)d_in[7];
    const float* b3 = (const float*)d_in[8];
    const float* Wl = (const float*)d_in[9];
    const float* bl = (const float*)d_in[10];
    float* out = (float*)d_out;

    const int* src = ei;
    const int* dst = ei + NE;

    float *h1, *h2, *h3, *q;
    uint32_t *w1t, *w2t, *w3t;
    cudaGetSymbolAddress((void**)&h1,  g_h1);
    cudaGetSymbolAddress((void**)&h2,  g_h2);
    cudaGetSymbolAddress((void**)&h3,  g_h3);
    cudaGetSymbolAddress((void**)&q,   g_q);
    cudaGetSymbolAddress((void**)&w1t, g_w1t);
    cudaGetSymbolAddress((void**)&w2t, g_w2t);
    cudaGetSymbolAddress((void**)&w3t, g_w3t);

    const int SMEM_B = SMEM_WORDS * 4;
    cudaFuncSetAttribute(gemm_tc, cudaFuncAttributeMaxDynamicSharedMemorySize, SMEM_B);

    const int T = 256;
    dim3 gemm_grid(2, (NN + 127) / 128);
    const int node_warps = (NN + 7) / 8;
    const int wtot = W1TN + 2 * W2TN;

    zero_cnt<<<NBLK, SCAN_T>>>();                                    // 0
    count_kernel<<<(NE + T - 1) / T, T>>>(dst);                      // 1
    cvt_wt<<<(wtot + T - 1) / T, T>>>(W1, W2, W3);                   // 2
    gemm_tc<<<gemm_grid, T, SMEM_B>>>(x, F0, F0, KP1, w1t, b1, h1, q); // 3 <- profiled
    scanA<<<NBLK, SCAN_T>>>();                                       // 4
    scanB<<<1, 512>>>();                                             // 5
    scanC<<<NBLK, SCAN_T>>>();                                       // 6
    place_kernel<<<(NE + T - 1) / T, T>>>(src, dst, ew);             // 7

    spmm_kernel<<<node_warps, T>>>(q, h1);                           // 8

    gemm_tc<<<gemm_grid, T, SMEM_B>>>(h1, HID, HID, KP2, w2t, b2, h2, q);
    spmm_kernel<<<node_warps, T>>>(q, h2);

    gemm_tc<<<gemm_grid, T, SMEM_B>>>(h2, HID, HID, KP2, w3t, b3, h3, q);
    spmm_kernel<<<node_warps, T>>>(q, h3);

    head_kernel<<<(NN + 7) / 8, T>>>(Wl, bl, out);
}

// round 9
// speedup vs baseline: 4.7589x; 1.0025x over previous
#include <cuda_runtime.h>
#include <cstdint>

#define NN 89250
#define NE 899756
#define F0 500
#define HID 256
#define NC  7
#define SCAN_T 256
#define NBLK ((NN + SCAN_T - 1) / SCAN_T)   // 349
#define KP1 512                              // layer-1 K padded
#define KP2 256

// ---------------- scratch (device globals) ---------------------------------
__device__ __align__(256) float g_h1[(size_t)NN * HID];
__device__ __align__(256) float g_h2[(size_t)NN * HID];
__device__ __align__(256) float g_h3[(size_t)NN * HID];
__device__ __align__(256) float g_q [(size_t)NN * HID];
// transposed tf32-rounded weights: [half(P/Q)][n 0..255][k 0..KP)
__device__ __align__(256) uint32_t g_w1t[2 * 256 * KP1];
__device__ __align__(256) uint32_t g_w2t[2 * 256 * KP2];
__device__ __align__(256) uint32_t g_w3t[2 * 256 * KP2];
__device__ int   g_cnt[NN];
__device__ int   g_row_start[NN];
__device__ int   g_row_fill[NN];
__device__ int   g_bsum[NBLK];
__device__ int   g_csr_src[NE];
__device__ float g_csr_w[NE];

#define W1TN (2 * 256 * KP1)   // 262144
#define W2TN (2 * 256 * KP2)   // 131072

// ---------------- CSR build kernels -----------------------------------------
__global__ void zero_cnt() {
    int i = blockIdx.x * blockDim.x + threadIdx.x;
    if (i < NN) g_cnt[i] = 0;
}
__global__ void count_kernel(const int* __restrict__ dst) {
    int e = blockIdx.x * blockDim.x + threadIdx.x;
    if (e < NE) atomicAdd(&g_cnt[dst[e]], 1);
}
__global__ void scanA() {
    __shared__ int s[SCAN_T];
    int t = threadIdx.x;
    int i = blockIdx.x * SCAN_T + t;
    s[t] = (i < NN) ? g_cnt[i] : 0;
    __syncthreads();
#pragma unroll
    for (int off = SCAN_T / 2; off > 0; off >>= 1) {
        if (t < off) s[t] += s[t + off];
        __syncthreads();
    }
    if (t == 0) g_bsum[blockIdx.x] = s[0];
}
__global__ void scanB() {
    __shared__ int s[512];
    int t = threadIdx.x;
    int v = (t < NBLK) ? g_bsum[t] : 0;
    s[t] = v;
    __syncthreads();
#pragma unroll
    for (int off = 1; off < 512; off <<= 1) {
        int x = (t >= off) ? s[t - off] : 0;
        __syncthreads();
        s[t] += x;
        __syncthreads();
    }
    if (t < NBLK) g_bsum[t] = s[t] - v;   // exclusive
}
__global__ void scanC() {
    __shared__ int s[SCAN_T];
    int t = threadIdx.x;
    int i = blockIdx.x * SCAN_T + t;
    int v = (i < NN) ? g_cnt[i] : 0;
    s[t] = v;
    __syncthreads();
#pragma unroll
    for (int off = 1; off < SCAN_T; off <<= 1) {
        int x = (t >= off) ? s[t - off] : 0;
        __syncthreads();
        s[t] += x;
        __syncthreads();
    }
    if (i < NN) {
        int excl = s[t] - v + g_bsum[blockIdx.x];
        g_row_start[i] = excl;
        g_row_fill[i]  = excl;
    }
}
__global__ void place_kernel(const int* __restrict__ src, const int* __restrict__ dst,
                             const float* __restrict__ ew) {
    int e = blockIdx.x * blockDim.x + threadIdx.x;
    if (e >= NE) return;
    int d = dst[e];
    int slot = atomicAdd(&g_row_fill[d], 1);
    g_csr_src[slot] = src[e];
    g_csr_w[slot]   = ew[e] / fmaxf((float)g_cnt[d], 1.0f);
}

// ---------------- tf32 helpers ------------------------------------------------
__device__ __forceinline__ uint32_t f2tf(float f) {
    uint32_t r;
    asm("cvt.rna.tf32.f32 %0, %1;" : "=r"(r) : "f"(f));
    return r;
}
__device__ __forceinline__ void mma_tf32(float c[4], const uint32_t a[4],
                                         uint32_t b0, uint32_t b1) {
    asm volatile(
        "mma.sync.aligned.m16n8k8.row.col.f32.tf32.tf32.f32 "
        "{%0,%1,%2,%3}, {%4,%5,%6,%7}, {%8,%9}, {%0,%1,%2,%3};"
        : "+f"(c[0]), "+f"(c[1]), "+f"(c[2]), "+f"(c[3])
        : "r"(a[0]), "r"(a[1]), "r"(a[2]), "r"(a[3]), "r"(b0), "r"(b1));
}
__device__ __forceinline__ void ldsm4(uint32_t r[4], uint32_t addr) {
    asm volatile("ldmatrix.sync.aligned.m8n8.x4.shared.b16 {%0,%1,%2,%3}, [%4];"
                 : "=r"(r[0]), "=r"(r[1]), "=r"(r[2]), "=r"(r[3]) : "r"(addr));
}
__device__ __forceinline__ void cp16(uint32_t dst, const void* src) {
    asm volatile("cp.async.cg.shared.global [%0], [%1], 16;" :: "r"(dst), "l"(src));
}
__device__ __forceinline__ uint32_t smem_u32(const void* p) {
    uint32_t a;
    asm("{ .reg .u64 t; cvta.to.shared.u64 t, %1; cvt.u32.u64 %0, t; }" : "=r"(a) : "l"(p));
    return a;
}

// transpose + tf32-round weights: Wt[half][n][k] = rna(W[half*K + k][n]); K-pad zeros
__global__ void cvt_wt(const float* __restrict__ W1, const float* __restrict__ W2,
                       const float* __restrict__ W3) {
    int i = blockIdx.x * blockDim.x + threadIdx.x;
    if (i < W1TN) {
        int half = i >> 17;
        int rem  = i & 131071;
        int n = rem >> 9, k = rem & 511;
        g_w1t[i] = (k < F0) ? f2tf(W1[((size_t)half * F0 + k) * 256 + n]) : 0u;
    } else if (i < W1TN + W2TN) {
        int j = i - W1TN;
        int half = j >> 16;
        int rem  = j & 65535;
        int n = rem >> 8, k = rem & 255;
        g_w2t[j] = f2tf(W2[((size_t)half * HID + k) * 256 + n]);
    } else if (i < W1TN + 2 * W2TN) {
        int j = i - W1TN - W2TN;
        int half = j >> 16;
        int rem  = j & 65535;
        int n = rem >> 8, k = rem & 255;
        g_w3t[j] = f2tf(W3[((size_t)half * HID + k) * 256 + n]);
    }
}

// ---------------- tf32 SAGE GEMM: 512 thr, block 128x256, warp 32x64 --------
// grid = (2, ceil(NN/128)). bx=0: OUT = A@Wtop + bias -> H; bx=1: OUT = A@Wbot -> Q
// 16 warps in 4x4 grid: wm = (wid>>2)*32, wn = (wid&3)*64. 4 warps/SMSP.
#define AS_STRIDE 36
#define BS_STRIDE 36
#define AS_STAGE  (128 * AS_STRIDE)     // 4608 words
#define BS_STAGE  (256 * BS_STRIDE)     // 9216 words
#define SMEM_WORDS (2 * AS_STAGE + 3 * BS_STAGE)   // 36864 words = 147456 B

__global__ __launch_bounds__(512, 1)
void gemm_tc(const float* __restrict__ A, int K, int lda, int KP,
             const uint32_t* __restrict__ Wt,   // [2][256][KP] transposed tf32
             const float* __restrict__ bias,
             float* __restrict__ H, float* __restrict__ Qb)
{
    extern __shared__ uint32_t sm[];
    uint32_t* As = sm;                       // [2][128][36]
    const uint32_t sb = smem_u32(sm);
    const uint32_t sbB = sb + 2 * AS_STAGE * 4;

    const int bx = blockIdx.x;               // 0 = P path, 1 = Q path
    const int bm = blockIdx.y * 128;
    const uint32_t* Wsel = Wt + (size_t)bx * 256 * KP;

    const int tid  = threadIdx.x;
    const int wid  = tid >> 5;
    const int lane = tid & 31;
    const int wm = (wid >> 2) * 32;          // 0,32,64,96
    const int wn = (wid & 3) * 64;           // 0,64,128,192
    const int r0 = lane >> 2, c0 = lane & 3;

    // LDSM lane address components
    const int al_row = lane & 15;
    const int al_w   = (lane >> 4) * 4;
    const int bl_n   = (lane & 7) + ((lane >> 4) & 1) * 8;
    const int bl_w   = ((lane >> 3) & 1) * 4;

    // A staging: 128 rows x 8 float4 chunks = 1024 chunks, 2 per thread
    const int a_row = tid >> 3;              // 0..63 (+64 on 2nd)
    const int a_kq  = (tid & 7) * 4;
    const int KT = KP / 32;

    float acc[2][8][4];
#pragma unroll
    for (int mi = 0; mi < 2; mi++)
#pragma unroll
        for (int ni = 0; ni < 8; ni++)
#pragma unroll
            for (int c = 0; c < 4; c++) acc[mi][ni][c] = 0.f;

    // ---- B loader (cp.async, 3-stage ring): 256 n-rows x 32 k-words ----
    auto loadB = [&](int s) {
        const int buf = s % 3;
        const int k0  = s * 32;
#pragma unroll
        for (int i = 0; i < 4; i++) {
            int c = tid + i * 512;
            int n = c >> 3, kc = (c & 7) * 4;
            uint32_t dst = sbB + (buf * BS_STAGE + n * BS_STRIDE + kc) * 4;
            cp16(dst, Wsel + (size_t)n * KP + k0 + kc);    // K padded: no bound
        }
    };
    // ---- A: gmem -> regs (2 float4 per thread) ----
    float4 rA[2];
    auto ldgA = [&](int s) {
        int gk = s * 32 + a_kq;
#pragma unroll
        for (int i = 0; i < 2; i++) {
            int gr = bm + a_row + i * 64;
            rA[i] = make_float4(0.f, 0.f, 0.f, 0.f);
            if (gr < NN && gk < K) rA[i] = *(const float4*)(A + (size_t)gr * lda + gk);
        }
    };
    // ---- A: regs -> smem (rna tf32 rounding) ----
    auto stsA = [&](int s) {
        uint32_t* base = As + (s & 1) * AS_STAGE;
#pragma unroll
        for (int i = 0; i < 2; i++) {
            uint4 v;
            v.x = f2tf(rA[i].x); v.y = f2tf(rA[i].y);
            v.z = f2tf(rA[i].z); v.w = f2tf(rA[i].w);
            *(uint4*)(base + (a_row + i * 64) * AS_STRIDE + a_kq) = v;
        }
    };

    // ---- prologue ----
    loadB(0); asm volatile("cp.async.commit_group;" ::: "memory");
    loadB(1); asm volatile("cp.async.commit_group;" ::: "memory");
    ldgA(0); stsA(0);
    ldgA(1);
    asm volatile("cp.async.wait_group 1;" ::: "memory");   // B0 ready
    __syncthreads();

    for (int s = 0; s < KT; s++) {
        if (s + 1 < KT) stsA(s + 1);
        if (s + 2 < KT) { ldgA(s + 2); loadB(s + 2); }
        asm volatile("cp.async.commit_group;" ::: "memory");

        const uint32_t aB = sb  + ((s & 1) * AS_STAGE) * 4;
        const uint32_t bB = sbB + ((s % 3) * BS_STAGE) * 4;
#pragma unroll
        for (int ks = 0; ks < 4; ks++) {
            const int k8 = ks * 8;
            uint32_t af[2][4], bfr[16];
#pragma unroll
            for (int mi = 0; mi < 2; mi++)
                ldsm4(af[mi], aB + ((wm + mi * 16 + al_row) * AS_STRIDE + k8 + al_w) * 4);
#pragma unroll
            for (int nip = 0; nip < 4; nip++)
                ldsm4(&bfr[nip * 4],
                      bB + ((wn + nip * 16 + bl_n) * BS_STRIDE + k8 + bl_w) * 4);
#pragma unroll
            for (int mi = 0; mi < 2; mi++)
#pragma unroll
                for (int ni = 0; ni < 8; ni++)
                    mma_tf32(acc[mi][ni], af[mi], bfr[ni * 2], bfr[ni * 2 + 1]);
        }

        if (s + 1 < KT) asm volatile("cp.async.wait_group 1;" ::: "memory");
        __syncthreads();
    }

    // ---- epilogue ----
    float2 b2[8];
    if (bx == 0) {
#pragma unroll
        for (int ni = 0; ni < 8; ni++) {
            int col = wn + ni * 8 + c0 * 2;
            b2[ni].x = bias[col]; b2[ni].y = bias[col + 1];
        }
    }
    float* OUT = (bx == 0) ? H : Qb;
#pragma unroll
    for (int mi = 0; mi < 2; mi++) {
#pragma unroll
        for (int ci = 0; ci < 2; ci++) {
            int row = bm + wm + mi * 16 + r0 + ci * 8;
            if (row >= NN) continue;
#pragma unroll
            for (int ni = 0; ni < 8; ni++) {
                int col = wn + ni * 8 + c0 * 2;
                float2 v;
                v.x = acc[mi][ni][ci * 2 + 0];
                v.y = acc[mi][ni][ci * 2 + 1];
                if (bx == 0) { v.x += b2[ni].x; v.y += b2[ni].y; }
                *(float2*)(OUT + (size_t)row * 256 + col) = v;
            }
        }
    }
}

// ---------------- gather SpMM: H[n] = relu(H[n] + sum_j w_j * Q[src_j]) -----
__global__ __launch_bounds__(256)
void spmm_kernel(const float* __restrict__ Q, float* __restrict__ H) {
    int gw   = (blockIdx.x * blockDim.x + threadIdx.x) >> 5;
    int lane = threadIdx.x & 31;
    if (gw >= NN) return;
    int beg = g_row_start[gw];
    int end = beg + g_cnt[gw];

    const float4* Q4 = (const float4*)Q;
    float4 acc0 = make_float4(0.f, 0.f, 0.f, 0.f);
    float4 acc1 = make_float4(0.f, 0.f, 0.f, 0.f);

    int j = beg;
    for (; j + 2 <= end; j += 2) {
        int   s0 = g_csr_src[j],   s1 = g_csr_src[j + 1];
        float w0 = g_csr_w[j],     w1 = g_csr_w[j + 1];
        float4 a0 = Q4[(size_t)s0 * 64 + lane];
        float4 b0 = Q4[(size_t)s0 * 64 + 32 + lane];
        float4 a1 = Q4[(size_t)s1 * 64 + lane];
        float4 b1 = Q4[(size_t)s1 * 64 + 32 + lane];
        acc0.x += w0 * a0.x + w1 * a1.x; acc0.y += w0 * a0.y + w1 * a1.y;
        acc0.z += w0 * a0.z + w1 * a1.z; acc0.w += w0 * a0.w + w1 * a1.w;
        acc1.x += w0 * b0.x + w1 * b1.x; acc1.y += w0 * b0.y + w1 * b1.y;
        acc1.z += w0 * b0.z + w1 * b1.z; acc1.w += w0 * b0.w + w1 * b1.w;
    }
    if (j < end) {
        int   s0 = g_csr_src[j];
        float w0 = g_csr_w[j];
        float4 a0 = Q4[(size_t)s0 * 64 + lane];
        float4 b0 = Q4[(size_t)s0 * 64 + 32 + lane];
        acc0.x += w0 * a0.x; acc0.y += w0 * a0.y; acc0.z += w0 * a0.z; acc0.w += w0 * a0.w;
        acc1.x += w0 * b0.x; acc1.y += w0 * b0.y; acc1.z += w0 * b0.z; acc1.w += w0 * b0.w;
    }

    float4* H4 = (float4*)H;
    size_t base = (size_t)gw * 64;
    float4 h0 = H4[base + lane];
    float4 h1 = H4[base + 32 + lane];
    h0.x = fmaxf(h0.x + acc0.x, 0.f); h0.y = fmaxf(h0.y + acc0.y, 0.f);
    h0.z = fmaxf(h0.z + acc0.z, 0.f); h0.w = fmaxf(h0.w + acc0.w, 0.f);
    h1.x = fmaxf(h1.x + acc1.x, 0.f); h1.y = fmaxf(h1.y + acc1.y, 0.f);
    h1.z = fmaxf(h1.z + acc1.z, 0.f); h1.w = fmaxf(h1.w + acc1.w, 0.f);
    H4[base + lane] = h0;
    H4[base + 32 + lane] = h1;
}

// ---------------- head (inputs already relu'd) ------------------------------
__global__ __launch_bounds__(256)
void head_kernel(const float* __restrict__ Wl, const float* __restrict__ bl,
                 float* __restrict__ out) {
    __shared__ float sW[768 * NC];
    int tid = threadIdx.x;
    for (int i = tid; i < 768 * NC; i += blockDim.x) sW[i] = Wl[i];
    __syncthreads();

    int lane = tid & 31;
    int node = blockIdx.x * (blockDim.x >> 5) + (tid >> 5);
    if (node >= NN) return;

    const float* h1 = g_h1 + (size_t)node * HID;
    const float* h2 = g_h2 + (size_t)node * HID;
    const float* h3 = g_h3 + (size_t)node * HID;

    float acc[NC];
#pragma unroll
    for (int c = 0; c < NC; c++) acc[c] = 0.f;

    for (int k = lane; k < HID; k += 32) {
        float v1 = h1[k], v2 = h2[k], v3 = h3[k];
#pragma unroll
        for (int c = 0; c < NC; c++)
            acc[c] += v1 * sW[k * NC + c]
                    + v2 * sW[(HID + k) * NC + c]
                    + v3 * sW[(2 * HID + k) * NC + c];
    }
#pragma unroll
    for (int c = 0; c < NC; c++)
        for (int off = 16; off > 0; off >>= 1)
            acc[c] += __shfl_down_sync(0xffffffffu, acc[c], off);

    if (lane == 0) {
        float lg[NC], mx = -1e30f;
#pragma unroll
        for (int c = 0; c < NC; c++) { lg[c] = acc[c] + bl[c]; mx = fmaxf(mx, lg[c]); }
        float s = 0.f;
#pragma unroll
        for (int c = 0; c < NC; c++) s += expf(lg[c] - mx);
        float lse = mx + logf(s);
#pragma unroll
        for (int c = 0; c < NC; c++) out[(size_t)node * NC + c] = lg[c] - lse;
    }
}

// ---------------------------------------------------------------------------
extern "C" void kernel_launch(void* const* d_in, const int* in_sizes, int n_in,
                              void* d_out, int out_size) {
    const float* x  = (const float*)d_in[0];
    const int*   ei = (const int*)d_in[1];
    const float* ew = (const float*)d_in[2];
    const float* W1 = (const float*)d_in[3];
    const float* b1 = (const float*)d_in[4];
    const float* W2 = (const float*)d_in[5];
    const float* b2 = (const float*)d_in[6];
    const float* W3 = (const float*)d_in[7];
    const float* b3 = (const float*)d_in[8];
    const float* Wl = (const float*)d_in[9];
    const float* bl = (const float*)d_in[10];
    float* out = (float*)d_out;

    const int* src = ei;
    const int* dst = ei + NE;

    float *h1, *h2, *h3, *q;
    uint32_t *w1t, *w2t, *w3t;
    cudaGetSymbolAddress((void**)&h1,  g_h1);
    cudaGetSymbolAddress((void**)&h2,  g_h2);
    cudaGetSymbolAddress((void**)&h3,  g_h3);
    cudaGetSymbolAddress((void**)&q,   g_q);
    cudaGetSymbolAddress((void**)&w1t, g_w1t);
    cudaGetSymbolAddress((void**)&w2t, g_w2t);
    cudaGetSymbolAddress((void**)&w3t, g_w3t);

    const int SMEM_B = SMEM_WORDS * 4;
    cudaFuncSetAttribute(gemm_tc, cudaFuncAttributeMaxDynamicSharedMemorySize, SMEM_B);

    const int T = 256;
    dim3 gemm_grid(2, (NN + 127) / 128);
    const int node_warps = (NN + 7) / 8;
    const int wtot = W1TN + 2 * W2TN;

    zero_cnt<<<NBLK, SCAN_T>>>();                                    // 0
    count_kernel<<<(NE + T - 1) / T, T>>>(dst);                      // 1
    cvt_wt<<<(wtot + T - 1) / T, T>>>(W1, W2, W3);                   // 2
    gemm_tc<<<gemm_grid, 512, SMEM_B>>>(x, F0, F0, KP1, w1t, b1, h1, q); // 3 <- profiled
    scanA<<<NBLK, SCAN_T>>>();                                       // 4
    scanB<<<1, 512>>>();                                             // 5
    scanC<<<NBLK, SCAN_T>>>();                                       // 6
    place_kernel<<<(NE + T - 1) / T, T>>>(src, dst, ew);             // 7

    spmm_kernel<<<node_warps, T>>>(q, h1);                           // 8

    gemm_tc<<<gemm_grid, 512, SMEM_B>>>(h1, HID, HID, KP2, w2t, b2, h2, q);
    spmm_kernel<<<node_warps, T>>>(q, h2);

    gemm_tc<<<gemm_grid, 512, SMEM_B>>>(h2, HID, HID, KP2, w3t, b3, h3, q);
    spmm_kernel<<<node_warps, T>>>(q, h3);

    head_kernel<<<(NN + 7) / 8, T>>>(Wl, bl, out);
}

// round 10
// speedup vs baseline: 5.1533x; 1.0829x over previous
#include <cuda_runtime.h>
#include <cuda_bf16.h>
#include <cstdint>

#define NN 89250
#define NE 899756
#define F0 500
#define HID 256
#define NC  7
#define SCAN_T 256
#define NBLK ((NN + SCAN_T - 1) / SCAN_T)   // 349
#define KP1 512                              // layer-1 K padded
#define KP2 256

// ---------------- scratch (device globals) ---------------------------------
__device__ __align__(256) float g_h1[(size_t)NN * HID];
__device__ __align__(256) float g_h2[(size_t)NN * HID];
__device__ __align__(256) float g_h3[(size_t)NN * HID];
__device__ __align__(256) uint32_t g_q[(size_t)NN * 128];   // Q in bf16x2
// transposed tf32-rounded weights: [half(P/Q)][n 0..255][k 0..KP)
__device__ __align__(256) uint32_t g_w1t[2 * 256 * KP1];
__device__ __align__(256) uint32_t g_w2t[2 * 256 * KP2];
__device__ __align__(256) uint32_t g_w3t[2 * 256 * KP2];
__device__ int   g_cnt[NN];
__device__ int   g_row_start[NN];
__device__ int   g_row_fill[NN];
__device__ int   g_bsum[NBLK];
__device__ int   g_csr_src[NE];
__device__ float g_csr_w[NE];

#define W1TN (2 * 256 * KP1)   // 262144
#define W2TN (2 * 256 * KP2)   // 131072

// ---------------- CSR build kernels -----------------------------------------
__global__ void zero_cnt() {
    int i = blockIdx.x * blockDim.x + threadIdx.x;
    if (i < NN) g_cnt[i] = 0;
}
__global__ void count_kernel(const int* __restrict__ dst) {
    int e = blockIdx.x * blockDim.x + threadIdx.x;
    if (e < NE) atomicAdd(&g_cnt[dst[e]], 1);
}
__global__ void scanA() {
    __shared__ int s[SCAN_T];
    int t = threadIdx.x;
    int i = blockIdx.x * SCAN_T + t;
    s[t] = (i < NN) ? g_cnt[i] : 0;
    __syncthreads();
#pragma unroll
    for (int off = SCAN_T / 2; off > 0; off >>= 1) {
        if (t < off) s[t] += s[t + off];
        __syncthreads();
    }
    if (t == 0) g_bsum[blockIdx.x] = s[0];
}
__global__ void scanB() {
    __shared__ int s[512];
    int t = threadIdx.x;
    int v = (t < NBLK) ? g_bsum[t] : 0;
    s[t] = v;
    __syncthreads();
#pragma unroll
    for (int off = 1; off < 512; off <<= 1) {
        int x = (t >= off) ? s[t - off] : 0;
        __syncthreads();
        s[t] += x;
        __syncthreads();
    }
    if (t < NBLK) g_bsum[t] = s[t] - v;   // exclusive
}
__global__ void scanC() {
    __shared__ int s[SCAN_T];
    int t = threadIdx.x;
    int i = blockIdx.x * SCAN_T + t;
    int v = (i < NN) ? g_cnt[i] : 0;
    s[t] = v;
    __syncthreads();
#pragma unroll
    for (int off = 1; off < SCAN_T; off <<= 1) {
        int x = (t >= off) ? s[t - off] : 0;
        __syncthreads();
        s[t] += x;
        __syncthreads();
    }
    if (i < NN) {
        int excl = s[t] - v + g_bsum[blockIdx.x];
        g_row_start[i] = excl;
        g_row_fill[i]  = excl;
    }
}
__global__ void place_kernel(const int* __restrict__ src, const int* __restrict__ dst,
                             const float* __restrict__ ew) {
    int e = blockIdx.x * blockDim.x + threadIdx.x;
    if (e >= NE) return;
    int d = dst[e];
    int slot = atomicAdd(&g_row_fill[d], 1);
    g_csr_src[slot] = src[e];
    g_csr_w[slot]   = ew[e] / fmaxf((float)g_cnt[d], 1.0f);
}

// ---------------- tf32 / bf16 helpers ----------------------------------------
__device__ __forceinline__ uint32_t f2tf(float f) {
    uint32_t r;
    asm("cvt.rna.tf32.f32 %0, %1;" : "=r"(r) : "f"(f));
    return r;
}
__device__ __forceinline__ void mma_tf32(float c[4], const uint32_t a[4],
                                         uint32_t b0, uint32_t b1) {
    asm volatile(
        "mma.sync.aligned.m16n8k8.row.col.f32.tf32.tf32.f32 "
        "{%0,%1,%2,%3}, {%4,%5,%6,%7}, {%8,%9}, {%0,%1,%2,%3};"
        : "+f"(c[0]), "+f"(c[1]), "+f"(c[2]), "+f"(c[3])
        : "r"(a[0]), "r"(a[1]), "r"(a[2]), "r"(a[3]), "r"(b0), "r"(b1));
}
__device__ __forceinline__ void ldsm4(uint32_t r[4], uint32_t addr) {
    asm volatile("ldmatrix.sync.aligned.m8n8.x4.shared.b16 {%0,%1,%2,%3}, [%4];"
                 : "=r"(r[0]), "=r"(r[1]), "=r"(r[2]), "=r"(r[3]) : "r"(addr));
}
__device__ __forceinline__ void cp16(uint32_t dst, const void* src) {
    asm volatile("cp.async.cg.shared.global [%0], [%1], 16;" :: "r"(dst), "l"(src));
}
__device__ __forceinline__ uint32_t smem_u32(const void* p) {
    uint32_t a;
    asm("{ .reg .u64 t; cvta.to.shared.u64 t, %1; cvt.u32.u64 %0, t; }" : "=r"(a) : "l"(p));
    return a;
}
__device__ __forceinline__ uint32_t pack_bf16x2(float lo, float hi) {
    __nv_bfloat162 t = __float22bfloat162_rn(make_float2(lo, hi));
    return *reinterpret_cast<uint32_t*>(&t);
}
__device__ __forceinline__ float bf_lo(uint32_t u) { return __uint_as_float(u << 16); }
__device__ __forceinline__ float bf_hi(uint32_t u) { return __uint_as_float(u & 0xffff0000u); }

// transpose + tf32-round weights: Wt[half][n][k] = rna(W[half*K + k][n]); K-pad zeros
__global__ void cvt_wt(const float* __restrict__ W1, const float* __restrict__ W2,
                       const float* __restrict__ W3) {
    int i = blockIdx.x * blockDim.x + threadIdx.x;
    if (i < W1TN) {
        int half = i >> 17;
        int rem  = i & 131071;
        int n = rem >> 9, k = rem & 511;
        g_w1t[i] = (k < F0) ? f2tf(W1[((size_t)half * F0 + k) * 256 + n]) : 0u;
    } else if (i < W1TN + W2TN) {
        int j = i - W1TN;
        int half = j >> 16;
        int rem  = j & 65535;
        int n = rem >> 8, k = rem & 255;
        g_w2t[j] = f2tf(W2[((size_t)half * HID + k) * 256 + n]);
    } else if (i < W1TN + 2 * W2TN) {
        int j = i - W1TN - W2TN;
        int half = j >> 16;
        int rem  = j & 65535;
        int n = rem >> 8, k = rem & 255;
        g_w3t[j] = f2tf(W3[((size_t)half * HID + k) * 256 + n]);
    }
}

// ---------------- tf32 SAGE GEMM: 512 thr, block 128x256, warp 32x64 --------
// grid = (2, ceil(NN/128)). bx=0: H = A@Wtop + bias (fp32); bx=1: Q = A@Wbot (bf16x2)
#define AS_STRIDE 36
#define BS_STRIDE 36
#define AS_STAGE  (128 * AS_STRIDE)     // 4608 words
#define BS_STAGE  (256 * BS_STRIDE)     // 9216 words
#define SMEM_WORDS (2 * AS_STAGE + 3 * BS_STAGE)   // 36864 words = 147456 B

__global__ __launch_bounds__(512, 1)
void gemm_tc(const float* __restrict__ A, int K, int lda, int KP,
             const uint32_t* __restrict__ Wt,   // [2][256][KP] transposed tf32
             const float* __restrict__ bias,
             float* __restrict__ H, uint32_t* __restrict__ Qb)
{
    extern __shared__ uint32_t sm[];
    uint32_t* As = sm;                       // [2][128][36]
    const uint32_t sb = smem_u32(sm);
    const uint32_t sbB = sb + 2 * AS_STAGE * 4;

    const int bx = blockIdx.x;               // 0 = P path, 1 = Q path
    const int bm = blockIdx.y * 128;
    const uint32_t* Wsel = Wt + (size_t)bx * 256 * KP;

    const int tid  = threadIdx.x;
    const int wid  = tid >> 5;
    const int lane = tid & 31;
    const int wm = (wid >> 2) * 32;          // 0,32,64,96
    const int wn = (wid & 3) * 64;           // 0,64,128,192
    const int r0 = lane >> 2, c0 = lane & 3;

    // LDSM lane address components
    const int al_row = lane & 15;
    const int al_w   = (lane >> 4) * 4;
    const int bl_n   = (lane & 7) + ((lane >> 4) & 1) * 8;
    const int bl_w   = ((lane >> 3) & 1) * 4;

    const int a_row = tid >> 3;              // 0..63 (+64 on 2nd)
    const int a_kq  = (tid & 7) * 4;
    const int KT = KP / 32;

    float acc[2][8][4];
#pragma unroll
    for (int mi = 0; mi < 2; mi++)
#pragma unroll
        for (int ni = 0; ni < 8; ni++)
#pragma unroll
            for (int c = 0; c < 4; c++) acc[mi][ni][c] = 0.f;

    auto loadB = [&](int s) {
        const int buf = s % 3;
        const int k0  = s * 32;
#pragma unroll
        for (int i = 0; i < 4; i++) {
            int c = tid + i * 512;
            int n = c >> 3, kc = (c & 7) * 4;
            uint32_t dst = sbB + (buf * BS_STAGE + n * BS_STRIDE + kc) * 4;
            cp16(dst, Wsel + (size_t)n * KP + k0 + kc);    // K padded: no bound
        }
    };
    float4 rA[2];
    auto ldgA = [&](int s) {
        int gk = s * 32 + a_kq;
#pragma unroll
        for (int i = 0; i < 2; i++) {
            int gr = bm + a_row + i * 64;
            rA[i] = make_float4(0.f, 0.f, 0.f, 0.f);
            if (gr < NN && gk < K) rA[i] = *(const float4*)(A + (size_t)gr * lda + gk);
        }
    };
    auto stsA = [&](int s) {
        uint32_t* base = As + (s & 1) * AS_STAGE;
#pragma unroll
        for (int i = 0; i < 2; i++) {
            uint4 v;
            v.x = f2tf(rA[i].x); v.y = f2tf(rA[i].y);
            v.z = f2tf(rA[i].z); v.w = f2tf(rA[i].w);
            *(uint4*)(base + (a_row + i * 64) * AS_STRIDE + a_kq) = v;
        }
    };

    // ---- prologue ----
    loadB(0); asm volatile("cp.async.commit_group;" ::: "memory");
    loadB(1); asm volatile("cp.async.commit_group;" ::: "memory");
    ldgA(0); stsA(0);
    ldgA(1);
    asm volatile("cp.async.wait_group 1;" ::: "memory");   // B0 ready
    __syncthreads();

    for (int s = 0; s < KT; s++) {
        if (s + 1 < KT) stsA(s + 1);
        if (s + 2 < KT) { ldgA(s + 2); loadB(s + 2); }
        asm volatile("cp.async.commit_group;" ::: "memory");

        const uint32_t aB = sb  + ((s & 1) * AS_STAGE) * 4;
        const uint32_t bB = sbB + ((s % 3) * BS_STAGE) * 4;
#pragma unroll
        for (int ks = 0; ks < 4; ks++) {
            const int k8 = ks * 8;
            uint32_t af[2][4], bfr[16];
#pragma unroll
            for (int mi = 0; mi < 2; mi++)
                ldsm4(af[mi], aB + ((wm + mi * 16 + al_row) * AS_STRIDE + k8 + al_w) * 4);
#pragma unroll
            for (int nip = 0; nip < 4; nip++)
                ldsm4(&bfr[nip * 4],
                      bB + ((wn + nip * 16 + bl_n) * BS_STRIDE + k8 + bl_w) * 4);
#pragma unroll
            for (int mi = 0; mi < 2; mi++)
#pragma unroll
                for (int ni = 0; ni < 8; ni++)
                    mma_tf32(acc[mi][ni], af[mi], bfr[ni * 2], bfr[ni * 2 + 1]);
        }

        if (s + 1 < KT) asm volatile("cp.async.wait_group 1;" ::: "memory");
        __syncthreads();
    }

    // ---- epilogue ----
    if (bx == 0) {
        float2 b2[8];
#pragma unroll
        for (int ni = 0; ni < 8; ni++) {
            int col = wn + ni * 8 + c0 * 2;
            b2[ni].x = bias[col]; b2[ni].y = bias[col + 1];
        }
#pragma unroll
        for (int mi = 0; mi < 2; mi++) {
#pragma unroll
            for (int ci = 0; ci < 2; ci++) {
                int row = bm + wm + mi * 16 + r0 + ci * 8;
                if (row >= NN) continue;
#pragma unroll
                for (int ni = 0; ni < 8; ni++) {
                    int col = wn + ni * 8 + c0 * 2;
                    float2 v;
                    v.x = acc[mi][ni][ci * 2 + 0] + b2[ni].x;
                    v.y = acc[mi][ni][ci * 2 + 1] + b2[ni].y;
                    *(float2*)(H + (size_t)row * 256 + col) = v;
                }
            }
        }
    } else {
#pragma unroll
        for (int mi = 0; mi < 2; mi++) {
#pragma unroll
            for (int ci = 0; ci < 2; ci++) {
                int row = bm + wm + mi * 16 + r0 + ci * 8;
                if (row >= NN) continue;
#pragma unroll
                for (int ni = 0; ni < 8; ni++) {
                    int col = wn + ni * 8 + c0 * 2;     // even
                    Qb[(size_t)row * 128 + (col >> 1)] =
                        pack_bf16x2(acc[mi][ni][ci * 2 + 0], acc[mi][ni][ci * 2 + 1]);
                }
            }
        }
    }
}

// ---------------- gather SpMM: H[n] = relu(H[n] + sum_j w_j * Q[src_j]) -----
// Q in bf16x2: one uint4 per lane per edge (8 values).
__global__ __launch_bounds__(256)
void spmm_kernel(const uint32_t* __restrict__ Q, float* __restrict__ H) {
    int gw   = (blockIdx.x * blockDim.x + threadIdx.x) >> 5;
    int lane = threadIdx.x & 31;
    if (gw >= NN) return;
    int beg = g_row_start[gw];
    int end = beg + g_cnt[gw];

    const uint4* Q4 = (const uint4*)Q;       // row = 32 uint4
    float acc[8];
#pragma unroll
    for (int i = 0; i < 8; i++) acc[i] = 0.f;

    int j = beg;
    for (; j + 2 <= end; j += 2) {
        int   s0 = g_csr_src[j],   s1 = g_csr_src[j + 1];
        float w0 = g_csr_w[j],     w1 = g_csr_w[j + 1];
        uint4 a = Q4[(size_t)s0 * 32 + lane];
        uint4 b = Q4[(size_t)s1 * 32 + lane];
        acc[0] += w0 * bf_lo(a.x) + w1 * bf_lo(b.x);
        acc[1] += w0 * bf_hi(a.x) + w1 * bf_hi(b.x);
        acc[2] += w0 * bf_lo(a.y) + w1 * bf_lo(b.y);
        acc[3] += w0 * bf_hi(a.y) + w1 * bf_hi(b.y);
        acc[4] += w0 * bf_lo(a.z) + w1 * bf_lo(b.z);
        acc[5] += w0 * bf_hi(a.z) + w1 * bf_hi(b.z);
        acc[6] += w0 * bf_lo(a.w) + w1 * bf_lo(b.w);
        acc[7] += w0 * bf_hi(a.w) + w1 * bf_hi(b.w);
    }
    if (j < end) {
        int   s0 = g_csr_src[j];
        float w0 = g_csr_w[j];
        uint4 a = Q4[(size_t)s0 * 32 + lane];
        acc[0] += w0 * bf_lo(a.x); acc[1] += w0 * bf_hi(a.x);
        acc[2] += w0 * bf_lo(a.y); acc[3] += w0 * bf_hi(a.y);
        acc[4] += w0 * bf_lo(a.z); acc[5] += w0 * bf_hi(a.z);
        acc[6] += w0 * bf_lo(a.w); acc[7] += w0 * bf_hi(a.w);
    }

    // lane owns 8 consecutive floats [lane*8 .. lane*8+7]
    float4* H4 = (float4*)H;
    size_t base = (size_t)gw * 64 + lane * 2;
    float4 h0 = H4[base];
    float4 h1 = H4[base + 1];
    h0.x = fmaxf(h0.x + acc[0], 0.f); h0.y = fmaxf(h0.y + acc[1], 0.f);
    h0.z = fmaxf(h0.z + acc[2], 0.f); h0.w = fmaxf(h0.w + acc[3], 0.f);
    h1.x = fmaxf(h1.x + acc[4], 0.f); h1.y = fmaxf(h1.y + acc[5], 0.f);
    h1.z = fmaxf(h1.z + acc[6], 0.f); h1.w = fmaxf(h1.w + acc[7], 0.f);
    H4[base]     = h0;
    H4[base + 1] = h1;
}

// ---------------- head (inputs already relu'd) ------------------------------
__global__ __launch_bounds__(256)
void head_kernel(const float* __restrict__ Wl, const float* __restrict__ bl,
                 float* __restrict__ out) {
    __shared__ float sW[768 * NC];
    int tid = threadIdx.x;
    for (int i = tid; i < 768 * NC; i += blockDim.x) sW[i] = Wl[i];
    __syncthreads();

    int lane = tid & 31;
    int node = blockIdx.x * (blockDim.x >> 5) + (tid >> 5);
    if (node >= NN) return;

    const float* h1 = g_h1 + (size_t)node * HID;
    const float* h2 = g_h2 + (size_t)node * HID;
    const float* h3 = g_h3 + (size_t)node * HID;

    float acc[NC];
#pragma unroll
    for (int c = 0; c < NC; c++) acc[c] = 0.f;

    for (int k = lane; k < HID; k += 32) {
        float v1 = h1[k], v2 = h2[k], v3 = h3[k];
#pragma unroll
        for (int c = 0; c < NC; c++)
            acc[c] += v1 * sW[k * NC + c]
                    + v2 * sW[(HID + k) * NC + c]
                    + v3 * sW[(2 * HID + k) * NC + c];
    }
#pragma unroll
    for (int c = 0; c < NC; c++)
        for (int off = 16; off > 0; off >>= 1)
            acc[c] += __shfl_down_sync(0xffffffffu, acc[c], off);

    if (lane == 0) {
        float lg[NC], mx = -1e30f;
#pragma unroll
        for (int c = 0; c < NC; c++) { lg[c] = acc[c] + bl[c]; mx = fmaxf(mx, lg[c]); }
        float s = 0.f;
#pragma unroll
        for (int c = 0; c < NC; c++) s += expf(lg[c] - mx);
        float lse = mx + logf(s);
#pragma unroll
        for (int c = 0; c < NC; c++) out[(size_t)node * NC + c] = lg[c] - lse;
    }
}

// ---------------------------------------------------------------------------
extern "C" void kernel_launch(void* const* d_in, const int* in_sizes, int n_in,
                              void* d_out, int out_size) {
    const float* x  = (const float*)d_in[0];
    const int*   ei = (const int*)d_in[1];
    const float* ew = (const float*)d_in[2];
    const float* W1 = (const float*)d_in[3];
    const float* b1 = (const float*)d_in[4];
    const float* W2 = (const float*)d_in[5];
    const float* b2 = (const float*)d_in[6];
    const float* W3 = (const float*)d_in[7];
    const float* b3 = (const float*)d_in[8];
    const float* Wl = (const float*)d_in[9];
    const float* bl = (const float*)d_in[10];
    float* out = (float*)d_out;

    const int* src = ei;
    const int* dst = ei + NE;

    float *h1, *h2, *h3;
    uint32_t *q, *w1t, *w2t, *w3t;
    cudaGetSymbolAddress((void**)&h1,  g_h1);
    cudaGetSymbolAddress((void**)&h2,  g_h2);
    cudaGetSymbolAddress((void**)&h3,  g_h3);
    cudaGetSymbolAddress((void**)&q,   g_q);
    cudaGetSymbolAddress((void**)&w1t, g_w1t);
    cudaGetSymbolAddress((void**)&w2t, g_w2t);
    cudaGetSymbolAddress((void**)&w3t, g_w3t);

    const int SMEM_B = SMEM_WORDS * 4;
    cudaFuncSetAttribute(gemm_tc, cudaFuncAttributeMaxDynamicSharedMemorySize, SMEM_B);

    const int T = 256;
    dim3 gemm_grid(2, (NN + 127) / 128);
    const int node_warps = (NN + 7) / 8;
    const int wtot = W1TN + 2 * W2TN;

    zero_cnt<<<NBLK, SCAN_T>>>();                                    // 0
    count_kernel<<<(NE + T - 1) / T, T>>>(dst);                      // 1
    cvt_wt<<<(wtot + T - 1) / T, T>>>(W1, W2, W3);                   // 2
    gemm_tc<<<gemm_grid, 512, SMEM_B>>>(x, F0, F0, KP1, w1t, b1, h1, q); // 3 <- profiled
    scanA<<<NBLK, SCAN_T>>>();                                       // 4
    scanB<<<1, 512>>>();                                             // 5
    scanC<<<NBLK, SCAN_T>>>();                                       // 6
    place_kernel<<<(NE + T - 1) / T, T>>>(src, dst, ew);             // 7

    spmm_kernel<<<node_warps, T>>>(q, h1);                           // 8

    gemm_tc<<<gemm_grid, 512, SMEM_B>>>(h1, HID, HID, KP2, w2t, b2, h2, q);
    spmm_kernel<<<node_warps, T>>>(q, h2);

    gemm_tc<<<gemm_grid, 512, SMEM_B>>>(h2, HID, HID, KP2, w3t, b3, h3, q);
    spmm_kernel<<<node_warps, T>>>(q, h3);

    head_kernel<<<(NN + 7) / 8, T>>>(Wl, bl, out);
}

// round 11
// speedup vs baseline: 6.5352x; 1.2682x over previous
#include <cuda_runtime.h>
#include <cuda_fp16.h>
#include <cuda_bf16.h>
#include <cstdint>

#define NN 89250
#define NE 899756
#define F0 500
#define HID 256
#define NC  7
#define SCAN_T 256
#define NBLK ((NN + SCAN_T - 1) / SCAN_T)   // 349
#define KP1 512                              // layer-1 K padded
#define KP2 256

// ---------------- scratch (device globals) ---------------------------------
__device__ __align__(256) float g_h1[(size_t)NN * HID];
__device__ __align__(256) float g_h2[(size_t)NN * HID];
__device__ __align__(256) float g_h3[(size_t)NN * HID];
__device__ __align__(256) uint32_t g_q[(size_t)NN * 128];   // Q in bf16x2
// transposed fp16 weights: [half(P/Q)][n 0..255][k 0..KP)
__device__ __align__(256) __half g_w1t[2 * 256 * KP1];
__device__ __align__(256) __half g_w2t[2 * 256 * KP2];
__device__ __align__(256) __half g_w3t[2 * 256 * KP2];
__device__ int   g_cnt[NN];
__device__ int   g_row_start[NN];
__device__ int   g_row_fill[NN];
__device__ int   g_bsum[NBLK];
__device__ int   g_csr_src[NE];
__device__ float g_csr_w[NE];

#define W1TN (2 * 256 * KP1)   // 262144
#define W2TN (2 * 256 * KP2)   // 131072

// ---------------- CSR build kernels -----------------------------------------
__global__ void zero_cnt() {
    int i = blockIdx.x * blockDim.x + threadIdx.x;
    if (i < NN) g_cnt[i] = 0;
}
__global__ void count_kernel(const int* __restrict__ dst) {
    int e = blockIdx.x * blockDim.x + threadIdx.x;
    if (e < NE) atomicAdd(&g_cnt[dst[e]], 1);
}
__global__ void scanA() {
    __shared__ int s[SCAN_T];
    int t = threadIdx.x;
    int i = blockIdx.x * SCAN_T + t;
    s[t] = (i < NN) ? g_cnt[i] : 0;
    __syncthreads();
#pragma unroll
    for (int off = SCAN_T / 2; off > 0; off >>= 1) {
        if (t < off) s[t] += s[t + off];
        __syncthreads();
    }
    if (t == 0) g_bsum[blockIdx.x] = s[0];
}
__global__ void scanB() {
    __shared__ int s[512];
    int t = threadIdx.x;
    int v = (t < NBLK) ? g_bsum[t] : 0;
    s[t] = v;
    __syncthreads();
#pragma unroll
    for (int off = 1; off < 512; off <<= 1) {
        int x = (t >= off) ? s[t - off] : 0;
        __syncthreads();
        s[t] += x;
        __syncthreads();
    }
    if (t < NBLK) g_bsum[t] = s[t] - v;   // exclusive
}
__global__ void scanC() {
    __shared__ int s[SCAN_T];
    int t = threadIdx.x;
    int i = blockIdx.x * SCAN_T + t;
    int v = (i < NN) ? g_cnt[i] : 0;
    s[t] = v;
    __syncthreads();
#pragma unroll
    for (int off = 1; off < SCAN_T; off <<= 1) {
        int x = (t >= off) ? s[t - off] : 0;
        __syncthreads();
        s[t] += x;
        __syncthreads();
    }
    if (i < NN) {
        int excl = s[t] - v + g_bsum[blockIdx.x];
        g_row_start[i] = excl;
        g_row_fill[i]  = excl;
    }
}
__global__ void place_kernel(const int* __restrict__ src, const int* __restrict__ dst,
                             const float* __restrict__ ew) {
    int e = blockIdx.x * blockDim.x + threadIdx.x;
    if (e >= NE) return;
    int d = dst[e];
    int slot = atomicAdd(&g_row_fill[d], 1);
    g_csr_src[slot] = src[e];
    g_csr_w[slot]   = ew[e] / fmaxf((float)g_cnt[d], 1.0f);
}

// ---------------- fp16 / bf16 helpers ----------------------------------------
__device__ __forceinline__ void mma_fp16(float c[4], const uint32_t a[4],
                                         uint32_t b0, uint32_t b1) {
    asm volatile(
        "mma.sync.aligned.m16n8k16.row.col.f32.f16.f16.f32 "
        "{%0,%1,%2,%3}, {%4,%5,%6,%7}, {%8,%9}, {%0,%1,%2,%3};"
        : "+f"(c[0]), "+f"(c[1]), "+f"(c[2]), "+f"(c[3])
        : "r"(a[0]), "r"(a[1]), "r"(a[2]), "r"(a[3]), "r"(b0), "r"(b1));
}
__device__ __forceinline__ void ldsm4(uint32_t r[4], uint32_t addr) {
    asm volatile("ldmatrix.sync.aligned.m8n8.x4.shared.b16 {%0,%1,%2,%3}, [%4];"
                 : "=r"(r[0]), "=r"(r[1]), "=r"(r[2]), "=r"(r[3]) : "r"(addr));
}
__device__ __forceinline__ void cp16(uint32_t dst, const void* src) {
    asm volatile("cp.async.cg.shared.global [%0], [%1], 16;" :: "r"(dst), "l"(src));
}
__device__ __forceinline__ uint32_t smem_u32(const void* p) {
    uint32_t a;
    asm("{ .reg .u64 t; cvta.to.shared.u64 t, %1; cvt.u32.u64 %0, t; }" : "=r"(a) : "l"(p));
    return a;
}
__device__ __forceinline__ uint32_t pack_h2(float lo, float hi) {
    __half2 t = __floats2half2_rn(lo, hi);
    return *reinterpret_cast<uint32_t*>(&t);
}
__device__ __forceinline__ uint32_t pack_bf16x2(float lo, float hi) {
    __nv_bfloat162 t = __float22bfloat162_rn(make_float2(lo, hi));
    return *reinterpret_cast<uint32_t*>(&t);
}
__device__ __forceinline__ float bf_lo(uint32_t u) { return __uint_as_float(u << 16); }
__device__ __forceinline__ float bf_hi(uint32_t u) { return __uint_as_float(u & 0xffff0000u); }

// transpose + fp16-round weights: Wt[half][n][k] = rn(W[half*K + k][n]); K-pad zeros
__global__ void cvt_wt(const float* __restrict__ W1, const float* __restrict__ W2,
                       const float* __restrict__ W3) {
    int i = blockIdx.x * blockDim.x + threadIdx.x;
    if (i < W1TN) {
        int half_ = i >> 17;
        int rem  = i & 131071;
        int n = rem >> 9, k = rem & 511;
        g_w1t[i] = (k < F0) ? __float2half_rn(W1[((size_t)half_ * F0 + k) * 256 + n])
                            : __float2half_rn(0.f);
    } else if (i < W1TN + W2TN) {
        int j = i - W1TN;
        int half_ = j >> 16;
        int rem  = j & 65535;
        int n = rem >> 8, k = rem & 255;
        g_w2t[j] = __float2half_rn(W2[((size_t)half_ * HID + k) * 256 + n]);
    } else if (i < W1TN + 2 * W2TN) {
        int j = i - W1TN - W2TN;
        int half_ = j >> 16;
        int rem  = j & 65535;
        int n = rem >> 8, k = rem & 255;
        g_w3t[j] = __float2half_rn(W3[((size_t)half_ * HID + k) * 256 + n]);
    }
}

// ---------------- fp16 SAGE GEMM: 512 thr, block 128x256, warp 32x64 --------
// grid = (2, ceil(NN/128)). bx=0: H = A@Wtop + bias (fp32); bx=1: Q = A@Wbot (bf16x2)
// A: [2][128 m][80B rows] fp16 k-major. B: [3][256 n][80B rows] fp16 n-major.
// mma.m16n8k16; all fragments via ldmatrix.x4.
#define AS_ROWB   80                         // bytes per A/B row (64 data + 16 pad)
#define AS_STAGEB (128 * AS_ROWB)            // 10240 B
#define BS_STAGEB (256 * AS_ROWB)            // 20480 B
#define SMEM_BYTES (2 * AS_STAGEB + 3 * BS_STAGEB)   // 81920 B

__global__ __launch_bounds__(512, 1)
void gemm_tc(const float* __restrict__ A, int K, int lda, int KP,
             const __half* __restrict__ Wt,   // [2][256][KP] transposed fp16
             const float* __restrict__ bias,
             float* __restrict__ H, uint32_t* __restrict__ Qb)
{
    extern __shared__ char sm[];
    const uint32_t sb  = smem_u32(sm);              // A base
    const uint32_t sbB = sb + 2 * AS_STAGEB;        // B base

    const int bx = blockIdx.x;               // 0 = P path, 1 = Q path
    const int bm = blockIdx.y * 128;
    const __half* Wsel = Wt + (size_t)bx * 256 * KP;

    const int tid  = threadIdx.x;
    const int wid  = tid >> 5;
    const int lane = tid & 31;
    const int wm = (wid >> 2) * 32;          // 0,32,64,96
    const int wn = (wid & 3) * 64;           // 0,64,128,192
    const int r0 = lane >> 2, c0 = lane & 3;

    // ldmatrix lane address components
    const int a_roff = (lane & 7) + ((lane >> 3) & 1) * 8;   // A: m pairs rows/row+8
    const int a_kb   = ((lane >> 4) & 1) * 16;               // A: k bytes 0/16
    const int b_roff = (lane & 7) + ((lane >> 4) & 1) * 8;   // B: n rows
    const int b_kb   = ((lane >> 3) & 1) * 16;               // B: k bytes 0/16

    // A staging: 128 rows x 4 chunks(16B) = 512 chunks, 1 per thread
    const int a_row = tid >> 2;              // 0..127
    const int a_k8  = (tid & 3) * 8;         // fp16 offset 0,8,16,24
    const int KT = KP / 32;

    float acc[2][8][4];
#pragma unroll
    for (int mi = 0; mi < 2; mi++)
#pragma unroll
        for (int ni = 0; ni < 8; ni++)
#pragma unroll
            for (int c = 0; c < 4; c++) acc[mi][ni][c] = 0.f;

    // ---- B loader (cp.async, 3-stage ring): 256 n-rows x 32 k-halves ----
    auto loadB = [&](int s) {
        const int buf = s % 3;
        const int k0  = s * 32;
#pragma unroll
        for (int i = 0; i < 2; i++) {
            int c = tid + i * 512;
            int n = c >> 2, kc = (c & 3) * 8;            // 8 halves = 16B
            uint32_t dst = sbB + buf * BS_STAGEB + n * AS_ROWB + kc * 2;
            cp16(dst, Wsel + (size_t)n * KP + k0 + kc);  // K padded: no bound
        }
    };
    // ---- A: gmem -> regs (8 floats per thread) ----
    float4 rA0, rA1;
    auto ldgA = [&](int s) {
        int gk = s * 32 + a_k8;
        int gr = bm + a_row;
        rA0 = make_float4(0.f, 0.f, 0.f, 0.f);
        rA1 = make_float4(0.f, 0.f, 0.f, 0.f);
        if (gr < NN) {
            if (gk < K)     rA0 = *(const float4*)(A + (size_t)gr * lda + gk);
            if (gk + 4 < K) rA1 = *(const float4*)(A + (size_t)gr * lda + gk + 4);
        }
    };
    // ---- A: regs -> smem (fp16 rn) ----
    auto stsA = [&](int s) {
        uint32_t dst = sb + (s & 1) * AS_STAGEB + a_row * AS_ROWB + a_k8 * 2;
        uint4 v;
        v.x = pack_h2(rA0.x, rA0.y); v.y = pack_h2(rA0.z, rA0.w);
        v.z = pack_h2(rA1.x, rA1.y); v.w = pack_h2(rA1.z, rA1.w);
        asm volatile("st.shared.v4.b32 [%0], {%1,%2,%3,%4};"
                     :: "r"(dst), "r"(v.x), "r"(v.y), "r"(v.z), "r"(v.w));
    };

    // ---- prologue ----
    loadB(0); asm volatile("cp.async.commit_group;" ::: "memory");
    loadB(1); asm volatile("cp.async.commit_group;" ::: "memory");
    ldgA(0); stsA(0);
    ldgA(1);
    asm volatile("cp.async.wait_group 1;" ::: "memory");   // B0 ready
    __syncthreads();

    for (int s = 0; s < KT; s++) {
        if (s + 1 < KT) stsA(s + 1);
        if (s + 2 < KT) { ldgA(s + 2); loadB(s + 2); }
        asm volatile("cp.async.commit_group;" ::: "memory");

        const uint32_t aB = sb  + (s & 1) * AS_STAGEB;
        const uint32_t bB = sbB + (s % 3) * BS_STAGEB;
#pragma unroll
        for (int ks = 0; ks < 2; ks++) {                 // two k16 steps per stage
            const int kb = ks * 32;                      // byte offset of k16 block
            uint32_t af[2][4], bfr[16];
#pragma unroll
            for (int mi = 0; mi < 2; mi++)
                ldsm4(af[mi], aB + (wm + mi * 16 + a_roff) * AS_ROWB + kb + a_kb);
#pragma unroll
            for (int nip = 0; nip < 4; nip++)
                ldsm4(&bfr[nip * 4],
                      bB + (wn + nip * 16 + b_roff) * AS_ROWB + kb + b_kb);
            // bfr layout per nip: r0=[n0-7,k0-7] r1=[n0-7,k8-15] r2=[n8-15,k0-7] r3=[n8-15,k8-15]
#pragma unroll
            for (int mi = 0; mi < 2; mi++)
#pragma unroll
                for (int nip = 0; nip < 4; nip++) {
                    mma_fp16(acc[mi][nip * 2 + 0], af[mi], bfr[nip * 4 + 0], bfr[nip * 4 + 1]);
                    mma_fp16(acc[mi][nip * 2 + 1], af[mi], bfr[nip * 4 + 2], bfr[nip * 4 + 3]);
                }
        }

        if (s + 1 < KT) asm volatile("cp.async.wait_group 1;" ::: "memory");
        __syncthreads();
    }

    // ---- epilogue ----
    if (bx == 0) {
        float2 b2[8];
#pragma unroll
        for (int ni = 0; ni < 8; ni++) {
            int col = wn + ni * 8 + c0 * 2;
            b2[ni].x = bias[col]; b2[ni].y = bias[col + 1];
        }
#pragma unroll
        for (int mi = 0; mi < 2; mi++) {
#pragma unroll
            for (int ci = 0; ci < 2; ci++) {
                int row = bm + wm + mi * 16 + r0 + ci * 8;
                if (row >= NN) continue;
#pragma unroll
                for (int ni = 0; ni < 8; ni++) {
                    int col = wn + ni * 8 + c0 * 2;
                    float2 v;
                    v.x = acc[mi][ni][ci * 2 + 0] + b2[ni].x;
                    v.y = acc[mi][ni][ci * 2 + 1] + b2[ni].y;
                    *(float2*)(H + (size_t)row * 256 + col) = v;
                }
            }
        }
    } else {
#pragma unroll
        for (int mi = 0; mi < 2; mi++) {
#pragma unroll
            for (int ci = 0; ci < 2; ci++) {
                int row = bm + wm + mi * 16 + r0 + ci * 8;
                if (row >= NN) continue;
#pragma unroll
                for (int ni = 0; ni < 8; ni++) {
                    int col = wn + ni * 8 + c0 * 2;     // even
                    Qb[(size_t)row * 128 + (col >> 1)] =
                        pack_bf16x2(acc[mi][ni][ci * 2 + 0], acc[mi][ni][ci * 2 + 1]);
                }
            }
        }
    }
}

// ---------------- gather SpMM: H[n] = relu(H[n] + sum_j w_j * Q[src_j]) -----
// Q in bf16x2: one uint4 per lane per edge (8 values).
__global__ __launch_bounds__(256)
void spmm_kernel(const uint32_t* __restrict__ Q, float* __restrict__ H) {
    int gw   = (blockIdx.x * blockDim.x + threadIdx.x) >> 5;
    int lane = threadIdx.x & 31;
    if (gw >= NN) return;
    int beg = g_row_start[gw];
    int end = beg + g_cnt[gw];

    const uint4* Q4 = (const uint4*)Q;       // row = 32 uint4
    float acc[8];
#pragma unroll
    for (int i = 0; i < 8; i++) acc[i] = 0.f;

    int j = beg;
    for (; j + 2 <= end; j += 2) {
        int   s0 = g_csr_src[j],   s1 = g_csr_src[j + 1];
        float w0 = g_csr_w[j],     w1 = g_csr_w[j + 1];
        uint4 a = Q4[(size_t)s0 * 32 + lane];
        uint4 b = Q4[(size_t)s1 * 32 + lane];
        acc[0] += w0 * bf_lo(a.x) + w1 * bf_lo(b.x);
        acc[1] += w0 * bf_hi(a.x) + w1 * bf_hi(b.x);
        acc[2] += w0 * bf_lo(a.y) + w1 * bf_lo(b.y);
        acc[3] += w0 * bf_hi(a.y) + w1 * bf_hi(b.y);
        acc[4] += w0 * bf_lo(a.z) + w1 * bf_lo(b.z);
        acc[5] += w0 * bf_hi(a.z) + w1 * bf_hi(b.z);
        acc[6] += w0 * bf_lo(a.w) + w1 * bf_lo(b.w);
        acc[7] += w0 * bf_hi(a.w) + w1 * bf_hi(b.w);
    }
    if (j < end) {
        int   s0 = g_csr_src[j];
        float w0 = g_csr_w[j];
        uint4 a = Q4[(size_t)s0 * 32 + lane];
        acc[0] += w0 * bf_lo(a.x); acc[1] += w0 * bf_hi(a.x);
        acc[2] += w0 * bf_lo(a.y); acc[3] += w0 * bf_hi(a.y);
        acc[4] += w0 * bf_lo(a.z); acc[5] += w0 * bf_hi(a.z);
        acc[6] += w0 * bf_lo(a.w); acc[7] += w0 * bf_hi(a.w);
    }

    float4* H4 = (float4*)H;
    size_t base = (size_t)gw * 64 + lane * 2;
    float4 h0 = H4[base];
    float4 h1 = H4[base + 1];
    h0.x = fmaxf(h0.x + acc[0], 0.f); h0.y = fmaxf(h0.y + acc[1], 0.f);
    h0.z = fmaxf(h0.z + acc[2], 0.f); h0.w = fmaxf(h0.w + acc[3], 0.f);
    h1.x = fmaxf(h1.x + acc[4], 0.f); h1.y = fmaxf(h1.y + acc[5], 0.f);
    h1.z = fmaxf(h1.z + acc[6], 0.f); h1.w = fmaxf(h1.w + acc[7], 0.f);
    H4[base]     = h0;
    H4[base + 1] = h1;
}

// ---------------- head (inputs already relu'd) ------------------------------
__global__ __launch_bounds__(256)
void head_kernel(const float* __restrict__ Wl, const float* __restrict__ bl,
                 float* __restrict__ out) {
    __shared__ float sW[768 * NC];
    int tid = threadIdx.x;
    for (int i = tid; i < 768 * NC; i += blockDim.x) sW[i] = Wl[i];
    __syncthreads();

    int lane = tid & 31;
    int node = blockIdx.x * (blockDim.x >> 5) + (tid >> 5);
    if (node >= NN) return;

    const float* h1 = g_h1 + (size_t)node * HID;
    const float* h2 = g_h2 + (size_t)node * HID;
    const float* h3 = g_h3 + (size_t)node * HID;

    float acc[NC];
#pragma unroll
    for (int c = 0; c < NC; c++) acc[c] = 0.f;

    for (int k = lane; k < HID; k += 32) {
        float v1 = h1[k], v2 = h2[k], v3 = h3[k];
#pragma unroll
        for (int c = 0; c < NC; c++)
            acc[c] += v1 * sW[k * NC + c]
                    + v2 * sW[(HID + k) * NC + c]
                    + v3 * sW[(2 * HID + k) * NC + c];
    }
#pragma unroll
    for (int c = 0; c < NC; c++)
        for (int off = 16; off > 0; off >>= 1)
            acc[c] += __shfl_down_sync(0xffffffffu, acc[c], off);

    if (lane == 0) {
        float lg[NC], mx = -1e30f;
#pragma unroll
        for (int c = 0; c < NC; c++) { lg[c] = acc[c] + bl[c]; mx = fmaxf(mx, lg[c]); }
        float s = 0.f;
#pragma unroll
        for (int c = 0; c < NC; c++) s += expf(lg[c] - mx);
        float lse = mx + logf(s);
#pragma unroll
        for (int c = 0; c < NC; c++) out[(size_t)node * NC + c] = lg[c] - lse;
    }
}

// ---------------------------------------------------------------------------
extern "C" void kernel_launch(void* const* d_in, const int* in_sizes, int n_in,
                              void* d_out, int out_size) {
    const float* x  = (const float*)d_in[0];
    const int*   ei = (const int*)d_in[1];
    const float* ew = (const float*)d_in[2];
    const float* W1 = (const float*)d_in[3];
    const float* b1 = (const float*)d_in[4];
    const float* W2 = (const float*)d_in[5];
    const float* b2 = (const float*)d_in[6];
    const float* W3 = (const float*)d_in[7];
    const float* b3 = (const float*)d_in[8];
    const float* Wl = (const float*)d_in[9];
    const float* bl = (const float*)d_in[10];
    float* out = (float*)d_out;

    const int* src = ei;
    const int* dst = ei + NE;

    float *h1, *h2, *h3;
    uint32_t *q;
    __half *w1t, *w2t, *w3t;
    cudaGetSymbolAddress((void**)&h1,  g_h1);
    cudaGetSymbolAddress((void**)&h2,  g_h2);
    cudaGetSymbolAddress((void**)&h3,  g_h3);
    cudaGetSymbolAddress((void**)&q,   g_q);
    cudaGetSymbolAddress((void**)&w1t, g_w1t);
    cudaGetSymbolAddress((void**)&w2t, g_w2t);
    cudaGetSymbolAddress((void**)&w3t, g_w3t);

    cudaFuncSetAttribute(gemm_tc, cudaFuncAttributeMaxDynamicSharedMemorySize, SMEM_BYTES);

    const int T = 256;
    dim3 gemm_grid(2, (NN + 127) / 128);
    const int node_warps = (NN + 7) / 8;
    const int wtot = W1TN + 2 * W2TN;

    zero_cnt<<<NBLK, SCAN_T>>>();                                    // 0
    count_kernel<<<(NE + T - 1) / T, T>>>(dst);                      // 1
    cvt_wt<<<(wtot + T - 1) / T, T>>>(W1, W2, W3);                   // 2
    gemm_tc<<<gemm_grid, 512, SMEM_BYTES>>>(x, F0, F0, KP1, w1t, b1, h1, q); // 3 <- profiled
    scanA<<<NBLK, SCAN_T>>>();                                       // 4
    scanB<<<1, 512>>>();                                             // 5
    scanC<<<NBLK, SCAN_T>>>();                                       // 6
    place_kernel<<<(NE + T - 1) / T, T>>>(src, dst, ew);             // 7

    spmm_kernel<<<node_warps, T>>>(q, h1);                           // 8

    gemm_tc<<<gemm_grid, 512, SMEM_BYTES>>>(h1, HID, HID, KP2, w2t, b2, h2, q);
    spmm_kernel<<<node_warps, T>>>(q, h2);

    gemm_tc<<<gemm_grid, 512, SMEM_BYTES>>>(h2, HID, HID, KP2, w3t, b3, h3, q);
    spmm_kernel<<<node_warps, T>>>(q, h3);

    head_kernel<<<(NN + 7) / 8, T>>>(Wl, bl, out);
}

// round 12
// speedup vs baseline: 6.8938x; 1.0549x over previous
#include <cuda_runtime.h>
#include <cuda_fp16.h>
#include <cuda_bf16.h>
#include <cstdint>

#define NN 89250
#define NE 899756
#define F0 500
#define HID 256
#define NC  7
#define SCAN_T 256
#define NBLK ((NN + SCAN_T - 1) / SCAN_T)   // 349
#define KP1 512                              // layer-1 K padded
#define KP2 256

// ---------------- scratch (device globals) ---------------------------------
__device__ __align__(256) float g_h1[(size_t)NN * HID];
__device__ __align__(256) float g_h2[(size_t)NN * HID];
__device__ __align__(256) float g_h3[(size_t)NN * HID];
__device__ __align__(256) uint32_t g_q[(size_t)NN * 128];   // Q in bf16x2
// transposed fp16 weights: [half(P/Q)][n 0..255][k 0..KP)
__device__ __align__(256) __half g_w1t[2 * 256 * KP1];
__device__ __align__(256) __half g_w2t[2 * 256 * KP2];
__device__ __align__(256) __half g_w3t[2 * 256 * KP2];
__device__ int   g_cnt[NN];
__device__ int   g_row_start[NN];
__device__ int   g_row_fill[NN];
__device__ int   g_bsum[NBLK];
__device__ int   g_csr_src[NE];
__device__ float g_csr_w[NE];

#define W1TN (2 * 256 * KP1)   // 262144
#define W2TN (2 * 256 * KP2)   // 131072

// ---------------- CSR build kernels -----------------------------------------
__global__ void zero_cnt() {
    int i = blockIdx.x * blockDim.x + threadIdx.x;
    if (i < NN) g_cnt[i] = 0;
}
__global__ void count_kernel(const int* __restrict__ dst) {
    int e = blockIdx.x * blockDim.x + threadIdx.x;
    if (e < NE) atomicAdd(&g_cnt[dst[e]], 1);
}
__global__ void scanA() {
    __shared__ int s[SCAN_T];
    int t = threadIdx.x;
    int i = blockIdx.x * SCAN_T + t;
    s[t] = (i < NN) ? g_cnt[i] : 0;
    __syncthreads();
#pragma unroll
    for (int off = SCAN_T / 2; off > 0; off >>= 1) {
        if (t < off) s[t] += s[t + off];
        __syncthreads();
    }
    if (t == 0) g_bsum[blockIdx.x] = s[0];
}
__global__ void scanB() {
    __shared__ int s[512];
    int t = threadIdx.x;
    int v = (t < NBLK) ? g_bsum[t] : 0;
    s[t] = v;
    __syncthreads();
#pragma unroll
    for (int off = 1; off < 512; off <<= 1) {
        int x = (t >= off) ? s[t - off] : 0;
        __syncthreads();
        s[t] += x;
        __syncthreads();
    }
    if (t < NBLK) g_bsum[t] = s[t] - v;   // exclusive
}
__global__ void scanC() {
    __shared__ int s[SCAN_T];
    int t = threadIdx.x;
    int i = blockIdx.x * SCAN_T + t;
    int v = (i < NN) ? g_cnt[i] : 0;
    s[t] = v;
    __syncthreads();
#pragma unroll
    for (int off = 1; off < SCAN_T; off <<= 1) {
        int x = (t >= off) ? s[t - off] : 0;
        __syncthreads();
        s[t] += x;
        __syncthreads();
    }
    if (i < NN) {
        int excl = s[t] - v + g_bsum[blockIdx.x];
        g_row_start[i] = excl;
        g_row_fill[i]  = excl;
    }
}
__global__ void place_kernel(const int* __restrict__ src, const int* __restrict__ dst,
                             const float* __restrict__ ew) {
    int e = blockIdx.x * blockDim.x + threadIdx.x;
    if (e >= NE) return;
    int d = dst[e];
    int slot = atomicAdd(&g_row_fill[d], 1);
    g_csr_src[slot] = src[e];
    g_csr_w[slot]   = ew[e] / fmaxf((float)g_cnt[d], 1.0f);
}

// ---------------- fp16 / bf16 helpers ----------------------------------------
__device__ __forceinline__ void mma_fp16(float c[4], const uint32_t a[4],
                                         uint32_t b0, uint32_t b1) {
    asm volatile(
        "mma.sync.aligned.m16n8k16.row.col.f32.f16.f16.f32 "
        "{%0,%1,%2,%3}, {%4,%5,%6,%7}, {%8,%9}, {%0,%1,%2,%3};"
        : "+f"(c[0]), "+f"(c[1]), "+f"(c[2]), "+f"(c[3])
        : "r"(a[0]), "r"(a[1]), "r"(a[2]), "r"(a[3]), "r"(b0), "r"(b1));
}
__device__ __forceinline__ void ldsm4(uint32_t r[4], uint32_t addr) {
    asm volatile("ldmatrix.sync.aligned.m8n8.x4.shared.b16 {%0,%1,%2,%3}, [%4];"
                 : "=r"(r[0]), "=r"(r[1]), "=r"(r[2]), "=r"(r[3]) : "r"(addr));
}
__device__ __forceinline__ void cp16(uint32_t dst, const void* src) {
    asm volatile("cp.async.cg.shared.global [%0], [%1], 16;" :: "r"(dst), "l"(src));
}
__device__ __forceinline__ uint32_t smem_u32(const void* p) {
    uint32_t a;
    asm("{ .reg .u64 t; cvta.to.shared.u64 t, %1; cvt.u32.u64 %0, t; }" : "=r"(a) : "l"(p));
    return a;
}
__device__ __forceinline__ uint32_t pack_h2(float lo, float hi) {
    __half2 t = __floats2half2_rn(lo, hi);
    return *reinterpret_cast<uint32_t*>(&t);
}
__device__ __forceinline__ uint32_t pack_bf16x2(float lo, float hi) {
    __nv_bfloat162 t = __float22bfloat162_rn(make_float2(lo, hi));
    return *reinterpret_cast<uint32_t*>(&t);
}
__device__ __forceinline__ float bf_lo(uint32_t u) { return __uint_as_float(u << 16); }
__device__ __forceinline__ float bf_hi(uint32_t u) { return __uint_as_float(u & 0xffff0000u); }

// transpose + fp16-round weights: Wt[half][n][k] = rn(W[half*K + k][n]); K-pad zeros
__global__ void cvt_wt(const float* __restrict__ W1, const float* __restrict__ W2,
                       const float* __restrict__ W3) {
    int i = blockIdx.x * blockDim.x + threadIdx.x;
    if (i < W1TN) {
        int half_ = i >> 17;
        int rem  = i & 131071;
        int n = rem >> 9, k = rem & 511;
        g_w1t[i] = (k < F0) ? __float2half_rn(W1[((size_t)half_ * F0 + k) * 256 + n])
                            : __float2half_rn(0.f);
    } else if (i < W1TN + W2TN) {
        int j = i - W1TN;
        int half_ = j >> 16;
        int rem  = j & 65535;
        int n = rem >> 8, k = rem & 255;
        g_w2t[j] = __float2half_rn(W2[((size_t)half_ * HID + k) * 256 + n]);
    } else if (i < W1TN + 2 * W2TN) {
        int j = i - W1TN - W2TN;
        int half_ = j >> 16;
        int rem  = j & 65535;
        int n = rem >> 8, k = rem & 255;
        g_w3t[j] = __float2half_rn(W3[((size_t)half_ * HID + k) * 256 + n]);
    }
}

// ---------------- fp16 SAGE GEMM: 256 thr, block 64x256, warp 32x64 ---------
// 2 CTAs/SM (regs<=128, smem 70KB). grid = (2, ceil(NN/64)).
// bx=0: H = A@Wtop + bias (fp32); bx=1: Q = A@Wbot (bf16x2)
// A: [2][64 m][80B rows] fp16 k-major. B: [3][256 n][80B rows] fp16 n-major.
#define AS_ROWB   80                         // bytes per A/B row (64 data + 16 pad)
#define AS_STAGEB (64 * AS_ROWB)             // 5120 B
#define BS_STAGEB (256 * AS_ROWB)            // 20480 B
#define SMEM_BYTES (2 * AS_STAGEB + 3 * BS_STAGEB)   // 71680 B

__global__ __launch_bounds__(256, 2)
void gemm_tc(const float* __restrict__ A, int K, int lda, int KP,
             const __half* __restrict__ Wt,   // [2][256][KP] transposed fp16
             const float* __restrict__ bias,
             float* __restrict__ H, uint32_t* __restrict__ Qb)
{
    extern __shared__ char sm[];
    const uint32_t sb  = smem_u32(sm);              // A base
    const uint32_t sbB = sb + 2 * AS_STAGEB;        // B base

    const int bx = blockIdx.x;               // 0 = P path, 1 = Q path
    const int bm = blockIdx.y * 64;
    const __half* Wsel = Wt + (size_t)bx * 256 * KP;

    const int tid  = threadIdx.x;
    const int wid  = tid >> 5;
    const int lane = tid & 31;
    const int wm = (wid >> 2) * 32;          // 0,32
    const int wn = (wid & 3) * 64;           // 0,64,128,192
    const int r0 = lane >> 2, c0 = lane & 3;

    // ldmatrix lane address components
    const int a_roff = (lane & 7) + ((lane >> 3) & 1) * 8;   // A: m rows/row+8
    const int a_kb   = ((lane >> 4) & 1) * 16;               // A: k bytes 0/16
    const int b_roff = (lane & 7) + ((lane >> 4) & 1) * 8;   // B: n rows
    const int b_kb   = ((lane >> 3) & 1) * 16;               // B: k bytes 0/16

    // A staging: 64 rows x 4 chunks(16B) = 256 chunks, 1 per thread
    const int a_row = tid >> 2;              // 0..63
    const int a_k8  = (tid & 3) * 8;         // fp16 offset 0,8,16,24
    const int KT = KP / 32;

    float acc[2][8][4];
#pragma unroll
    for (int mi = 0; mi < 2; mi++)
#pragma unroll
        for (int ni = 0; ni < 8; ni++)
#pragma unroll
            for (int c = 0; c < 4; c++) acc[mi][ni][c] = 0.f;

    // ---- B loader (cp.async, 3-stage ring): 256 n-rows x 32 k-halves ----
    auto loadB = [&](int s) {
        const int buf = s % 3;
        const int k0  = s * 32;
#pragma unroll
        for (int i = 0; i < 4; i++) {
            int c = tid + i * 256;
            int n = c >> 2, kc = (c & 3) * 8;            // 8 halves = 16B
            uint32_t dst = sbB + buf * BS_STAGEB + n * AS_ROWB + kc * 2;
            cp16(dst, Wsel + (size_t)n * KP + k0 + kc);  // K padded: no bound
        }
    };
    // ---- A: gmem -> regs (8 floats per thread) ----
    float4 rA0, rA1;
    auto ldgA = [&](int s) {
        int gk = s * 32 + a_k8;
        int gr = bm + a_row;
        rA0 = make_float4(0.f, 0.f, 0.f, 0.f);
        rA1 = make_float4(0.f, 0.f, 0.f, 0.f);
        if (gr < NN) {
            if (gk < K)     rA0 = *(const float4*)(A + (size_t)gr * lda + gk);
            if (gk + 4 < K) rA1 = *(const float4*)(A + (size_t)gr * lda + gk + 4);
        }
    };
    // ---- A: regs -> smem (fp16 rn) ----
    auto stsA = [&](int s) {
        uint32_t dst = sb + (s & 1) * AS_STAGEB + a_row * AS_ROWB + a_k8 * 2;
        uint4 v;
        v.x = pack_h2(rA0.x, rA0.y); v.y = pack_h2(rA0.z, rA0.w);
        v.z = pack_h2(rA1.x, rA1.y); v.w = pack_h2(rA1.z, rA1.w);
        asm volatile("st.shared.v4.b32 [%0], {%1,%2,%3,%4};"
                     :: "r"(dst), "r"(v.x), "r"(v.y), "r"(v.z), "r"(v.w));
    };

    // ---- prologue ----
    loadB(0); asm volatile("cp.async.commit_group;" ::: "memory");
    loadB(1); asm volatile("cp.async.commit_group;" ::: "memory");
    ldgA(0); stsA(0);
    ldgA(1);
    asm volatile("cp.async.wait_group 1;" ::: "memory");   // B0 ready
    __syncthreads();

    for (int s = 0; s < KT; s++) {
        if (s + 1 < KT) stsA(s + 1);
        if (s + 2 < KT) { ldgA(s + 2); loadB(s + 2); }
        asm volatile("cp.async.commit_group;" ::: "memory");

        const uint32_t aB = sb  + (s & 1) * AS_STAGEB;
        const uint32_t bB = sbB + (s % 3) * BS_STAGEB;
#pragma unroll
        for (int ks = 0; ks < 2; ks++) {                 // two k16 steps per stage
            const int kb = ks * 32;                      // byte offset of k16 block
            uint32_t af[2][4], bfr[16];
#pragma unroll
            for (int mi = 0; mi < 2; mi++)
                ldsm4(af[mi], aB + (wm + mi * 16 + a_roff) * AS_ROWB + kb + a_kb);
#pragma unroll
            for (int nip = 0; nip < 4; nip++)
                ldsm4(&bfr[nip * 4],
                      bB + (wn + nip * 16 + b_roff) * AS_ROWB + kb + b_kb);
#pragma unroll
            for (int mi = 0; mi < 2; mi++)
#pragma unroll
                for (int nip = 0; nip < 4; nip++) {
                    mma_fp16(acc[mi][nip * 2 + 0], af[mi], bfr[nip * 4 + 0], bfr[nip * 4 + 1]);
                    mma_fp16(acc[mi][nip * 2 + 1], af[mi], bfr[nip * 4 + 2], bfr[nip * 4 + 3]);
                }
        }

        if (s + 1 < KT) asm volatile("cp.async.wait_group 1;" ::: "memory");
        __syncthreads();
    }

    // ---- epilogue ----
    if (bx == 0) {
        float2 b2[8];
#pragma unroll
        for (int ni = 0; ni < 8; ni++) {
            int col = wn + ni * 8 + c0 * 2;
            b2[ni].x = bias[col]; b2[ni].y = bias[col + 1];
        }
#pragma unroll
        for (int mi = 0; mi < 2; mi++) {
#pragma unroll
            for (int ci = 0; ci < 2; ci++) {
                int row = bm + wm + mi * 16 + r0 + ci * 8;
                if (row >= NN) continue;
#pragma unroll
                for (int ni = 0; ni < 8; ni++) {
                    int col = wn + ni * 8 + c0 * 2;
                    float2 v;
                    v.x = acc[mi][ni][ci * 2 + 0] + b2[ni].x;
                    v.y = acc[mi][ni][ci * 2 + 1] + b2[ni].y;
                    *(float2*)(H + (size_t)row * 256 + col) = v;
                }
            }
        }
    } else {
#pragma unroll
        for (int mi = 0; mi < 2; mi++) {
#pragma unroll
            for (int ci = 0; ci < 2; ci++) {
                int row = bm + wm + mi * 16 + r0 + ci * 8;
                if (row >= NN) continue;
#pragma unroll
                for (int ni = 0; ni < 8; ni++) {
                    int col = wn + ni * 8 + c0 * 2;     // even
                    Qb[(size_t)row * 128 + (col >> 1)] =
                        pack_bf16x2(acc[mi][ni][ci * 2 + 0], acc[mi][ni][ci * 2 + 1]);
                }
            }
        }
    }
}

// ---------------- gather SpMM: H[n] = relu(H[n] + sum_j w_j * Q[src_j]) -----
// Q in bf16x2: one uint4 per lane per edge (8 values).
__global__ __launch_bounds__(256)
void spmm_kernel(const uint32_t* __restrict__ Q, float* __restrict__ H) {
    int gw   = (blockIdx.x * blockDim.x + threadIdx.x) >> 5;
    int lane = threadIdx.x & 31;
    if (gw >= NN) return;
    int beg = g_row_start[gw];
    int end = beg + g_cnt[gw];

    const uint4* Q4 = (const uint4*)Q;       // row = 32 uint4
    float acc[8];
#pragma unroll
    for (int i = 0; i < 8; i++) acc[i] = 0.f;

    int j = beg;
    for (; j + 2 <= end; j += 2) {
        int   s0 = g_csr_src[j],   s1 = g_csr_src[j + 1];
        float w0 = g_csr_w[j],     w1 = g_csr_w[j + 1];
        uint4 a = Q4[(size_t)s0 * 32 + lane];
        uint4 b = Q4[(size_t)s1 * 32 + lane];
        acc[0] += w0 * bf_lo(a.x) + w1 * bf_lo(b.x);
        acc[1] += w0 * bf_hi(a.x) + w1 * bf_hi(b.x);
        acc[2] += w0 * bf_lo(a.y) + w1 * bf_lo(b.y);
        acc[3] += w0 * bf_hi(a.y) + w1 * bf_hi(b.y);
        acc[4] += w0 * bf_lo(a.z) + w1 * bf_lo(b.z);
        acc[5] += w0 * bf_hi(a.z) + w1 * bf_hi(b.z);
        acc[6] += w0 * bf_lo(a.w) + w1 * bf_lo(b.w);
        acc[7] += w0 * bf_hi(a.w) + w1 * bf_hi(b.w);
    }
    if (j < end) {
        int   s0 = g_csr_src[j];
        float w0 = g_csr_w[j];
        uint4 a = Q4[(size_t)s0 * 32 + lane];
        acc[0] += w0 * bf_lo(a.x); acc[1] += w0 * bf_hi(a.x);
        acc[2] += w0 * bf_lo(a.y); acc[3] += w0 * bf_hi(a.y);
        acc[4] += w0 * bf_lo(a.z); acc[5] += w0 * bf_hi(a.z);
        acc[6] += w0 * bf_lo(a.w); acc[7] += w0 * bf_hi(a.w);
    }

    float4* H4 = (float4*)H;
    size_t base = (size_t)gw * 64 + lane * 2;
    float4 h0 = H4[base];
    float4 h1 = H4[base + 1];
    h0.x = fmaxf(h0.x + acc[0], 0.f); h0.y = fmaxf(h0.y + acc[1], 0.f);
    h0.z = fmaxf(h0.z + acc[2], 0.f); h0.w = fmaxf(h0.w + acc[3], 0.f);
    h1.x = fmaxf(h1.x + acc[4], 0.f); h1.y = fmaxf(h1.y + acc[5], 0.f);
    h1.z = fmaxf(h1.z + acc[6], 0.f); h1.w = fmaxf(h1.w + acc[7], 0.f);
    H4[base]     = h0;
    H4[base + 1] = h1;
}

// ---------------- head (inputs already relu'd) ------------------------------
__global__ __launch_bounds__(256)
void head_kernel(const float* __restrict__ Wl, const float* __restrict__ bl,
                 float* __restrict__ out) {
    __shared__ float sW[768 * NC];
    int tid = threadIdx.x;
    for (int i = tid; i < 768 * NC; i += blockDim.x) sW[i] = Wl[i];
    __syncthreads();

    int lane = tid & 31;
    int node = blockIdx.x * (blockDim.x >> 5) + (tid >> 5);
    if (node >= NN) return;

    const float* h1 = g_h1 + (size_t)node * HID;
    const float* h2 = g_h2 + (size_t)node * HID;
    const float* h3 = g_h3 + (size_t)node * HID;

    float acc[NC];
#pragma unroll
    for (int c = 0; c < NC; c++) acc[c] = 0.f;

    for (int k = lane; k < HID; k += 32) {
        float v1 = h1[k], v2 = h2[k], v3 = h3[k];
#pragma unroll
        for (int c = 0; c < NC; c++)
            acc[c] += v1 * sW[k * NC + c]
                    + v2 * sW[(HID + k) * NC + c]
                    + v3 * sW[(2 * HID + k) * NC + c];
    }
#pragma unroll
    for (int c = 0; c < NC; c++)
        for (int off = 16; off > 0; off >>= 1)
            acc[c] += __shfl_down_sync(0xffffffffu, acc[c], off);

    if (lane == 0) {
        float lg[NC], mx = -1e30f;
#pragma unroll
        for (int c = 0; c < NC; c++) { lg[c] = acc[c] + bl[c]; mx = fmaxf(mx, lg[c]); }
        float s = 0.f;
#pragma unroll
        for (int c = 0; c < NC; c++) s += expf(lg[c] - mx);
        float lse = mx + logf(s);
#pragma unroll
        for (int c = 0; c < NC; c++) out[(size_t)node * NC + c] = lg[c] - lse;
    }
}

// ---------------------------------------------------------------------------
extern "C" void kernel_launch(void* const* d_in, const int* in_sizes, int n_in,
                              void* d_out, int out_size) {
    const float* x  = (const float*)d_in[0];
    const int*   ei = (const int*)d_in[1];
    const float* ew = (const float*)d_in[2];
    const float* W1 = (const float*)d_in[3];
    const float* b1 = (const float*)d_in[4];
    const float* W2 = (const float*)d_in[5];
    const float* b2 = (const float*)d_in[6];
    const float* W3 = (const float*)d_in[7];
    const float* b3 = (const float*)d_in[8];
    const float* Wl = (const float*)d_in[9];
    const float* bl = (const float*)d_in[10];
    float* out = (float*)d_out;

    const int* src = ei;
    const int* dst = ei + NE;

    float *h1, *h2, *h3;
    uint32_t *q;
    __half *w1t, *w2t, *w3t;
    cudaGetSymbolAddress((void**)&h1,  g_h1);
    cudaGetSymbolAddress((void**)&h2,  g_h2);
    cudaGetSymbolAddress((void**)&h3,  g_h3);
    cudaGetSymbolAddress((void**)&q,   g_q);
    cudaGetSymbolAddress((void**)&w1t, g_w1t);
    cudaGetSymbolAddress((void**)&w2t, g_w2t);
    cudaGetSymbolAddress((void**)&w3t, g_w3t);

    cudaFuncSetAttribute(gemm_tc, cudaFuncAttributeMaxDynamicSharedMemorySize, SMEM_BYTES);

    const int T = 256;
    dim3 gemm_grid(2, (NN + 63) / 64);     // 2 x 1395
    const int node_warps = (NN + 7) / 8;
    const int wtot = W1TN + 2 * W2TN;

    zero_cnt<<<NBLK, SCAN_T>>>();                                    // 0
    count_kernel<<<(NE + T - 1) / T, T>>>(dst);                      // 1
    cvt_wt<<<(wtot + T - 1) / T, T>>>(W1, W2, W3);                   // 2
    gemm_tc<<<gemm_grid, T, SMEM_BYTES>>>(x, F0, F0, KP1, w1t, b1, h1, q); // 3 <- profiled
    scanA<<<NBLK, SCAN_T>>>();                                       // 4
    scanB<<<1, 512>>>();                                             // 5
    scanC<<<NBLK, SCAN_T>>>();                                       // 6
    place_kernel<<<(NE + T - 1) / T, T>>>(src, dst, ew);             // 7

    spmm_kernel<<<node_warps, T>>>(q, h1);                           // 8

    gemm_tc<<<gemm_grid, T, SMEM_BYTES>>>(h1, HID, HID, KP2, w2t, b2, h2, q);
    spmm_kernel<<<node_warps, T>>>(q, h2);

    gemm_tc<<<gemm_grid, T, SMEM_BYTES>>>(h2, HID, HID, KP2, w3t, b3, h3, q);
    spmm_kernel<<<node_warps, T>>>(q, h3);

    head_kernel<<<(NN + 7) / 8, T>>>(Wl, bl, out);
}

// round 13
// speedup vs baseline: 7.0415x; 1.0214x over previous
#include <cuda_runtime.h>
#include <cuda_fp16.h>
#include <cstdint>

#define NN 89250
#define NE 899756
#define F0 500
#define HID 256
#define NC  7
#define SCAN_T 256
#define NBLK ((NN + SCAN_T - 1) / SCAN_T)   // 349
#define KP1 512                              // layer-1 K padded
#define KP2 256

// ---------------- scratch (device globals) ---------------------------------
// activations stored as fp16x2 (uint32 words): [node][128]
__device__ __align__(256) uint32_t g_h1[(size_t)NN * 128];
__device__ __align__(256) uint32_t g_h2[(size_t)NN * 128];
__device__ __align__(256) uint32_t g_h3[(size_t)NN * 128];
__device__ __align__(256) uint32_t g_q [(size_t)NN * 128];
// transposed fp16 weights: [half(P/Q)][n 0..255][k 0..KP)
__device__ __align__(256) __half g_w1t[2 * 256 * KP1];
__device__ __align__(256) __half g_w2t[2 * 256 * KP2];
__device__ __align__(256) __half g_w3t[2 * 256 * KP2];
__device__ int   g_cnt[NN];
__device__ int   g_row_start[NN];
__device__ int   g_row_fill[NN];
__device__ int   g_bsum[NBLK];
__device__ int   g_csr_src[NE];
__device__ float g_csr_w[NE];

#define W1TN (2 * 256 * KP1)   // 262144
#define W2TN (2 * 256 * KP2)   // 131072

// ---------------- CSR build kernels -----------------------------------------
__global__ void zero_cnt() {
    int i = blockIdx.x * blockDim.x + threadIdx.x;
    if (i < NN) g_cnt[i] = 0;
}
__global__ void count_kernel(const int* __restrict__ dst) {
    int e = blockIdx.x * blockDim.x + threadIdx.x;
    if (e < NE) atomicAdd(&g_cnt[dst[e]], 1);
}
__global__ void scanA() {
    __shared__ int s[SCAN_T];
    int t = threadIdx.x;
    int i = blockIdx.x * SCAN_T + t;
    s[t] = (i < NN) ? g_cnt[i] : 0;
    __syncthreads();
#pragma unroll
    for (int off = SCAN_T / 2; off > 0; off >>= 1) {
        if (t < off) s[t] += s[t + off];
        __syncthreads();
    }
    if (t == 0) g_bsum[blockIdx.x] = s[0];
}
__global__ void scanB() {
    __shared__ int s[512];
    int t = threadIdx.x;
    int v = (t < NBLK) ? g_bsum[t] : 0;
    s[t] = v;
    __syncthreads();
#pragma unroll
    for (int off = 1; off < 512; off <<= 1) {
        int x = (t >= off) ? s[t - off] : 0;
        __syncthreads();
        s[t] += x;
        __syncthreads();
    }
    if (t < NBLK) g_bsum[t] = s[t] - v;   // exclusive
}
__global__ void scanC() {
    __shared__ int s[SCAN_T];
    int t = threadIdx.x;
    int i = blockIdx.x * SCAN_T + t;
    int v = (i < NN) ? g_cnt[i] : 0;
    s[t] = v;
    __syncthreads();
#pragma unroll
    for (int off = 1; off < SCAN_T; off <<= 1) {
        int x = (t >= off) ? s[t - off] : 0;
        __syncthreads();
        s[t] += x;
        __syncthreads();
    }
    if (i < NN) {
        int excl = s[t] - v + g_bsum[blockIdx.x];
        g_row_start[i] = excl;
        g_row_fill[i]  = excl;
    }
}
__global__ void place_kernel(const int* __restrict__ src, const int* __restrict__ dst,
                             const float* __restrict__ ew) {
    int e = blockIdx.x * blockDim.x + threadIdx.x;
    if (e >= NE) return;
    int d = dst[e];
    int slot = atomicAdd(&g_row_fill[d], 1);
    g_csr_src[slot] = src[e];
    g_csr_w[slot]   = ew[e] / fmaxf((float)g_cnt[d], 1.0f);
}

// ---------------- fp16 helpers -----------------------------------------------
__device__ __forceinline__ void mma_fp16(float c[4], const uint32_t a[4],
                                         uint32_t b0, uint32_t b1) {
    asm volatile(
        "mma.sync.aligned.m16n8k16.row.col.f32.f16.f16.f32 "
        "{%0,%1,%2,%3}, {%4,%5,%6,%7}, {%8,%9}, {%0,%1,%2,%3};"
        : "+f"(c[0]), "+f"(c[1]), "+f"(c[2]), "+f"(c[3])
        : "r"(a[0]), "r"(a[1]), "r"(a[2]), "r"(a[3]), "r"(b0), "r"(b1));
}
__device__ __forceinline__ void ldsm4(uint32_t r[4], uint32_t addr) {
    asm volatile("ldmatrix.sync.aligned.m8n8.x4.shared.b16 {%0,%1,%2,%3}, [%4];"
                 : "=r"(r[0]), "=r"(r[1]), "=r"(r[2]), "=r"(r[3]) : "r"(addr));
}
__device__ __forceinline__ void cp16(uint32_t dst, const void* src) {
    asm volatile("cp.async.cg.shared.global [%0], [%1], 16;" :: "r"(dst), "l"(src));
}
__device__ __forceinline__ uint32_t smem_u32(const void* p) {
    uint32_t a;
    asm("{ .reg .u64 t; cvta.to.shared.u64 t, %1; cvt.u32.u64 %0, t; }" : "=r"(a) : "l"(p));
    return a;
}
__device__ __forceinline__ uint32_t pack_h2(float lo, float hi) {
    __half2 t = __floats2half2_rn(lo, hi);
    return *reinterpret_cast<uint32_t*>(&t);
}
__device__ __forceinline__ float2 unpack_h2(uint32_t u) {
    __half2 h = *reinterpret_cast<__half2*>(&u);
    return __half22float2(h);
}

// transpose + fp16-round weights: Wt[half][n][k] = rn(W[half*K + k][n]); K-pad zeros
__global__ void cvt_wt(const float* __restrict__ W1, const float* __restrict__ W2,
                       const float* __restrict__ W3) {
    int i = blockIdx.x * blockDim.x + threadIdx.x;
    if (i < W1TN) {
        int half_ = i >> 17;
        int rem  = i & 131071;
        int n = rem >> 9, k = rem & 511;
        g_w1t[i] = (k < F0) ? __float2half_rn(W1[((size_t)half_ * F0 + k) * 256 + n])
                            : __float2half_rn(0.f);
    } else if (i < W1TN + W2TN) {
        int j = i - W1TN;
        int half_ = j >> 16;
        int rem  = j & 65535;
        int n = rem >> 8, k = rem & 255;
        g_w2t[j] = __float2half_rn(W2[((size_t)half_ * HID + k) * 256 + n]);
    } else if (i < W1TN + 2 * W2TN) {
        int j = i - W1TN - W2TN;
        int half_ = j >> 16;
        int rem  = j & 65535;
        int n = rem >> 8, k = rem & 255;
        g_w3t[j] = __float2half_rn(W3[((size_t)half_ * HID + k) * 256 + n]);
    }
}

// ---------------- shared GEMM config -----------------------------------------
#define AS_ROWB   80                         // bytes per A/B smem row (64 data + 16 pad)
#define A_STAGEB  (64 * AS_ROWB)             // 5120 B
#define B_STAGEB  (256 * AS_ROWB)            // 20480 B
#define SMEM_F32A (2 * A_STAGEB + 3 * B_STAGEB)   // 71680 B
#define SMEM_F16A (3 * A_STAGEB + 3 * B_STAGEB)   // 76800 B

// ---------------- GEMM core compute+epilogue (shared via macro-ish inline) ---
// warp layout: 8 warps, wm=(wid>>2)*32 (0,32), wn=(wid&3)*64
// epilogue packs fp16 pairs to OUT[row*128 + col/2]; bx=0 adds bias first.

// ---------------- layer-1 GEMM: fp32 A (register-staged), fp16 out ----------
__global__ __launch_bounds__(256, 2)
void gemm_f32A(const float* __restrict__ A, int K, int lda, int KP,
               const __half* __restrict__ Wt, const float* __restrict__ bias,
               uint32_t* __restrict__ Hq, uint32_t* __restrict__ Qb)
{
    extern __shared__ char sm[];
    const uint32_t sb  = smem_u32(sm);
    const uint32_t sbB = sb + 2 * A_STAGEB;

    const int bx = blockIdx.x;
    const int bm = blockIdx.y * 64;
    const __half* Wsel = Wt + (size_t)bx * 256 * KP;

    const int tid  = threadIdx.x;
    const int wid  = tid >> 5;
    const int lane = tid & 31;
    const int wm = (wid >> 2) * 32;
    const int wn = (wid & 3) * 64;
    const int r0 = lane >> 2, c0 = lane & 3;

    const int a_roff = (lane & 7) + ((lane >> 3) & 1) * 8;
    const int a_kb   = ((lane >> 4) & 1) * 16;
    const int b_roff = (lane & 7) + ((lane >> 4) & 1) * 8;
    const int b_kb   = ((lane >> 3) & 1) * 16;

    const int a_row = tid >> 2;
    const int a_k8  = (tid & 3) * 8;
    const int KT = KP / 32;

    float acc[2][8][4];
#pragma unroll
    for (int mi = 0; mi < 2; mi++)
#pragma unroll
        for (int ni = 0; ni < 8; ni++)
#pragma unroll
            for (int c = 0; c < 4; c++) acc[mi][ni][c] = 0.f;

    auto loadB = [&](int s) {
        const int buf = s % 3;
        const int k0  = s * 32;
#pragma unroll
        for (int i = 0; i < 4; i++) {
            int c = tid + i * 256;
            int n = c >> 2, kc = (c & 3) * 8;
            uint32_t dst = sbB + buf * B_STAGEB + n * AS_ROWB + kc * 2;
            cp16(dst, Wsel + (size_t)n * KP + k0 + kc);
        }
    };
    float4 rA0, rA1;
    auto ldgA = [&](int s) {
        int gk = s * 32 + a_k8;
        int gr = bm + a_row;
        rA0 = make_float4(0.f, 0.f, 0.f, 0.f);
        rA1 = make_float4(0.f, 0.f, 0.f, 0.f);
        if (gr < NN) {
            if (gk < K)     rA0 = *(const float4*)(A + (size_t)gr * lda + gk);
            if (gk + 4 < K) rA1 = *(const float4*)(A + (size_t)gr * lda + gk + 4);
        }
    };
    auto stsA = [&](int s) {
        uint32_t dst = sb + (s & 1) * A_STAGEB + a_row * AS_ROWB + a_k8 * 2;
        uint4 v;
        v.x = pack_h2(rA0.x, rA0.y); v.y = pack_h2(rA0.z, rA0.w);
        v.z = pack_h2(rA1.x, rA1.y); v.w = pack_h2(rA1.z, rA1.w);
        asm volatile("st.shared.v4.b32 [%0], {%1,%2,%3,%4};"
                     :: "r"(dst), "r"(v.x), "r"(v.y), "r"(v.z), "r"(v.w));
    };

    loadB(0); asm volatile("cp.async.commit_group;" ::: "memory");
    loadB(1); asm volatile("cp.async.commit_group;" ::: "memory");
    ldgA(0); stsA(0);
    ldgA(1);
    asm volatile("cp.async.wait_group 1;" ::: "memory");
    __syncthreads();

    for (int s = 0; s < KT; s++) {
        if (s + 1 < KT) stsA(s + 1);
        if (s + 2 < KT) { ldgA(s + 2); loadB(s + 2); }
        asm volatile("cp.async.commit_group;" ::: "memory");

        const uint32_t aB = sb  + (s & 1) * A_STAGEB;
        const uint32_t bB = sbB + (s % 3) * B_STAGEB;
#pragma unroll
        for (int ks = 0; ks < 2; ks++) {
            const int kb = ks * 32;
            uint32_t af[2][4], bfr[16];
#pragma unroll
            for (int mi = 0; mi < 2; mi++)
                ldsm4(af[mi], aB + (wm + mi * 16 + a_roff) * AS_ROWB + kb + a_kb);
#pragma unroll
            for (int nip = 0; nip < 4; nip++)
                ldsm4(&bfr[nip * 4],
                      bB + (wn + nip * 16 + b_roff) * AS_ROWB + kb + b_kb);
#pragma unroll
            for (int mi = 0; mi < 2; mi++)
#pragma unroll
                for (int nip = 0; nip < 4; nip++) {
                    mma_fp16(acc[mi][nip * 2 + 0], af[mi], bfr[nip * 4 + 0], bfr[nip * 4 + 1]);
                    mma_fp16(acc[mi][nip * 2 + 1], af[mi], bfr[nip * 4 + 2], bfr[nip * 4 + 3]);
                }
        }

        if (s + 1 < KT) asm volatile("cp.async.wait_group 1;" ::: "memory");
        __syncthreads();
    }

    uint32_t* OUT = (bx == 0) ? Hq : Qb;
    float2 b2[8];
    if (bx == 0) {
#pragma unroll
        for (int ni = 0; ni < 8; ni++) {
            int col = wn + ni * 8 + c0 * 2;
            b2[ni].x = bias[col]; b2[ni].y = bias[col + 1];
        }
    }
#pragma unroll
    for (int mi = 0; mi < 2; mi++) {
#pragma unroll
        for (int ci = 0; ci < 2; ci++) {
            int row = bm + wm + mi * 16 + r0 + ci * 8;
            if (row >= NN) continue;
#pragma unroll
            for (int ni = 0; ni < 8; ni++) {
                int col = wn + ni * 8 + c0 * 2;
                float vx = acc[mi][ni][ci * 2 + 0];
                float vy = acc[mi][ni][ci * 2 + 1];
                if (bx == 0) { vx += b2[ni].x; vy += b2[ni].y; }
                OUT[(size_t)row * 128 + (col >> 1)] = pack_h2(vx, vy);
            }
        }
    }
}

// ---------------- layers 2/3 GEMM: fp16 A via pure cp.async ------------------
__global__ __launch_bounds__(256, 2)
void gemm_f16A(const __half* __restrict__ A,   // [NN][256] fp16
               const __half* __restrict__ Wt, const float* __restrict__ bias,
               uint32_t* __restrict__ Hq, uint32_t* __restrict__ Qb)
{
    extern __shared__ char sm[];
    const uint32_t sb  = smem_u32(sm);
    const uint32_t sbB = sb + 3 * A_STAGEB;
    const int KP = KP2;                      // 256

    const int bx = blockIdx.x;
    const int bm = blockIdx.y * 64;
    const __half* Wsel = Wt + (size_t)bx * 256 * KP;

    const int tid  = threadIdx.x;
    const int wid  = tid >> 5;
    const int lane = tid & 31;
    const int wm = (wid >> 2) * 32;
    const int wn = (wid & 3) * 64;
    const int r0 = lane >> 2, c0 = lane & 3;

    const int a_roff = (lane & 7) + ((lane >> 3) & 1) * 8;
    const int a_kb   = ((lane >> 4) & 1) * 16;
    const int b_roff = (lane & 7) + ((lane >> 4) & 1) * 8;
    const int b_kb   = ((lane >> 3) & 1) * 16;
    const int KT = KP / 32;                  // 8

    float acc[2][8][4];
#pragma unroll
    for (int mi = 0; mi < 2; mi++)
#pragma unroll
        for (int ni = 0; ni < 8; ni++)
#pragma unroll
            for (int c = 0; c < 4; c++) acc[mi][ni][c] = 0.f;

    auto loadStage = [&](int s) {
        const int buf = s % 3;
        const int k0  = s * 32;
        // A: 64 rows x 32 halves, 16B chunks (4/row, 1/thread)
        {
            int r = tid >> 2, kc = (tid & 3) * 8;
            uint32_t dst = sb + buf * A_STAGEB + r * AS_ROWB + kc * 2;
            int gr = bm + r;
            if (gr < NN) cp16(dst, A + (size_t)gr * 256 + k0 + kc);
            else asm volatile("st.shared.v4.b32 [%0], {%1,%1,%1,%1};"
                              :: "r"(dst), "r"(0u));
        }
        // B: 256 rows x 32 halves (4 chunks/thread)
#pragma unroll
        for (int i = 0; i < 4; i++) {
            int c = tid + i * 256;
            int n = c >> 2, kc = (c & 3) * 8;
            uint32_t dst = sbB + buf * B_STAGEB + n * AS_ROWB + kc * 2;
            cp16(dst, Wsel + (size_t)n * KP + k0 + kc);
        }
    };

    loadStage(0); asm volatile("cp.async.commit_group;" ::: "memory");
    loadStage(1); asm volatile("cp.async.commit_group;" ::: "memory");
    asm volatile("cp.async.wait_group 1;" ::: "memory");
    __syncthreads();

    for (int s = 0; s < KT; s++) {
        if (s + 2 < KT) loadStage(s + 2);
        asm volatile("cp.async.commit_group;" ::: "memory");

        const uint32_t aB = sb  + (s % 3) * A_STAGEB;
        const uint32_t bB = sbB + (s % 3) * B_STAGEB;
#pragma unroll
        for (int ks = 0; ks < 2; ks++) {
            const int kb = ks * 32;
            uint32_t af[2][4], bfr[16];
#pragma unroll
            for (int mi = 0; mi < 2; mi++)
                ldsm4(af[mi], aB + (wm + mi * 16 + a_roff) * AS_ROWB + kb + a_kb);
#pragma unroll
            for (int nip = 0; nip < 4; nip++)
                ldsm4(&bfr[nip * 4],
                      bB + (wn + nip * 16 + b_roff) * AS_ROWB + kb + b_kb);
#pragma unroll
            for (int mi = 0; mi < 2; mi++)
#pragma unroll
                for (int nip = 0; nip < 4; nip++) {
                    mma_fp16(acc[mi][nip * 2 + 0], af[mi], bfr[nip * 4 + 0], bfr[nip * 4 + 1]);
                    mma_fp16(acc[mi][nip * 2 + 1], af[mi], bfr[nip * 4 + 2], bfr[nip * 4 + 3]);
                }
        }

        if (s + 1 < KT) asm volatile("cp.async.wait_group 1;" ::: "memory");
        __syncthreads();
    }

    uint32_t* OUT = (bx == 0) ? Hq : Qb;
    float2 b2[8];
    if (bx == 0) {
#pragma unroll
        for (int ni = 0; ni < 8; ni++) {
            int col = wn + ni * 8 + c0 * 2;
            b2[ni].x = bias[col]; b2[ni].y = bias[col + 1];
        }
    }
#pragma unroll
    for (int mi = 0; mi < 2; mi++) {
#pragma unroll
        for (int ci = 0; ci < 2; ci++) {
            int row = bm + wm + mi * 16 + r0 + ci * 8;
            if (row >= NN) continue;
#pragma unroll
            for (int ni = 0; ni < 8; ni++) {
                int col = wn + ni * 8 + c0 * 2;
                float vx = acc[mi][ni][ci * 2 + 0];
                float vy = acc[mi][ni][ci * 2 + 1];
                if (bx == 0) { vx += b2[ni].x; vy += b2[ni].y; }
                OUT[(size_t)row * 128 + (col >> 1)] = pack_h2(vx, vy);
            }
        }
    }
}

// ---------------- gather SpMM: H[n] = relu(H[n] + sum_j w_j * Q[src_j]) -----
// Q and H in fp16x2. One uint4/lane/edge; one uint4 H RMW per lane.
__global__ __launch_bounds__(256)
void spmm_kernel(const uint32_t* __restrict__ Q, uint32_t* __restrict__ H) {
    int gw   = (blockIdx.x * blockDim.x + threadIdx.x) >> 5;
    int lane = threadIdx.x & 31;
    if (gw >= NN) return;
    int beg = g_row_start[gw];
    int end = beg + g_cnt[gw];

    const uint4* Q4 = (const uint4*)Q;       // row = 32 uint4
    float acc[8];
#pragma unroll
    for (int i = 0; i < 8; i++) acc[i] = 0.f;

#define ACCUM(u, w, o) { float2 f = unpack_h2(u); acc[o] += (w) * f.x; acc[o+1] += (w) * f.y; }

    int j = beg;
    for (; j + 2 <= end; j += 2) {
        int   s0 = g_csr_src[j],   s1 = g_csr_src[j + 1];
        float w0 = g_csr_w[j],     w1 = g_csr_w[j + 1];
        uint4 a = Q4[(size_t)s0 * 32 + lane];
        uint4 b = Q4[(size_t)s1 * 32 + lane];
        ACCUM(a.x, w0, 0) ACCUM(a.y, w0, 2) ACCUM(a.z, w0, 4) ACCUM(a.w, w0, 6)
        ACCUM(b.x, w1, 0) ACCUM(b.y, w1, 2) ACCUM(b.z, w1, 4) ACCUM(b.w, w1, 6)
    }
    if (j < end) {
        int   s0 = g_csr_src[j];
        float w0 = g_csr_w[j];
        uint4 a = Q4[(size_t)s0 * 32 + lane];
        ACCUM(a.x, w0, 0) ACCUM(a.y, w0, 2) ACCUM(a.z, w0, 4) ACCUM(a.w, w0, 6)
    }
#undef ACCUM

    uint4* H4 = (uint4*)H;
    size_t base = (size_t)gw * 32 + lane;
    uint4 hv = H4[base];
    float2 f0 = unpack_h2(hv.x), f1 = unpack_h2(hv.y);
    float2 f2 = unpack_h2(hv.z), f3 = unpack_h2(hv.w);
    hv.x = pack_h2(fmaxf(f0.x + acc[0], 0.f), fmaxf(f0.y + acc[1], 0.f));
    hv.y = pack_h2(fmaxf(f1.x + acc[2], 0.f), fmaxf(f1.y + acc[3], 0.f));
    hv.z = pack_h2(fmaxf(f2.x + acc[4], 0.f), fmaxf(f2.y + acc[5], 0.f));
    hv.w = pack_h2(fmaxf(f3.x + acc[6], 0.f), fmaxf(f3.y + acc[7], 0.f));
    H4[base] = hv;
}

// ---------------- head (inputs already relu'd, fp16) -------------------------
__global__ __launch_bounds__(256)
void head_kernel(const float* __restrict__ Wl, const float* __restrict__ bl,
                 float* __restrict__ out) {
    __shared__ float sW[768 * NC];
    int tid = threadIdx.x;
    for (int i = tid; i < 768 * NC; i += blockDim.x) sW[i] = Wl[i];
    __syncthreads();

    int lane = tid & 31;
    int node = blockIdx.x * (blockDim.x >> 5) + (tid >> 5);
    if (node >= NN) return;

    const uint32_t* h1 = g_h1 + (size_t)node * 128;
    const uint32_t* h2 = g_h2 + (size_t)node * 128;
    const uint32_t* h3 = g_h3 + (size_t)node * 128;

    float acc[NC];
#pragma unroll
    for (int c = 0; c < NC; c++) acc[c] = 0.f;

    for (int kk = lane; kk < 128; kk += 32) {
        float2 v1 = unpack_h2(h1[kk]);
        float2 v2 = unpack_h2(h2[kk]);
        float2 v3 = unpack_h2(h3[kk]);
        int k = kk * 2;
#pragma unroll
        for (int c = 0; c < NC; c++)
            acc[c] += v1.x * sW[k * NC + c]           + v1.y * sW[(k + 1) * NC + c]
                    + v2.x * sW[(256 + k) * NC + c]   + v2.y * sW[(257 + k) * NC + c]
                    + v3.x * sW[(512 + k) * NC + c]   + v3.y * sW[(513 + k) * NC + c];
    }
#pragma unroll
    for (int c = 0; c < NC; c++)
        for (int off = 16; off > 0; off >>= 1)
            acc[c] += __shfl_down_sync(0xffffffffu, acc[c], off);

    if (lane == 0) {
        float lg[NC], mx = -1e30f;
#pragma unroll
        for (int c = 0; c < NC; c++) { lg[c] = acc[c] + bl[c]; mx = fmaxf(mx, lg[c]); }
        float s = 0.f;
#pragma unroll
        for (int c = 0; c < NC; c++) s += expf(lg[c] - mx);
        float lse = mx + logf(s);
#pragma unroll
        for (int c = 0; c < NC; c++) out[(size_t)node * NC + c] = lg[c] - lse;
    }
}

// ---------------------------------------------------------------------------
extern "C" void kernel_launch(void* const* d_in, const int* in_sizes, int n_in,
                              void* d_out, int out_size) {
    const float* x  = (const float*)d_in[0];
    const int*   ei = (const int*)d_in[1];
    const float* ew = (const float*)d_in[2];
    const float* W1 = (const float*)d_in[3];
    const float* b1 = (const float*)d_in[4];
    const float* W2 = (const float*)d_in[5];
    const float* b2 = (const float*)d_in[6];
    const float* W3 = (const float*)d_in[7];
    const float* b3 = (const float*)d_in[8];
    const float* Wl = (const float*)d_in[9];
    const float* bl = (const float*)d_in[10];
    float* out = (float*)d_out;

    const int* src = ei;
    const int* dst = ei + NE;

    uint32_t *h1, *h2, *h3, *q;
    __half *w1t, *w2t, *w3t;
    cudaGetSymbolAddress((void**)&h1,  g_h1);
    cudaGetSymbolAddress((void**)&h2,  g_h2);
    cudaGetSymbolAddress((void**)&h3,  g_h3);
    cudaGetSymbolAddress((void**)&q,   g_q);
    cudaGetSymbolAddress((void**)&w1t, g_w1t);
    cudaGetSymbolAddress((void**)&w2t, g_w2t);
    cudaGetSymbolAddress((void**)&w3t, g_w3t);

    cudaFuncSetAttribute(gemm_f32A, cudaFuncAttributeMaxDynamicSharedMemorySize, SMEM_F32A);
    cudaFuncSetAttribute(gemm_f16A, cudaFuncAttributeMaxDynamicSharedMemorySize, SMEM_F16A);

    const int T = 256;
    dim3 gemm_grid(2, (NN + 63) / 64);     // 2 x 1395
    const int node_warps = (NN + 7) / 8;
    const int wtot = W1TN + 2 * W2TN;

    zero_cnt<<<NBLK, SCAN_T>>>();                                    // 0
    count_kernel<<<(NE + T - 1) / T, T>>>(dst);                      // 1
    cvt_wt<<<(wtot + T - 1) / T, T>>>(W1, W2, W3);                   // 2
    gemm_f32A<<<gemm_grid, T, SMEM_F32A>>>(x, F0, F0, KP1, w1t, b1, h1, q); // 3 <- profiled
    scanA<<<NBLK, SCAN_T>>>();                                       // 4
    scanB<<<1, 512>>>();                                             // 5
    scanC<<<NBLK, SCAN_T>>>();                                       // 6
    place_kernel<<<(NE + T - 1) / T, T>>>(src, dst, ew);             // 7

    spmm_kernel<<<node_warps, T>>>(q, h1);                           // 8

    gemm_f16A<<<gemm_grid, T, SMEM_F16A>>>((const __half*)h1, w2t, b2, h2, q);
    spmm_kernel<<<node_warps, T>>>(q, h2);

    gemm_f16A<<<gemm_grid, T, SMEM_F16A>>>((const __half*)h2, w3t, b3, h3, q);
    spmm_kernel<<<node_warps, T>>>(q, h3);

    head_kernel<<<(NN + 7) / 8, T>>>(Wl, bl, out);
}

// round 14
// speedup vs baseline: 7.0930x; 1.0073x over previous
#include <cuda_runtime.h>
#include <cuda_fp16.h>
#include <cstdint>

#define NN 89250
#define NE 899756
#define F0 500
#define HID 256
#define NC  7
#define SCAN_T 256
#define NBLK ((NN + SCAN_T - 1) / SCAN_T)   // 349
#define KP1 512                              // layer-1 K padded
#define KP2 256

// ---------------- scratch (device globals) ---------------------------------
// activations stored as fp16x2 (uint32 words): [node][128]
__device__ __align__(256) uint32_t g_h1[(size_t)NN * 128];
__device__ __align__(256) uint32_t g_h2[(size_t)NN * 128];
__device__ __align__(256) uint32_t g_h3[(size_t)NN * 128];
__device__ __align__(256) uint32_t g_q [(size_t)NN * 128];
// transposed fp16 weights: [half(P/Q)][n 0..255][k 0..KP)
__device__ __align__(256) __half g_w1t[2 * 256 * KP1];
__device__ __align__(256) __half g_w2t[2 * 256 * KP2];
__device__ __align__(256) __half g_w3t[2 * 256 * KP2];
__device__ int   g_cnt[NN];
__device__ int   g_row_start[NN];
__device__ int   g_row_fill[NN];
__device__ int   g_bsum[NBLK];
__device__ int   g_csr_src[NE];
__device__ float g_csr_w[NE];

#define W1TN (2 * 256 * KP1)   // 262144
#define W2TN (2 * 256 * KP2)   // 131072

// ---------------- CSR build kernels -----------------------------------------
__global__ void zero_cnt() {
    int i = blockIdx.x * blockDim.x + threadIdx.x;
    if (i < NN) g_cnt[i] = 0;
}
__global__ void count_kernel(const int* __restrict__ dst) {
    int e = blockIdx.x * blockDim.x + threadIdx.x;
    if (e < NE) atomicAdd(&g_cnt[dst[e]], 1);
}
__global__ void scanA() {
    __shared__ int s[SCAN_T];
    int t = threadIdx.x;
    int i = blockIdx.x * SCAN_T + t;
    s[t] = (i < NN) ? g_cnt[i] : 0;
    __syncthreads();
#pragma unroll
    for (int off = SCAN_T / 2; off > 0; off >>= 1) {
        if (t < off) s[t] += s[t + off];
        __syncthreads();
    }
    if (t == 0) g_bsum[blockIdx.x] = s[0];
}
__global__ void scanB() {
    __shared__ int s[512];
    int t = threadIdx.x;
    int v = (t < NBLK) ? g_bsum[t] : 0;
    s[t] = v;
    __syncthreads();
#pragma unroll
    for (int off = 1; off < 512; off <<= 1) {
        int x = (t >= off) ? s[t - off] : 0;
        __syncthreads();
        s[t] += x;
        __syncthreads();
    }
    if (t < NBLK) g_bsum[t] = s[t] - v;   // exclusive
}
__global__ void scanC() {
    __shared__ int s[SCAN_T];
    int t = threadIdx.x;
    int i = blockIdx.x * SCAN_T + t;
    int v = (i < NN) ? g_cnt[i] : 0;
    s[t] = v;
    __syncthreads();
#pragma unroll
    for (int off = 1; off < SCAN_T; off <<= 1) {
        int x = (t >= off) ? s[t - off] : 0;
        __syncthreads();
        s[t] += x;
        __syncthreads();
    }
    if (i < NN) {
        int excl = s[t] - v + g_bsum[blockIdx.x];
        g_row_start[i] = excl;
        g_row_fill[i]  = excl;
    }
}
__global__ void place_kernel(const int* __restrict__ src, const int* __restrict__ dst,
                             const float* __restrict__ ew) {
    int e = blockIdx.x * blockDim.x + threadIdx.x;
    if (e >= NE) return;
    int d = dst[e];
    int slot = atomicAdd(&g_row_fill[d], 1);
    g_csr_src[slot] = src[e];
    g_csr_w[slot]   = ew[e] / fmaxf((float)g_cnt[d], 1.0f);
}

// ---------------- fp16 helpers -----------------------------------------------
__device__ __forceinline__ void mma_fp16(float c[4], const uint32_t a[4],
                                         uint32_t b0, uint32_t b1) {
    asm volatile(
        "mma.sync.aligned.m16n8k16.row.col.f32.f16.f16.f32 "
        "{%0,%1,%2,%3}, {%4,%5,%6,%7}, {%8,%9}, {%0,%1,%2,%3};"
        : "+f"(c[0]), "+f"(c[1]), "+f"(c[2]), "+f"(c[3])
        : "r"(a[0]), "r"(a[1]), "r"(a[2]), "r"(a[3]), "r"(b0), "r"(b1));
}
__device__ __forceinline__ void ldsm4(uint32_t r[4], uint32_t addr) {
    asm volatile("ldmatrix.sync.aligned.m8n8.x4.shared.b16 {%0,%1,%2,%3}, [%4];"
                 : "=r"(r[0]), "=r"(r[1]), "=r"(r[2]), "=r"(r[3]) : "r"(addr));
}
__device__ __forceinline__ void cp16(uint32_t dst, const void* src) {
    asm volatile("cp.async.cg.shared.global [%0], [%1], 16;" :: "r"(dst), "l"(src));
}
__device__ __forceinline__ uint32_t smem_u32(const void* p) {
    uint32_t a;
    asm("{ .reg .u64 t; cvta.to.shared.u64 t, %1; cvt.u32.u64 %0, t; }" : "=r"(a) : "l"(p));
    return a;
}
__device__ __forceinline__ uint32_t pack_h2(float lo, float hi) {
    __half2 t = __floats2half2_rn(lo, hi);
    return *reinterpret_cast<uint32_t*>(&t);
}
__device__ __forceinline__ float2 unpack_h2(uint32_t u) {
    __half2 h = *reinterpret_cast<__half2*>(&u);
    return __half22float2(h);
}

// transpose + fp16-round weights: Wt[half][n][k] = rn(W[half*K + k][n]); K-pad zeros
__global__ void cvt_wt(const float* __restrict__ W1, const float* __restrict__ W2,
                       const float* __restrict__ W3) {
    int i = blockIdx.x * blockDim.x + threadIdx.x;
    if (i < W1TN) {
        int half_ = i >> 17;
        int rem  = i & 131071;
        int n = rem >> 9, k = rem & 511;
        g_w1t[i] = (k < F0) ? __float2half_rn(W1[((size_t)half_ * F0 + k) * 256 + n])
                            : __float2half_rn(0.f);
    } else if (i < W1TN + W2TN) {
        int j = i - W1TN;
        int half_ = j >> 16;
        int rem  = j & 65535;
        int n = rem >> 8, k = rem & 255;
        g_w2t[j] = __float2half_rn(W2[((size_t)half_ * HID + k) * 256 + n]);
    } else if (i < W1TN + 2 * W2TN) {
        int j = i - W1TN - W2TN;
        int half_ = j >> 16;
        int rem  = j & 65535;
        int n = rem >> 8, k = rem & 255;
        g_w3t[j] = __float2half_rn(W3[((size_t)half_ * HID + k) * 256 + n]);
    }
}

// ---------------- shared GEMM config -----------------------------------------
#define AS_ROWB   80                         // bytes per A/B smem row (64 data + 16 pad)
#define A_STAGEB  (64 * AS_ROWB)             // 5120 B
#define B_STAGEB  (256 * AS_ROWB)            // 20480 B
#define SMEM_F32A (2 * A_STAGEB + 4 * B_STAGEB)   // 92160 B
#define SMEM_F16A (4 * A_STAGEB + 4 * B_STAGEB)   // 102400 B

// ---------------- layer-1 GEMM: fp32 A (register-staged), fp16 out ----------
// B ring: 4 stages, prefetch distance 3, wait_group 2.
__global__ __launch_bounds__(256, 2)
void gemm_f32A(const float* __restrict__ A, int K, int lda, int KP,
               const __half* __restrict__ Wt, const float* __restrict__ bias,
               uint32_t* __restrict__ Hq, uint32_t* __restrict__ Qb)
{
    extern __shared__ char sm[];
    const uint32_t sb  = smem_u32(sm);
    const uint32_t sbB = sb + 2 * A_STAGEB;

    const int bx = blockIdx.x;
    const int bm = blockIdx.y * 64;
    const __half* Wsel = Wt + (size_t)bx * 256 * KP;

    const int tid  = threadIdx.x;
    const int wid  = tid >> 5;
    const int lane = tid & 31;
    const int wm = (wid >> 2) * 32;
    const int wn = (wid & 3) * 64;
    const int r0 = lane >> 2, c0 = lane & 3;

    const int a_roff = (lane & 7) + ((lane >> 3) & 1) * 8;
    const int a_kb   = ((lane >> 4) & 1) * 16;
    const int b_roff = (lane & 7) + ((lane >> 4) & 1) * 8;
    const int b_kb   = ((lane >> 3) & 1) * 16;

    const int a_row = tid >> 2;
    const int a_k8  = (tid & 3) * 8;
    const int KT = KP / 32;

    float acc[2][8][4];
#pragma unroll
    for (int mi = 0; mi < 2; mi++)
#pragma unroll
        for (int ni = 0; ni < 8; ni++)
#pragma unroll
            for (int c = 0; c < 4; c++) acc[mi][ni][c] = 0.f;

    auto loadB = [&](int s) {
        const int buf = s & 3;
        const int k0  = s * 32;
#pragma unroll
        for (int i = 0; i < 4; i++) {
            int c = tid + i * 256;
            int n = c >> 2, kc = (c & 3) * 8;
            uint32_t dst = sbB + buf * B_STAGEB + n * AS_ROWB + kc * 2;
            cp16(dst, Wsel + (size_t)n * KP + k0 + kc);
        }
    };
    float4 rA0, rA1;
    auto ldgA = [&](int s) {
        int gk = s * 32 + a_k8;
        int gr = bm + a_row;
        rA0 = make_float4(0.f, 0.f, 0.f, 0.f);
        rA1 = make_float4(0.f, 0.f, 0.f, 0.f);
        if (gr < NN) {
            if (gk < K)     rA0 = *(const float4*)(A + (size_t)gr * lda + gk);
            if (gk + 4 < K) rA1 = *(const float4*)(A + (size_t)gr * lda + gk + 4);
        }
    };
    auto stsA = [&](int s) {
        uint32_t dst = sb + (s & 1) * A_STAGEB + a_row * AS_ROWB + a_k8 * 2;
        uint4 v;
        v.x = pack_h2(rA0.x, rA0.y); v.y = pack_h2(rA0.z, rA0.w);
        v.z = pack_h2(rA1.x, rA1.y); v.w = pack_h2(rA1.z, rA1.w);
        asm volatile("st.shared.v4.b32 [%0], {%1,%2,%3,%4};"
                     :: "r"(dst), "r"(v.x), "r"(v.y), "r"(v.z), "r"(v.w));
    };

    loadB(0); asm volatile("cp.async.commit_group;" ::: "memory");
    loadB(1); asm volatile("cp.async.commit_group;" ::: "memory");
    loadB(2); asm volatile("cp.async.commit_group;" ::: "memory");
    ldgA(0); stsA(0);
    ldgA(1);
    asm volatile("cp.async.wait_group 2;" ::: "memory");   // B0 ready
    __syncthreads();

    for (int s = 0; s < KT; s++) {
        if (s + 1 < KT) stsA(s + 1);
        if (s + 2 < KT) ldgA(s + 2);
        if (s + 3 < KT) loadB(s + 3);
        asm volatile("cp.async.commit_group;" ::: "memory");

        const uint32_t aB = sb  + (s & 1) * A_STAGEB;
        const uint32_t bB = sbB + (s & 3) * B_STAGEB;
#pragma unroll
        for (int ks = 0; ks < 2; ks++) {
            const int kb = ks * 32;
            uint32_t af[2][4], bfr[16];
#pragma unroll
            for (int mi = 0; mi < 2; mi++)
                ldsm4(af[mi], aB + (wm + mi * 16 + a_roff) * AS_ROWB + kb + a_kb);
#pragma unroll
            for (int nip = 0; nip < 4; nip++)
                ldsm4(&bfr[nip * 4],
                      bB + (wn + nip * 16 + b_roff) * AS_ROWB + kb + b_kb);
#pragma unroll
            for (int mi = 0; mi < 2; mi++)
#pragma unroll
                for (int nip = 0; nip < 4; nip++) {
                    mma_fp16(acc[mi][nip * 2 + 0], af[mi], bfr[nip * 4 + 0], bfr[nip * 4 + 1]);
                    mma_fp16(acc[mi][nip * 2 + 1], af[mi], bfr[nip * 4 + 2], bfr[nip * 4 + 3]);
                }
        }

        if (s + 1 < KT) asm volatile("cp.async.wait_group 2;" ::: "memory");
        __syncthreads();
    }

    uint32_t* OUT = (bx == 0) ? Hq : Qb;
    float2 b2[8];
    if (bx == 0) {
#pragma unroll
        for (int ni = 0; ni < 8; ni++) {
            int col = wn + ni * 8 + c0 * 2;
            b2[ni].x = bias[col]; b2[ni].y = bias[col + 1];
        }
    }
#pragma unroll
    for (int mi = 0; mi < 2; mi++) {
#pragma unroll
        for (int ci = 0; ci < 2; ci++) {
            int row = bm + wm + mi * 16 + r0 + ci * 8;
            if (row >= NN) continue;
#pragma unroll
            for (int ni = 0; ni < 8; ni++) {
                int col = wn + ni * 8 + c0 * 2;
                float vx = acc[mi][ni][ci * 2 + 0];
                float vy = acc[mi][ni][ci * 2 + 1];
                if (bx == 0) { vx += b2[ni].x; vy += b2[ni].y; }
                OUT[(size_t)row * 128 + (col >> 1)] = pack_h2(vx, vy);
            }
        }
    }
}

// ---------------- layers 2/3 GEMM: fp16 A via pure cp.async ------------------
// A+B rings: 4 stages, prefetch distance 3, wait_group 2.
__global__ __launch_bounds__(256, 2)
void gemm_f16A(const __half* __restrict__ A,   // [NN][256] fp16
               const __half* __restrict__ Wt, const float* __restrict__ bias,
               uint32_t* __restrict__ Hq, uint32_t* __restrict__ Qb)
{
    extern __shared__ char sm[];
    const uint32_t sb  = smem_u32(sm);
    const uint32_t sbB = sb + 4 * A_STAGEB;
    const int KP = KP2;                      // 256

    const int bx = blockIdx.x;
    const int bm = blockIdx.y * 64;
    const __half* Wsel = Wt + (size_t)bx * 256 * KP;

    const int tid  = threadIdx.x;
    const int wid  = tid >> 5;
    const int lane = tid & 31;
    const int wm = (wid >> 2) * 32;
    const int wn = (wid & 3) * 64;
    const int r0 = lane >> 2, c0 = lane & 3;

    const int a_roff = (lane & 7) + ((lane >> 3) & 1) * 8;
    const int a_kb   = ((lane >> 4) & 1) * 16;
    const int b_roff = (lane & 7) + ((lane >> 4) & 1) * 8;
    const int b_kb   = ((lane >> 3) & 1) * 16;
    const int KT = KP / 32;                  // 8

    float acc[2][8][4];
#pragma unroll
    for (int mi = 0; mi < 2; mi++)
#pragma unroll
        for (int ni = 0; ni < 8; ni++)
#pragma unroll
            for (int c = 0; c < 4; c++) acc[mi][ni][c] = 0.f;

    auto loadStage = [&](int s) {
        const int buf = s & 3;
        const int k0  = s * 32;
        {
            int r = tid >> 2, kc = (tid & 3) * 8;
            uint32_t dst = sb + buf * A_STAGEB + r * AS_ROWB + kc * 2;
            int gr = bm + r;
            if (gr < NN) cp16(dst, A + (size_t)gr * 256 + k0 + kc);
            else asm volatile("st.shared.v4.b32 [%0], {%1,%1,%1,%1};"
                              :: "r"(dst), "r"(0u));
        }
#pragma unroll
        for (int i = 0; i < 4; i++) {
            int c = tid + i * 256;
            int n = c >> 2, kc = (c & 3) * 8;
            uint32_t dst = sbB + buf * B_STAGEB + n * AS_ROWB + kc * 2;
            cp16(dst, Wsel + (size_t)n * KP + k0 + kc);
        }
    };

    loadStage(0); asm volatile("cp.async.commit_group;" ::: "memory");
    loadStage(1); asm volatile("cp.async.commit_group;" ::: "memory");
    loadStage(2); asm volatile("cp.async.commit_group;" ::: "memory");
    asm volatile("cp.async.wait_group 2;" ::: "memory");
    __syncthreads();

    for (int s = 0; s < KT; s++) {
        if (s + 3 < KT) loadStage(s + 3);
        asm volatile("cp.async.commit_group;" ::: "memory");

        const uint32_t aB = sb  + (s & 3) * A_STAGEB;
        const uint32_t bB = sbB + (s & 3) * B_STAGEB;
#pragma unroll
        for (int ks = 0; ks < 2; ks++) {
            const int kb = ks * 32;
            uint32_t af[2][4], bfr[16];
#pragma unroll
            for (int mi = 0; mi < 2; mi++)
                ldsm4(af[mi], aB + (wm + mi * 16 + a_roff) * AS_ROWB + kb + a_kb);
#pragma unroll
            for (int nip = 0; nip < 4; nip++)
                ldsm4(&bfr[nip * 4],
                      bB + (wn + nip * 16 + b_roff) * AS_ROWB + kb + b_kb);
#pragma unroll
            for (int mi = 0; mi < 2; mi++)
#pragma unroll
                for (int nip = 0; nip < 4; nip++) {
                    mma_fp16(acc[mi][nip * 2 + 0], af[mi], bfr[nip * 4 + 0], bfr[nip * 4 + 1]);
                    mma_fp16(acc[mi][nip * 2 + 1], af[mi], bfr[nip * 4 + 2], bfr[nip * 4 + 3]);
                }
        }

        if (s + 1 < KT) asm volatile("cp.async.wait_group 2;" ::: "memory");
        __syncthreads();
    }

    uint32_t* OUT = (bx == 0) ? Hq : Qb;
    float2 b2[8];
    if (bx == 0) {
#pragma unroll
        for (int ni = 0; ni < 8; ni++) {
            int col = wn + ni * 8 + c0 * 2;
            b2[ni].x = bias[col]; b2[ni].y = bias[col + 1];
        }
    }
#pragma unroll
    for (int mi = 0; mi < 2; mi++) {
#pragma unroll
        for (int ci = 0; ci < 2; ci++) {
            int row = bm + wm + mi * 16 + r0 + ci * 8;
            if (row >= NN) continue;
#pragma unroll
            for (int ni = 0; ni < 8; ni++) {
                int col = wn + ni * 8 + c0 * 2;
                float vx = acc[mi][ni][ci * 2 + 0];
                float vy = acc[mi][ni][ci * 2 + 1];
                if (bx == 0) { vx += b2[ni].x; vy += b2[ni].y; }
                OUT[(size_t)row * 128 + (col >> 1)] = pack_h2(vx, vy);
            }
        }
    }
}

// ---------------- gather SpMM: H[n] = relu(H[n] + sum_j w_j * Q[src_j]) -----
// Q and H in fp16x2. One uint4/lane/edge; unroll-4 over edges for MLP.
__global__ __launch_bounds__(256)
void spmm_kernel(const uint32_t* __restrict__ Q, uint32_t* __restrict__ H) {
    int gw   = (blockIdx.x * blockDim.x + threadIdx.x) >> 5;
    int lane = threadIdx.x & 31;
    if (gw >= NN) return;
    int beg = g_row_start[gw];
    int end = beg + g_cnt[gw];

    const uint4* Q4 = (const uint4*)Q;       // row = 32 uint4
    float acc[8];
#pragma unroll
    for (int i = 0; i < 8; i++) acc[i] = 0.f;

#define ACCUM(u, w, o) { float2 f = unpack_h2(u); acc[o] += (w) * f.x; acc[o+1] += (w) * f.y; }

    int j = beg;
    for (; j + 4 <= end; j += 4) {
        int   s0 = g_csr_src[j],     s1 = g_csr_src[j + 1];
        int   s2 = g_csr_src[j + 2], s3 = g_csr_src[j + 3];
        float w0 = g_csr_w[j],       w1 = g_csr_w[j + 1];
        float w2 = g_csr_w[j + 2],   w3 = g_csr_w[j + 3];
        uint4 a = Q4[(size_t)s0 * 32 + lane];
        uint4 b = Q4[(size_t)s1 * 32 + lane];
        uint4 c = Q4[(size_t)s2 * 32 + lane];
        uint4 d = Q4[(size_t)s3 * 32 + lane];
        ACCUM(a.x, w0, 0) ACCUM(a.y, w0, 2) ACCUM(a.z, w0, 4) ACCUM(a.w, w0, 6)
        ACCUM(b.x, w1, 0) ACCUM(b.y, w1, 2) ACCUM(b.z, w1, 4) ACCUM(b.w, w1, 6)
        ACCUM(c.x, w2, 0) ACCUM(c.y, w2, 2) ACCUM(c.z, w2, 4) ACCUM(c.w, w2, 6)
        ACCUM(d.x, w3, 0) ACCUM(d.y, w3, 2) ACCUM(d.z, w3, 4) ACCUM(d.w, w3, 6)
    }
    for (; j < end; j++) {
        int   s0 = g_csr_src[j];
        float w0 = g_csr_w[j];
        uint4 a = Q4[(size_t)s0 * 32 + lane];
        ACCUM(a.x, w0, 0) ACCUM(a.y, w0, 2) ACCUM(a.z, w0, 4) ACCUM(a.w, w0, 6)
    }
#undef ACCUM

    uint4* H4 = (uint4*)H;
    size_t base = (size_t)gw * 32 + lane;
    uint4 hv = H4[base];
    float2 f0 = unpack_h2(hv.x), f1 = unpack_h2(hv.y);
    float2 f2 = unpack_h2(hv.z), f3 = unpack_h2(hv.w);
    hv.x = pack_h2(fmaxf(f0.x + acc[0], 0.f), fmaxf(f0.y + acc[1], 0.f));
    hv.y = pack_h2(fmaxf(f1.x + acc[2], 0.f), fmaxf(f1.y + acc[3], 0.f));
    hv.z = pack_h2(fmaxf(f2.x + acc[4], 0.f), fmaxf(f2.y + acc[5], 0.f));
    hv.w = pack_h2(fmaxf(f3.x + acc[6], 0.f), fmaxf(f3.y + acc[7], 0.f));
    H4[base] = hv;
}

// ---------------- head (inputs already relu'd, fp16) -------------------------
__global__ __launch_bounds__(256)
void head_kernel(const float* __restrict__ Wl, const float* __restrict__ bl,
                 float* __restrict__ out) {
    __shared__ float sW[768 * NC];
    int tid = threadIdx.x;
    for (int i = tid; i < 768 * NC; i += blockDim.x) sW[i] = Wl[i];
    __syncthreads();

    int lane = tid & 31;
    int node = blockIdx.x * (blockDim.x >> 5) + (tid >> 5);
    if (node >= NN) return;

    const uint32_t* h1 = g_h1 + (size_t)node * 128;
    const uint32_t* h2 = g_h2 + (size_t)node * 128;
    const uint32_t* h3 = g_h3 + (size_t)node * 128;

    float acc[NC];
#pragma unroll
    for (int c = 0; c < NC; c++) acc[c] = 0.f;

    for (int kk = lane; kk < 128; kk += 32) {
        float2 v1 = unpack_h2(h1[kk]);
        float2 v2 = unpack_h2(h2[kk]);
        float2 v3 = unpack_h2(h3[kk]);
        int k = kk * 2;
#pragma unroll
        for (int c = 0; c < NC; c++)
            acc[c] += v1.x * sW[k * NC + c]           + v1.y * sW[(k + 1) * NC + c]
                    + v2.x * sW[(256 + k) * NC + c]   + v2.y * sW[(257 + k) * NC + c]
                    + v3.x * sW[(512 + k) * NC + c]   + v3.y * sW[(513 + k) * NC + c];
    }
#pragma unroll
    for (int c = 0; c < NC; c++)
        for (int off = 16; off > 0; off >>= 1)
            acc[c] += __shfl_down_sync(0xffffffffu, acc[c], off);

    if (lane == 0) {
        float lg[NC], mx = -1e30f;
#pragma unroll
        for (int c = 0; c < NC; c++) { lg[c] = acc[c] + bl[c]; mx = fmaxf(mx, lg[c]); }
        float s = 0.f;
#pragma unroll
        for (int c = 0; c < NC; c++) s += expf(lg[c] - mx);
        float lse = mx + logf(s);
#pragma unroll
        for (int c = 0; c < NC; c++) out[(size_t)node * NC + c] = lg[c] - lse;
    }
}

// ---------------------------------------------------------------------------
extern "C" void kernel_launch(void* const* d_in, const int* in_sizes, int n_in,
                              void* d_out, int out_size) {
    const float* x  = (const float*)d_in[0];
    const int*   ei = (const int*)d_in[1];
    const float* ew = (const float*)d_in[2];
    const float* W1 = (const float*)d_in[3];
    const float* b1 = (const float*)d_in[4];
    const float* W2 = (const float*)d_in[5];
    const float* b2 = (const float*)d_in[6];
    const float* W3 = (const float*)d_in[7];
    const float* b3 = (const float*)d_in[8];
    const float* Wl = (const float*)d_in[9];
    const float* bl = (const float*)d_in[10];
    float* out = (float*)d_out;

    const int* src = ei;
    const int* dst = ei + NE;

    uint32_t *h1, *h2, *h3, *q;
    __half *w1t, *w2t, *w3t;
    cudaGetSymbolAddress((void**)&h1,  g_h1);
    cudaGetSymbolAddress((void**)&h2,  g_h2);
    cudaGetSymbolAddress((void**)&h3,  g_h3);
    cudaGetSymbolAddress((void**)&q,   g_q);
    cudaGetSymbolAddress((void**)&w1t, g_w1t);
    cudaGetSymbolAddress((void**)&w2t, g_w2t);
    cudaGetSymbolAddress((void**)&w3t, g_w3t);

    cudaFuncSetAttribute(gemm_f32A, cudaFuncAttributeMaxDynamicSharedMemorySize, SMEM_F32A);
    cudaFuncSetAttribute(gemm_f16A, cudaFuncAttributeMaxDynamicSharedMemorySize, SMEM_F16A);

    const int T = 256;
    dim3 gemm_grid(2, (NN + 63) / 64);     // 2 x 1395
    const int node_warps = (NN + 7) / 8;
    const int wtot = W1TN + 2 * W2TN;

    zero_cnt<<<NBLK, SCAN_T>>>();                                    // 0
    count_kernel<<<(NE + T - 1) / T, T>>>(dst);                      // 1
    cvt_wt<<<(wtot + T - 1) / T, T>>>(W1, W2, W3);                   // 2
    gemm_f32A<<<gemm_grid, T, SMEM_F32A>>>(x, F0, F0, KP1, w1t, b1, h1, q); // 3 <- profiled
    scanA<<<NBLK, SCAN_T>>>();                                       // 4
    scanB<<<1, 512>>>();                                             // 5
    scanC<<<NBLK, SCAN_T>>>();                                       // 6
    place_kernel<<<(NE + T - 1) / T, T>>>(src, dst, ew);             // 7

    spmm_kernel<<<node_warps, T>>>(q, h1);                           // 8

    gemm_f16A<<<gemm_grid, T, SMEM_F16A>>>((const __half*)h1, w2t, b2, h2, q);
    spmm_kernel<<<node_warps, T>>>(q, h2);

    gemm_f16A<<<gemm_grid, T, SMEM_F16A>>>((const __half*)h2, w3t, b3, h3, q);
    spmm_kernel<<<node_warps, T>>>(q, h3);

    head_kernel<<<(NN + 7) / 8, T>>>(Wl, bl, out);
}

// round 15
// speedup vs baseline: 7.1416x; 1.0069x over previous
#include <cuda_runtime.h>
#include <cuda_fp16.h>
#include <cstdint>

#define NN 89250
#define NE 899756
#define F0 500
#define HID 256
#define NC  7
#define SCAN_T 256
#define NBLK ((NN + SCAN_T - 1) / SCAN_T)   // 349
#define KP1 512                              // layer-1 K padded
#define KP2 256

// ---------------- scratch (device globals) ---------------------------------
// activations stored as fp16x2 (uint32 words): [node][128]
__device__ __align__(256) uint32_t g_h1[(size_t)NN * 128];
__device__ __align__(256) uint32_t g_h2[(size_t)NN * 128];
__device__ __align__(256) uint32_t g_p3[(size_t)NN * 128];  // layer-3 P (pre-agg)
__device__ __align__(256) uint32_t g_q [(size_t)NN * 128];
// transposed fp16 weights: [half(P/Q)][n 0..255][k 0..KP)
__device__ __align__(256) __half g_w1t[2 * 256 * KP1];
__device__ __align__(256) __half g_w2t[2 * 256 * KP2];
__device__ __align__(256) __half g_w3t[2 * 256 * KP2];
__device__ int   g_cnt[NN];
__device__ int   g_row_start[NN];
__device__ int   g_row_fill[NN];
__device__ int   g_bsum[NBLK];
__device__ int   g_csr_src[NE];
__device__ float g_csr_w[NE];

#define W1TN (2 * 256 * KP1)   // 262144
#define W2TN (2 * 256 * KP2)   // 131072

// ---------------- CSR build kernels -----------------------------------------
__global__ void zero_cnt() {
    int i = blockIdx.x * blockDim.x + threadIdx.x;
    if (i < NN) g_cnt[i] = 0;
}
__global__ void count_kernel(const int* __restrict__ dst) {
    int e = blockIdx.x * blockDim.x + threadIdx.x;
    if (e < NE) atomicAdd(&g_cnt[dst[e]], 1);
}
__global__ void scanA() {
    __shared__ int s[SCAN_T];
    int t = threadIdx.x;
    int i = blockIdx.x * SCAN_T + t;
    s[t] = (i < NN) ? g_cnt[i] : 0;
    __syncthreads();
#pragma unroll
    for (int off = SCAN_T / 2; off > 0; off >>= 1) {
        if (t < off) s[t] += s[t + off];
        __syncthreads();
    }
    if (t == 0) g_bsum[blockIdx.x] = s[0];
}
__global__ void scanB() {
    __shared__ int s[512];
    int t = threadIdx.x;
    int v = (t < NBLK) ? g_bsum[t] : 0;
    s[t] = v;
    __syncthreads();
#pragma unroll
    for (int off = 1; off < 512; off <<= 1) {
        int x = (t >= off) ? s[t - off] : 0;
        __syncthreads();
        s[t] += x;
        __syncthreads();
    }
    if (t < NBLK) g_bsum[t] = s[t] - v;   // exclusive
}
__global__ void scanC() {
    __shared__ int s[SCAN_T];
    int t = threadIdx.x;
    int i = blockIdx.x * SCAN_T + t;
    int v = (i < NN) ? g_cnt[i] : 0;
    s[t] = v;
    __syncthreads();
#pragma unroll
    for (int off = 1; off < SCAN_T; off <<= 1) {
        int x = (t >= off) ? s[t - off] : 0;
        __syncthreads();
        s[t] += x;
        __syncthreads();
    }
    if (i < NN) {
        int excl = s[t] - v + g_bsum[blockIdx.x];
        g_row_start[i] = excl;
        g_row_fill[i]  = excl;
    }
}
__global__ void place_kernel(const int* __restrict__ src, const int* __restrict__ dst,
                             const float* __restrict__ ew) {
    int e = blockIdx.x * blockDim.x + threadIdx.x;
    if (e >= NE) return;
    int d = dst[e];
    int slot = atomicAdd(&g_row_fill[d], 1);
    g_csr_src[slot] = src[e];
    g_csr_w[slot]   = ew[e] / fmaxf((float)g_cnt[d], 1.0f);
}

// ---------------- fp16 helpers -----------------------------------------------
__device__ __forceinline__ void mma_fp16(float c[4], const uint32_t a[4],
                                         uint32_t b0, uint32_t b1) {
    asm volatile(
        "mma.sync.aligned.m16n8k16.row.col.f32.f16.f16.f32 "
        "{%0,%1,%2,%3}, {%4,%5,%6,%7}, {%8,%9}, {%0,%1,%2,%3};"
        : "+f"(c[0]), "+f"(c[1]), "+f"(c[2]), "+f"(c[3])
        : "r"(a[0]), "r"(a[1]), "r"(a[2]), "r"(a[3]), "r"(b0), "r"(b1));
}
__device__ __forceinline__ void ldsm4(uint32_t r[4], uint32_t addr) {
    asm volatile("ldmatrix.sync.aligned.m8n8.x4.shared.b16 {%0,%1,%2,%3}, [%4];"
                 : "=r"(r[0]), "=r"(r[1]), "=r"(r[2]), "=r"(r[3]) : "r"(addr));
}
__device__ __forceinline__ void cp16(uint32_t dst, const void* src) {
    asm volatile("cp.async.cg.shared.global [%0], [%1], 16;" :: "r"(dst), "l"(src));
}
__device__ __forceinline__ uint32_t smem_u32(const void* p) {
    uint32_t a;
    asm("{ .reg .u64 t; cvta.to.shared.u64 t, %1; cvt.u32.u64 %0, t; }" : "=r"(a) : "l"(p));
    return a;
}
__device__ __forceinline__ uint32_t pack_h2(float lo, float hi) {
    __half2 t = __floats2half2_rn(lo, hi);
    return *reinterpret_cast<uint32_t*>(&t);
}
__device__ __forceinline__ float2 unpack_h2(uint32_t u) {
    __half2 h = *reinterpret_cast<__half2*>(&u);
    return __half22float2(h);
}

// transpose + fp16-round weights: Wt[half][n][k] = rn(W[half*K + k][n]); K-pad zeros
__global__ void cvt_wt(const float* __restrict__ W1, const float* __restrict__ W2,
                       const float* __restrict__ W3) {
    int i = blockIdx.x * blockDim.x + threadIdx.x;
    if (i < W1TN) {
        int half_ = i >> 17;
        int rem  = i & 131071;
        int n = rem >> 9, k = rem & 511;
        g_w1t[i] = (k < F0) ? __float2half_rn(W1[((size_t)half_ * F0 + k) * 256 + n])
                            : __float2half_rn(0.f);
    } else if (i < W1TN + W2TN) {
        int j = i - W1TN;
        int half_ = j >> 16;
        int rem  = j & 65535;
        int n = rem >> 8, k = rem & 255;
        g_w2t[j] = __float2half_rn(W2[((size_t)half_ * HID + k) * 256 + n]);
    } else if (i < W1TN + 2 * W2TN) {
        int j = i - W1TN - W2TN;
        int half_ = j >> 16;
        int rem  = j & 65535;
        int n = rem >> 8, k = rem & 255;
        g_w3t[j] = __float2half_rn(W3[((size_t)half_ * HID + k) * 256 + n]);
    }
}

// ---------------- shared GEMM config -----------------------------------------
#define AS_ROWB   80                         // bytes per A/B smem row (64 data + 16 pad)
#define A_STAGEB  (64 * AS_ROWB)             // 5120 B
#define B_STAGEB  (256 * AS_ROWB)            // 20480 B
#define SMEM_F32A (2 * A_STAGEB + 4 * B_STAGEB)   // 92160 B
#define SMEM_F16A (4 * A_STAGEB + 4 * B_STAGEB)   // 102400 B

// ---------------- layer-1 GEMM: fp32 A (register-staged), fp16 out ----------
__global__ __launch_bounds__(256, 2)
void gemm_f32A(const float* __restrict__ A, int K, int lda, int KP,
               const __half* __restrict__ Wt, const float* __restrict__ bias,
               uint32_t* __restrict__ Hq, uint32_t* __restrict__ Qb)
{
    extern __shared__ char sm[];
    const uint32_t sb  = smem_u32(sm);
    const uint32_t sbB = sb + 2 * A_STAGEB;

    const int bx = blockIdx.x;
    const int bm = blockIdx.y * 64;
    const __half* Wsel = Wt + (size_t)bx * 256 * KP;

    const int tid  = threadIdx.x;
    const int wid  = tid >> 5;
    const int lane = tid & 31;
    const int wm = (wid >> 2) * 32;
    const int wn = (wid & 3) * 64;
    const int r0 = lane >> 2, c0 = lane & 3;

    const int a_roff = (lane & 7) + ((lane >> 3) & 1) * 8;
    const int a_kb   = ((lane >> 4) & 1) * 16;
    const int b_roff = (lane & 7) + ((lane >> 4) & 1) * 8;
    const int b_kb   = ((lane >> 3) & 1) * 16;

    const int a_row = tid >> 2;
    const int a_k8  = (tid & 3) * 8;
    const int KT = KP / 32;

    float acc[2][8][4];
#pragma unroll
    for (int mi = 0; mi < 2; mi++)
#pragma unroll
        for (int ni = 0; ni < 8; ni++)
#pragma unroll
            for (int c = 0; c < 4; c++) acc[mi][ni][c] = 0.f;

    auto loadB = [&](int s) {
        const int buf = s & 3;
        const int k0  = s * 32;
#pragma unroll
        for (int i = 0; i < 4; i++) {
            int c = tid + i * 256;
            int n = c >> 2, kc = (c & 3) * 8;
            uint32_t dst = sbB + buf * B_STAGEB + n * AS_ROWB + kc * 2;
            cp16(dst, Wsel + (size_t)n * KP + k0 + kc);
        }
    };
    float4 rA0, rA1;
    auto ldgA = [&](int s) {
        int gk = s * 32 + a_k8;
        int gr = bm + a_row;
        rA0 = make_float4(0.f, 0.f, 0.f, 0.f);
        rA1 = make_float4(0.f, 0.f, 0.f, 0.f);
        if (gr < NN) {
            if (gk < K)     rA0 = *(const float4*)(A + (size_t)gr * lda + gk);
            if (gk + 4 < K) rA1 = *(const float4*)(A + (size_t)gr * lda + gk + 4);
        }
    };
    auto stsA = [&](int s) {
        uint32_t dst = sb + (s & 1) * A_STAGEB + a_row * AS_ROWB + a_k8 * 2;
        uint4 v;
        v.x = pack_h2(rA0.x, rA0.y); v.y = pack_h2(rA0.z, rA0.w);
        v.z = pack_h2(rA1.x, rA1.y); v.w = pack_h2(rA1.z, rA1.w);
        asm volatile("st.shared.v4.b32 [%0], {%1,%2,%3,%4};"
                     :: "r"(dst), "r"(v.x), "r"(v.y), "r"(v.z), "r"(v.w));
    };

    loadB(0); asm volatile("cp.async.commit_group;" ::: "memory");
    loadB(1); asm volatile("cp.async.commit_group;" ::: "memory");
    loadB(2); asm volatile("cp.async.commit_group;" ::: "memory");
    ldgA(0); stsA(0);
    ldgA(1);
    asm volatile("cp.async.wait_group 2;" ::: "memory");   // B0 ready
    __syncthreads();

    for (int s = 0; s < KT; s++) {
        if (s + 1 < KT) stsA(s + 1);
        if (s + 2 < KT) ldgA(s + 2);
        if (s + 3 < KT) loadB(s + 3);
        asm volatile("cp.async.commit_group;" ::: "memory");

        const uint32_t aB = sb  + (s & 1) * A_STAGEB;
        const uint32_t bB = sbB + (s & 3) * B_STAGEB;
#pragma unroll
        for (int ks = 0; ks < 2; ks++) {
            const int kb = ks * 32;
            uint32_t af[2][4], bfr[16];
#pragma unroll
            for (int mi = 0; mi < 2; mi++)
                ldsm4(af[mi], aB + (wm + mi * 16 + a_roff) * AS_ROWB + kb + a_kb);
#pragma unroll
            for (int nip = 0; nip < 4; nip++)
                ldsm4(&bfr[nip * 4],
                      bB + (wn + nip * 16 + b_roff) * AS_ROWB + kb + b_kb);
#pragma unroll
            for (int mi = 0; mi < 2; mi++)
#pragma unroll
                for (int nip = 0; nip < 4; nip++) {
                    mma_fp16(acc[mi][nip * 2 + 0], af[mi], bfr[nip * 4 + 0], bfr[nip * 4 + 1]);
                    mma_fp16(acc[mi][nip * 2 + 1], af[mi], bfr[nip * 4 + 2], bfr[nip * 4 + 3]);
                }
        }

        if (s + 1 < KT) asm volatile("cp.async.wait_group 2;" ::: "memory");
        __syncthreads();
    }

    uint32_t* OUT = (bx == 0) ? Hq : Qb;
    float2 b2[8];
    if (bx == 0) {
#pragma unroll
        for (int ni = 0; ni < 8; ni++) {
            int col = wn + ni * 8 + c0 * 2;
            b2[ni].x = bias[col]; b2[ni].y = bias[col + 1];
        }
    }
#pragma unroll
    for (int mi = 0; mi < 2; mi++) {
#pragma unroll
        for (int ci = 0; ci < 2; ci++) {
            int row = bm + wm + mi * 16 + r0 + ci * 8;
            if (row >= NN) continue;
#pragma unroll
            for (int ni = 0; ni < 8; ni++) {
                int col = wn + ni * 8 + c0 * 2;
                float vx = acc[mi][ni][ci * 2 + 0];
                float vy = acc[mi][ni][ci * 2 + 1];
                if (bx == 0) { vx += b2[ni].x; vy += b2[ni].y; }
                OUT[(size_t)row * 128 + (col >> 1)] = pack_h2(vx, vy);
            }
        }
    }
}

// ---------------- layers 2/3 GEMM: fp16 A via pure cp.async ------------------
__global__ __launch_bounds__(256, 2)
void gemm_f16A(const __half* __restrict__ A,   // [NN][256] fp16
               const __half* __restrict__ Wt, const float* __restrict__ bias,
               uint32_t* __restrict__ Hq, uint32_t* __restrict__ Qb)
{
    extern __shared__ char sm[];
    const uint32_t sb  = smem_u32(sm);
    const uint32_t sbB = sb + 4 * A_STAGEB;
    const int KP = KP2;                      // 256

    const int bx = blockIdx.x;
    const int bm = blockIdx.y * 64;
    const __half* Wsel = Wt + (size_t)bx * 256 * KP;

    const int tid  = threadIdx.x;
    const int wid  = tid >> 5;
    const int lane = tid & 31;
    const int wm = (wid >> 2) * 32;
    const int wn = (wid & 3) * 64;
    const int r0 = lane >> 2, c0 = lane & 3;

    const int a_roff = (lane & 7) + ((lane >> 3) & 1) * 8;
    const int a_kb   = ((lane >> 4) & 1) * 16;
    const int b_roff = (lane & 7) + ((lane >> 4) & 1) * 8;
    const int b_kb   = ((lane >> 3) & 1) * 16;
    const int KT = KP / 32;                  // 8

    float acc[2][8][4];
#pragma unroll
    for (int mi = 0; mi < 2; mi++)
#pragma unroll
        for (int ni = 0; ni < 8; ni++)
#pragma unroll
            for (int c = 0; c < 4; c++) acc[mi][ni][c] = 0.f;

    auto loadStage = [&](int s) {
        const int buf = s & 3;
        const int k0  = s * 32;
        {
            int r = tid >> 2, kc = (tid & 3) * 8;
            uint32_t dst = sb + buf * A_STAGEB + r * AS_ROWB + kc * 2;
            int gr = bm + r;
            if (gr < NN) cp16(dst, A + (size_t)gr * 256 + k0 + kc);
            else asm volatile("st.shared.v4.b32 [%0], {%1,%1,%1,%1};"
                              :: "r"(dst), "r"(0u));
        }
#pragma unroll
        for (int i = 0; i < 4; i++) {
            int c = tid + i * 256;
            int n = c >> 2, kc = (c & 3) * 8;
            uint32_t dst = sbB + buf * B_STAGEB + n * AS_ROWB + kc * 2;
            cp16(dst, Wsel + (size_t)n * KP + k0 + kc);
        }
    };

    loadStage(0); asm volatile("cp.async.commit_group;" ::: "memory");
    loadStage(1); asm volatile("cp.async.commit_group;" ::: "memory");
    loadStage(2); asm volatile("cp.async.commit_group;" ::: "memory");
    asm volatile("cp.async.wait_group 2;" ::: "memory");
    __syncthreads();

    for (int s = 0; s < KT; s++) {
        if (s + 3 < KT) loadStage(s + 3);
        asm volatile("cp.async.commit_group;" ::: "memory");

        const uint32_t aB = sb  + (s & 3) * A_STAGEB;
        const uint32_t bB = sbB + (s & 3) * B_STAGEB;
#pragma unroll
        for (int ks = 0; ks < 2; ks++) {
            const int kb = ks * 32;
            uint32_t af[2][4], bfr[16];
#pragma unroll
            for (int mi = 0; mi < 2; mi++)
                ldsm4(af[mi], aB + (wm + mi * 16 + a_roff) * AS_ROWB + kb + a_kb);
#pragma unroll
            for (int nip = 0; nip < 4; nip++)
                ldsm4(&bfr[nip * 4],
                      bB + (wn + nip * 16 + b_roff) * AS_ROWB + kb + b_kb);
#pragma unroll
            for (int mi = 0; mi < 2; mi++)
#pragma unroll
                for (int nip = 0; nip < 4; nip++) {
                    mma_fp16(acc[mi][nip * 2 + 0], af[mi], bfr[nip * 4 + 0], bfr[nip * 4 + 1]);
                    mma_fp16(acc[mi][nip * 2 + 1], af[mi], bfr[nip * 4 + 2], bfr[nip * 4 + 3]);
                }
        }

        if (s + 1 < KT) asm volatile("cp.async.wait_group 2;" ::: "memory");
        __syncthreads();
    }

    uint32_t* OUT = (bx == 0) ? Hq : Qb;
    float2 b2[8];
    if (bx == 0) {
#pragma unroll
        for (int ni = 0; ni < 8; ni++) {
            int col = wn + ni * 8 + c0 * 2;
            b2[ni].x = bias[col]; b2[ni].y = bias[col + 1];
        }
    }
#pragma unroll
    for (int mi = 0; mi < 2; mi++) {
#pragma unroll
        for (int ci = 0; ci < 2; ci++) {
            int row = bm + wm + mi * 16 + r0 + ci * 8;
            if (row >= NN) continue;
#pragma unroll
            for (int ni = 0; ni < 8; ni++) {
                int col = wn + ni * 8 + c0 * 2;
                float vx = acc[mi][ni][ci * 2 + 0];
                float vy = acc[mi][ni][ci * 2 + 1];
                if (bx == 0) { vx += b2[ni].x; vy += b2[ni].y; }
                OUT[(size_t)row * 128 + (col >> 1)] = pack_h2(vx, vy);
            }
        }
    }
}

// ---------------- gather SpMM (layers 1/2): H = relu(H + sum w*Q[src]) ------
__global__ __launch_bounds__(256)
void spmm_kernel(const uint32_t* __restrict__ Q, uint32_t* __restrict__ H) {
    int gw   = (blockIdx.x * blockDim.x + threadIdx.x) >> 5;
    int lane = threadIdx.x & 31;
    if (gw >= NN) return;
    int beg = g_row_start[gw];
    int end = beg + g_cnt[gw];

    const uint4* Q4 = (const uint4*)Q;       // row = 32 uint4
    float acc[8];
#pragma unroll
    for (int i = 0; i < 8; i++) acc[i] = 0.f;

#define ACCUM(u, w, o) { float2 f = unpack_h2(u); acc[o] += (w) * f.x; acc[o+1] += (w) * f.y; }

    int j = beg;
    for (; j + 4 <= end; j += 4) {
        int   s0 = g_csr_src[j],     s1 = g_csr_src[j + 1];
        int   s2 = g_csr_src[j + 2], s3 = g_csr_src[j + 3];
        float w0 = g_csr_w[j],       w1 = g_csr_w[j + 1];
        float w2 = g_csr_w[j + 2],   w3 = g_csr_w[j + 3];
        uint4 a = Q4[(size_t)s0 * 32 + lane];
        uint4 b = Q4[(size_t)s1 * 32 + lane];
        uint4 c = Q4[(size_t)s2 * 32 + lane];
        uint4 d = Q4[(size_t)s3 * 32 + lane];
        ACCUM(a.x, w0, 0) ACCUM(a.y, w0, 2) ACCUM(a.z, w0, 4) ACCUM(a.w, w0, 6)
        ACCUM(b.x, w1, 0) ACCUM(b.y, w1, 2) ACCUM(b.z, w1, 4) ACCUM(b.w, w1, 6)
        ACCUM(c.x, w2, 0) ACCUM(c.y, w2, 2) ACCUM(c.z, w2, 4) ACCUM(c.w, w2, 6)
        ACCUM(d.x, w3, 0) ACCUM(d.y, w3, 2) ACCUM(d.z, w3, 4) ACCUM(d.w, w3, 6)
    }
    for (; j < end; j++) {
        int   s0 = g_csr_src[j];
        float w0 = g_csr_w[j];
        uint4 a = Q4[(size_t)s0 * 32 + lane];
        ACCUM(a.x, w0, 0) ACCUM(a.y, w0, 2) ACCUM(a.z, w0, 4) ACCUM(a.w, w0, 6)
    }

    uint4* H4 = (uint4*)H;
    size_t base = (size_t)gw * 32 + lane;
    uint4 hv = H4[base];
    float2 f0 = unpack_h2(hv.x), f1 = unpack_h2(hv.y);
    float2 f2 = unpack_h2(hv.z), f3 = unpack_h2(hv.w);
    hv.x = pack_h2(fmaxf(f0.x + acc[0], 0.f), fmaxf(f0.y + acc[1], 0.f));
    hv.y = pack_h2(fmaxf(f1.x + acc[2], 0.f), fmaxf(f1.y + acc[3], 0.f));
    hv.z = pack_h2(fmaxf(f2.x + acc[4], 0.f), fmaxf(f2.y + acc[5], 0.f));
    hv.w = pack_h2(fmaxf(f3.x + acc[6], 0.f), fmaxf(f3.y + acc[7], 0.f));
    H4[base] = hv;
}

// ---------------- fused spmm3 + head ----------------------------------------
// h3 = relu(P3 + agg) stays in registers; logits = [h1|h2|h3]@Wl + bl; log_softmax.
__global__ __launch_bounds__(256)
void spmm3_head(const uint32_t* __restrict__ Q, const uint32_t* __restrict__ P3,
                const float* __restrict__ Wl, const float* __restrict__ bl,
                float* __restrict__ out) {
    __shared__ float sW[768 * NC];
    int tid = threadIdx.x;
    for (int i = tid; i < 768 * NC; i += blockDim.x) sW[i] = Wl[i];
    __syncthreads();

    int gw   = (blockIdx.x * blockDim.x + tid) >> 5;
    int lane = tid & 31;
    if (gw >= NN) return;
    int beg = g_row_start[gw];
    int end = beg + g_cnt[gw];

    const uint4* Q4 = (const uint4*)Q;
    float acc[8];
#pragma unroll
    for (int i = 0; i < 8; i++) acc[i] = 0.f;

    int j = beg;
    for (; j + 4 <= end; j += 4) {
        int   s0 = g_csr_src[j],     s1 = g_csr_src[j + 1];
        int   s2 = g_csr_src[j + 2], s3 = g_csr_src[j + 3];
        float w0 = g_csr_w[j],       w1 = g_csr_w[j + 1];
        float w2 = g_csr_w[j + 2],   w3 = g_csr_w[j + 3];
        uint4 a = Q4[(size_t)s0 * 32 + lane];
        uint4 b = Q4[(size_t)s1 * 32 + lane];
        uint4 c = Q4[(size_t)s2 * 32 + lane];
        uint4 d = Q4[(size_t)s3 * 32 + lane];
        ACCUM(a.x, w0, 0) ACCUM(a.y, w0, 2) ACCUM(a.z, w0, 4) ACCUM(a.w, w0, 6)
        ACCUM(b.x, w1, 0) ACCUM(b.y, w1, 2) ACCUM(b.z, w1, 4) ACCUM(b.w, w1, 6)
        ACCUM(c.x, w2, 0) ACCUM(c.y, w2, 2) ACCUM(c.z, w2, 4) ACCUM(c.w, w2, 6)
        ACCUM(d.x, w3, 0) ACCUM(d.y, w3, 2) ACCUM(d.z, w3, 4) ACCUM(d.w, w3, 6)
    }
    for (; j < end; j++) {
        int   s0 = g_csr_src[j];
        float w0 = g_csr_w[j];
        uint4 a = Q4[(size_t)s0 * 32 + lane];
        ACCUM(a.x, w0, 0) ACCUM(a.y, w0, 2) ACCUM(a.z, w0, 4) ACCUM(a.w, w0, 6)
    }
#undef ACCUM

    // h3 (this lane's 8 values, fp32): relu(P3 + acc)
    const uint4* P34 = (const uint4*)P3;
    size_t base = (size_t)gw * 32 + lane;
    uint4 pv = P34[base];
    float h3v[8];
    {
        float2 f0 = unpack_h2(pv.x), f1 = unpack_h2(pv.y);
        float2 f2 = unpack_h2(pv.z), f3 = unpack_h2(pv.w);
        h3v[0] = fmaxf(f0.x + acc[0], 0.f); h3v[1] = fmaxf(f0.y + acc[1], 0.f);
        h3v[2] = fmaxf(f1.x + acc[2], 0.f); h3v[3] = fmaxf(f1.y + acc[3], 0.f);
        h3v[4] = fmaxf(f2.x + acc[4], 0.f); h3v[5] = fmaxf(f2.y + acc[5], 0.f);
        h3v[6] = fmaxf(f3.x + acc[6], 0.f); h3v[7] = fmaxf(f3.y + acc[7], 0.f);
    }

    // head: lane owns columns [lane*8, lane*8+8) of each 256-wide block
    uint4 h1v = ((const uint4*)g_h1)[base];
    uint4 h2v = ((const uint4*)g_h2)[base];
    float lacc[NC];
#pragma unroll
    for (int c = 0; c < NC; c++) lacc[c] = 0.f;

    int k0 = lane * 8;
    const uint32_t u1[4] = {h1v.x, h1v.y, h1v.z, h1v.w};
    const uint32_t u2[4] = {h2v.x, h2v.y, h2v.z, h2v.w};
#pragma unroll
    for (int p = 0; p < 4; p++) {
        float2 v1 = unpack_h2(u1[p]);
        float2 v2 = unpack_h2(u2[p]);
        int k = k0 + p * 2;
#pragma unroll
        for (int c = 0; c < NC; c++) {
            lacc[c] += v1.x * sW[k * NC + c]         + v1.y * sW[(k + 1) * NC + c]
                     + v2.x * sW[(256 + k) * NC + c] + v2.y * sW[(257 + k) * NC + c]
                     + h3v[p * 2]     * sW[(512 + k) * NC + c]
                     + h3v[p * 2 + 1] * sW[(513 + k) * NC + c];
        }
    }
#pragma unroll
    for (int c = 0; c < NC; c++)
        for (int off = 16; off > 0; off >>= 1)
            lacc[c] += __shfl_down_sync(0xffffffffu, lacc[c], off);

    if (lane == 0) {
        float lg[NC], mx = -1e30f;
#pragma unroll
        for (int c = 0; c < NC; c++) { lg[c] = lacc[c] + bl[c]; mx = fmaxf(mx, lg[c]); }
        float s = 0.f;
#pragma unroll
        for (int c = 0; c < NC; c++) s += expf(lg[c] - mx);
        float lse = mx + logf(s);
#pragma unroll
        for (int c = 0; c < NC; c++) out[(size_t)gw * NC + c] = lg[c] - lse;
    }
}

// ---------------------------------------------------------------------------
extern "C" void kernel_launch(void* const* d_in, const int* in_sizes, int n_in,
                              void* d_out, int out_size) {
    const float* x  = (const float*)d_in[0];
    const int*   ei = (const int*)d_in[1];
    const float* ew = (const float*)d_in[2];
    const float* W1 = (const float*)d_in[3];
    const float* b1 = (const float*)d_in[4];
    const float* W2 = (const float*)d_in[5];
    const float* b2 = (const float*)d_in[6];
    const float* W3 = (const float*)d_in[7];
    const float* b3 = (const float*)d_in[8];
    const float* Wl = (const float*)d_in[9];
    const float* bl = (const float*)d_in[10];
    float* out = (float*)d_out;

    const int* src = ei;
    const int* dst = ei + NE;

    uint32_t *h1, *h2, *p3, *q;
    __half *w1t, *w2t, *w3t;
    cudaGetSymbolAddress((void**)&h1,  g_h1);
    cudaGetSymbolAddress((void**)&h2,  g_h2);
    cudaGetSymbolAddress((void**)&p3,  g_p3);
    cudaGetSymbolAddress((void**)&q,   g_q);
    cudaGetSymbolAddress((void**)&w1t, g_w1t);
    cudaGetSymbolAddress((void**)&w2t, g_w2t);
    cudaGetSymbolAddress((void**)&w3t, g_w3t);

    cudaFuncSetAttribute(gemm_f32A, cudaFuncAttributeMaxDynamicSharedMemorySize, SMEM_F32A);
    cudaFuncSetAttribute(gemm_f16A, cudaFuncAttributeMaxDynamicSharedMemorySize, SMEM_F16A);

    const int T = 256;
    dim3 gemm_grid(2, (NN + 63) / 64);     // 2 x 1395
    const int node_warps = (NN + 7) / 8;
    const int wtot = W1TN + 2 * W2TN;

    zero_cnt<<<NBLK, SCAN_T>>>();                                    // 0
    count_kernel<<<(NE + T - 1) / T, T>>>(dst);                      // 1
    cvt_wt<<<(wtot + T - 1) / T, T>>>(W1, W2, W3);                   // 2
    gemm_f32A<<<gemm_grid, T, SMEM_F32A>>>(x, F0, F0, KP1, w1t, b1, h1, q); // 3 <- profiled
    scanA<<<NBLK, SCAN_T>>>();                                       // 4
    scanB<<<1, 512>>>();                                             // 5
    scanC<<<NBLK, SCAN_T>>>();                                       // 6
    place_kernel<<<(NE + T - 1) / T, T>>>(src, dst, ew);             // 7

    spmm_kernel<<<node_warps, T>>>(q, h1);                           // 8

    gemm_f16A<<<gemm_grid, T, SMEM_F16A>>>((const __half*)h1, w2t, b2, h2, q);
    spmm_kernel<<<node_warps, T>>>(q, h2);

    gemm_f16A<<<gemm_grid, T, SMEM_F16A>>>((const __half*)h2, w3t, b3, p3, q);
    spmm3_head<<<node_warps, T>>>(q, p3, Wl, bl, out);
}

// round 16
// speedup vs baseline: 7.2659x; 1.0174x over previous
#include <cuda_runtime.h>
#include <cuda_fp16.h>
#include <cstdint>

#define NN 89250
#define NE 899756
#define F0 500
#define HID 256
#define NC  7
#define SCAN_T 256
#define NBLK ((NN + SCAN_T - 1) / SCAN_T)   // 349
#define KP1 512                              // layer-1 K padded
#define KP2 256

// ---------------- scratch (device globals) ---------------------------------
__device__ __align__(256) uint32_t g_h1[(size_t)NN * 128];
__device__ __align__(256) uint32_t g_h2[(size_t)NN * 128];
__device__ __align__(256) uint32_t g_p3[(size_t)NN * 128];  // layer-3 P (pre-agg)
__device__ __align__(256) uint32_t g_q [(size_t)NN * 128];
__device__ __align__(256) __half g_w1t[2 * 256 * KP1];
__device__ __align__(256) __half g_w2t[2 * 256 * KP2];
__device__ __align__(256) __half g_w3t[2 * 256 * KP2];
__device__ int   g_cnt[NN];
__device__ int   g_row_start[NN];
__device__ int   g_row_fill[NN];
__device__ int   g_bsum[NBLK];
__device__ int   g_csr_src[NE];
__device__ float g_csr_w[NE];

#define W1TN (2 * 256 * KP1)   // 262144
#define W2TN (2 * 256 * KP2)   // 131072

// ---------------- CSR build kernels -----------------------------------------
__global__ void zero_cnt() {
    int i = blockIdx.x * blockDim.x + threadIdx.x;
    if (i < NN) g_cnt[i] = 0;
}
__global__ void count_kernel(const int* __restrict__ dst) {
    int e = blockIdx.x * blockDim.x + threadIdx.x;
    if (e < NE) atomicAdd(&g_cnt[dst[e]], 1);
}
__global__ void scanA() {
    __shared__ int s[SCAN_T];
    int t = threadIdx.x;
    int i = blockIdx.x * SCAN_T + t;
    s[t] = (i < NN) ? g_cnt[i] : 0;
    __syncthreads();
#pragma unroll
    for (int off = SCAN_T / 2; off > 0; off >>= 1) {
        if (t < off) s[t] += s[t + off];
        __syncthreads();
    }
    if (t == 0) g_bsum[blockIdx.x] = s[0];
}
__global__ void scanB() {
    __shared__ int s[512];
    int t = threadIdx.x;
    int v = (t < NBLK) ? g_bsum[t] : 0;
    s[t] = v;
    __syncthreads();
#pragma unroll
    for (int off = 1; off < 512; off <<= 1) {
        int x = (t >= off) ? s[t - off] : 0;
        __syncthreads();
        s[t] += x;
        __syncthreads();
    }
    if (t < NBLK) g_bsum[t] = s[t] - v;   // exclusive
}
__global__ void scanC() {
    __shared__ int s[SCAN_T];
    int t = threadIdx.x;
    int i = blockIdx.x * SCAN_T + t;
    int v = (i < NN) ? g_cnt[i] : 0;
    s[t] = v;
    __syncthreads();
#pragma unroll
    for (int off = 1; off < SCAN_T; off <<= 1) {
        int x = (t >= off) ? s[t - off] : 0;
        __syncthreads();
        s[t] += x;
        __syncthreads();
    }
    if (i < NN) {
        int excl = s[t] - v + g_bsum[blockIdx.x];
        g_row_start[i] = excl;
        g_row_fill[i]  = excl;
    }
}
__global__ void place_kernel(const int* __restrict__ src, const int* __restrict__ dst,
                             const float* __restrict__ ew) {
    int e = blockIdx.x * blockDim.x + threadIdx.x;
    if (e >= NE) return;
    int d = dst[e];
    int slot = atomicAdd(&g_row_fill[d], 1);
    g_csr_src[slot] = src[e];
    g_csr_w[slot]   = ew[e] / fmaxf((float)g_cnt[d], 1.0f);
}

// ---------------- fp16 helpers -----------------------------------------------
__device__ __forceinline__ void mma_fp16(float c[4], const uint32_t a[4],
                                         uint32_t b0, uint32_t b1) {
    asm volatile(
        "mma.sync.aligned.m16n8k16.row.col.f32.f16.f16.f32 "
        "{%0,%1,%2,%3}, {%4,%5,%6,%7}, {%8,%9}, {%0,%1,%2,%3};"
        : "+f"(c[0]), "+f"(c[1]), "+f"(c[2]), "+f"(c[3])
        : "r"(a[0]), "r"(a[1]), "r"(a[2]), "r"(a[3]), "r"(b0), "r"(b1));
}
__device__ __forceinline__ void ldsm4(uint32_t r[4], uint32_t addr) {
    asm volatile("ldmatrix.sync.aligned.m8n8.x4.shared.b16 {%0,%1,%2,%3}, [%4];"
                 : "=r"(r[0]), "=r"(r[1]), "=r"(r[2]), "=r"(r[3]) : "r"(addr));
}
__device__ __forceinline__ void cp16(uint32_t dst, const void* src) {
    asm volatile("cp.async.cg.shared.global [%0], [%1], 16;" :: "r"(dst), "l"(src));
}
__device__ __forceinline__ uint32_t smem_u32(const void* p) {
    uint32_t a;
    asm("{ .reg .u64 t; cvta.to.shared.u64 t, %1; cvt.u32.u64 %0, t; }" : "=r"(a) : "l"(p));
    return a;
}
__device__ __forceinline__ uint32_t pack_h2(float lo, float hi) {
    __half2 t = __floats2half2_rn(lo, hi);
    return *reinterpret_cast<uint32_t*>(&t);
}
__device__ __forceinline__ float2 unpack_h2(uint32_t u) {
    __half2 h = *reinterpret_cast<__half2*>(&u);
    return __half22float2(h);
}

// transpose + fp16-round W1 only (feeds gemm1; stays on main stream)
__global__ void cvt_w1(const float* __restrict__ W1) {
    int i = blockIdx.x * blockDim.x + threadIdx.x;
    if (i < W1TN) {
        int half_ = i >> 17;
        int rem  = i & 131071;
        int n = rem >> 9, k = rem & 511;
        g_w1t[i] = (k < F0) ? __float2half_rn(W1[((size_t)half_ * F0 + k) * 256 + n])
                            : __float2half_rn(0.f);
    }
}
// transpose + fp16-round W2/W3 (side stream; only needed by gemm2/3)
__global__ void cvt_w23(const float* __restrict__ W2, const float* __restrict__ W3) {
    int i = blockIdx.x * blockDim.x + threadIdx.x;
    if (i < W2TN) {
        int half_ = i >> 16;
        int rem  = i & 65535;
        int n = rem >> 8, k = rem & 255;
        g_w2t[i] = __float2half_rn(W2[((size_t)half_ * HID + k) * 256 + n]);
    } else if (i < 2 * W2TN) {
        int j = i - W2TN;
        int half_ = j >> 16;
        int rem  = j & 65535;
        int n = rem >> 8, k = rem & 255;
        g_w3t[j] = __float2half_rn(W3[((size_t)half_ * HID + k) * 256 + n]);
    }
}

// ---------------- shared GEMM config -----------------------------------------
#define AS_ROWB   80
#define A_STAGEB  (64 * AS_ROWB)             // 5120 B
#define B_STAGEB  (256 * AS_ROWB)            // 20480 B
#define SMEM_F32A (2 * A_STAGEB + 4 * B_STAGEB)   // 92160 B
#define SMEM_F16A (4 * A_STAGEB + 4 * B_STAGEB)   // 102400 B

// ---------------- layer-1 GEMM: fp32 A (register-staged), fp16 out ----------
__global__ __launch_bounds__(256, 2)
void gemm_f32A(const float* __restrict__ A, int K, int lda, int KP,
               const __half* __restrict__ Wt, const float* __restrict__ bias,
               uint32_t* __restrict__ Hq, uint32_t* __restrict__ Qb)
{
    extern __shared__ char sm[];
    const uint32_t sb  = smem_u32(sm);
    const uint32_t sbB = sb + 2 * A_STAGEB;

    const int bx = blockIdx.x;
    const int bm = blockIdx.y * 64;
    const __half* Wsel = Wt + (size_t)bx * 256 * KP;

    const int tid  = threadIdx.x;
    const int wid  = tid >> 5;
    const int lane = tid & 31;
    const int wm = (wid >> 2) * 32;
    const int wn = (wid & 3) * 64;
    const int r0 = lane >> 2, c0 = lane & 3;

    const int a_roff = (lane & 7) + ((lane >> 3) & 1) * 8;
    const int a_kb   = ((lane >> 4) & 1) * 16;
    const int b_roff = (lane & 7) + ((lane >> 4) & 1) * 8;
    const int b_kb   = ((lane >> 3) & 1) * 16;

    const int a_row = tid >> 2;
    const int a_k8  = (tid & 3) * 8;
    const int KT = KP / 32;

    float acc[2][8][4];
#pragma unroll
    for (int mi = 0; mi < 2; mi++)
#pragma unroll
        for (int ni = 0; ni < 8; ni++)
#pragma unroll
            for (int c = 0; c < 4; c++) acc[mi][ni][c] = 0.f;

    auto loadB = [&](int s) {
        const int buf = s & 3;
        const int k0  = s * 32;
#pragma unroll
        for (int i = 0; i < 4; i++) {
            int c = tid + i * 256;
            int n = c >> 2, kc = (c & 3) * 8;
            uint32_t dst = sbB + buf * B_STAGEB + n * AS_ROWB + kc * 2;
            cp16(dst, Wsel + (size_t)n * KP + k0 + kc);
        }
    };
    float4 rA0, rA1;
    auto ldgA = [&](int s) {
        int gk = s * 32 + a_k8;
        int gr = bm + a_row;
        rA0 = make_float4(0.f, 0.f, 0.f, 0.f);
        rA1 = make_float4(0.f, 0.f, 0.f, 0.f);
        if (gr < NN) {
            if (gk < K)     rA0 = *(const float4*)(A + (size_t)gr * lda + gk);
            if (gk + 4 < K) rA1 = *(const float4*)(A + (size_t)gr * lda + gk + 4);
        }
    };
    auto stsA = [&](int s) {
        uint32_t dst = sb + (s & 1) * A_STAGEB + a_row * AS_ROWB + a_k8 * 2;
        uint4 v;
        v.x = pack_h2(rA0.x, rA0.y); v.y = pack_h2(rA0.z, rA0.w);
        v.z = pack_h2(rA1.x, rA1.y); v.w = pack_h2(rA1.z, rA1.w);
        asm volatile("st.shared.v4.b32 [%0], {%1,%2,%3,%4};"
                     :: "r"(dst), "r"(v.x), "r"(v.y), "r"(v.z), "r"(v.w));
    };

    loadB(0); asm volatile("cp.async.commit_group;" ::: "memory");
    loadB(1); asm volatile("cp.async.commit_group;" ::: "memory");
    loadB(2); asm volatile("cp.async.commit_group;" ::: "memory");
    ldgA(0); stsA(0);
    ldgA(1);
    asm volatile("cp.async.wait_group 2;" ::: "memory");   // B0 ready
    __syncthreads();

    for (int s = 0; s < KT; s++) {
        if (s + 1 < KT) stsA(s + 1);
        if (s + 2 < KT) ldgA(s + 2);
        if (s + 3 < KT) loadB(s + 3);
        asm volatile("cp.async.commit_group;" ::: "memory");

        const uint32_t aB = sb  + (s & 1) * A_STAGEB;
        const uint32_t bB = sbB + (s & 3) * B_STAGEB;
#pragma unroll
        for (int ks = 0; ks < 2; ks++) {
            const int kb = ks * 32;
            uint32_t af[2][4], bfr[16];
#pragma unroll
            for (int mi = 0; mi < 2; mi++)
                ldsm4(af[mi], aB + (wm + mi * 16 + a_roff) * AS_ROWB + kb + a_kb);
#pragma unroll
            for (int nip = 0; nip < 4; nip++)
                ldsm4(&bfr[nip * 4],
                      bB + (wn + nip * 16 + b_roff) * AS_ROWB + kb + b_kb);
#pragma unroll
            for (int mi = 0; mi < 2; mi++)
#pragma unroll
                for (int nip = 0; nip < 4; nip++) {
                    mma_fp16(acc[mi][nip * 2 + 0], af[mi], bfr[nip * 4 + 0], bfr[nip * 4 + 1]);
                    mma_fp16(acc[mi][nip * 2 + 1], af[mi], bfr[nip * 4 + 2], bfr[nip * 4 + 3]);
                }
        }

        if (s + 1 < KT) asm volatile("cp.async.wait_group 2;" ::: "memory");
        __syncthreads();
    }

    uint32_t* OUT = (bx == 0) ? Hq : Qb;
    float2 b2[8];
    if (bx == 0) {
#pragma unroll
        for (int ni = 0; ni < 8; ni++) {
            int col = wn + ni * 8 + c0 * 2;
            b2[ni].x = bias[col]; b2[ni].y = bias[col + 1];
        }
    }
#pragma unroll
    for (int mi = 0; mi < 2; mi++) {
#pragma unroll
        for (int ci = 0; ci < 2; ci++) {
            int row = bm + wm + mi * 16 + r0 + ci * 8;
            if (row >= NN) continue;
#pragma unroll
            for (int ni = 0; ni < 8; ni++) {
                int col = wn + ni * 8 + c0 * 2;
                float vx = acc[mi][ni][ci * 2 + 0];
                float vy = acc[mi][ni][ci * 2 + 1];
                if (bx == 0) { vx += b2[ni].x; vy += b2[ni].y; }
                OUT[(size_t)row * 128 + (col >> 1)] = pack_h2(vx, vy);
            }
        }
    }
}

// ---------------- layers 2/3 GEMM: fp16 A via pure cp.async ------------------
__global__ __launch_bounds__(256, 2)
void gemm_f16A(const __half* __restrict__ A,   // [NN][256] fp16
               const __half* __restrict__ Wt, const float* __restrict__ bias,
               uint32_t* __restrict__ Hq, uint32_t* __restrict__ Qb)
{
    extern __shared__ char sm[];
    const uint32_t sb  = smem_u32(sm);
    const uint32_t sbB = sb + 4 * A_STAGEB;
    const int KP = KP2;                      // 256

    const int bx = blockIdx.x;
    const int bm = blockIdx.y * 64;
    const __half* Wsel = Wt + (size_t)bx * 256 * KP;

    const int tid  = threadIdx.x;
    const int wid  = tid >> 5;
    const int lane = tid & 31;
    const int wm = (wid >> 2) * 32;
    const int wn = (wid & 3) * 64;
    const int r0 = lane >> 2, c0 = lane & 3;

    const int a_roff = (lane & 7) + ((lane >> 3) & 1) * 8;
    const int a_kb   = ((lane >> 4) & 1) * 16;
    const int b_roff = (lane & 7) + ((lane >> 4) & 1) * 8;
    const int b_kb   = ((lane >> 3) & 1) * 16;
    const int KT = KP / 32;                  // 8

    float acc[2][8][4];
#pragma unroll
    for (int mi = 0; mi < 2; mi++)
#pragma unroll
        for (int ni = 0; ni < 8; ni++)
#pragma unroll
            for (int c = 0; c < 4; c++) acc[mi][ni][c] = 0.f;

    auto loadStage = [&](int s) {
        const int buf = s & 3;
        const int k0  = s * 32;
        {
            int r = tid >> 2, kc = (tid & 3) * 8;
            uint32_t dst = sb + buf * A_STAGEB + r * AS_ROWB + kc * 2;
            int gr = bm + r;
            if (gr < NN) cp16(dst, A + (size_t)gr * 256 + k0 + kc);
            else asm volatile("st.shared.v4.b32 [%0], {%1,%1,%1,%1};"
                              :: "r"(dst), "r"(0u));
        }
#pragma unroll
        for (int i = 0; i < 4; i++) {
            int c = tid + i * 256;
            int n = c >> 2, kc = (c & 3) * 8;
            uint32_t dst = sbB + buf * B_STAGEB + n * AS_ROWB + kc * 2;
            cp16(dst, Wsel + (size_t)n * KP + k0 + kc);
        }
    };

    loadStage(0); asm volatile("cp.async.commit_group;" ::: "memory");
    loadStage(1); asm volatile("cp.async.commit_group;" ::: "memory");
    loadStage(2); asm volatile("cp.async.commit_group;" ::: "memory");
    asm volatile("cp.async.wait_group 2;" ::: "memory");
    __syncthreads();

    for (int s = 0; s < KT; s++) {
        if (s + 3 < KT) loadStage(s + 3);
        asm volatile("cp.async.commit_group;" ::: "memory");

        const uint32_t aB = sb  + (s & 3) * A_STAGEB;
        const uint32_t bB = sbB + (s & 3) * B_STAGEB;
#pragma unroll
        for (int ks = 0; ks < 2; ks++) {
            const int kb = ks * 32;
            uint32_t af[2][4], bfr[16];
#pragma unroll
            for (int mi = 0; mi < 2; mi++)
                ldsm4(af[mi], aB + (wm + mi * 16 + a_roff) * AS_ROWB + kb + a_kb);
#pragma unroll
            for (int nip = 0; nip < 4; nip++)
                ldsm4(&bfr[nip * 4],
                      bB + (wn + nip * 16 + b_roff) * AS_ROWB + kb + b_kb);
#pragma unroll
            for (int mi = 0; mi < 2; mi++)
#pragma unroll
                for (int nip = 0; nip < 4; nip++) {
                    mma_fp16(acc[mi][nip * 2 + 0], af[mi], bfr[nip * 4 + 0], bfr[nip * 4 + 1]);
                    mma_fp16(acc[mi][nip * 2 + 1], af[mi], bfr[nip * 4 + 2], bfr[nip * 4 + 3]);
                }
        }

        if (s + 1 < KT) asm volatile("cp.async.wait_group 2;" ::: "memory");
        __syncthreads();
    }

    uint32_t* OUT = (bx == 0) ? Hq : Qb;
    float2 b2[8];
    if (bx == 0) {
#pragma unroll
        for (int ni = 0; ni < 8; ni++) {
            int col = wn + ni * 8 + c0 * 2;
            b2[ni].x = bias[col]; b2[ni].y = bias[col + 1];
        }
    }
#pragma unroll
    for (int mi = 0; mi < 2; mi++) {
#pragma unroll
        for (int ci = 0; ci < 2; ci++) {
            int row = bm + wm + mi * 16 + r0 + ci * 8;
            if (row >= NN) continue;
#pragma unroll
            for (int ni = 0; ni < 8; ni++) {
                int col = wn + ni * 8 + c0 * 2;
                float vx = acc[mi][ni][ci * 2 + 0];
                float vy = acc[mi][ni][ci * 2 + 1];
                if (bx == 0) { vx += b2[ni].x; vy += b2[ni].y; }
                OUT[(size_t)row * 128 + (col >> 1)] = pack_h2(vx, vy);
            }
        }
    }
}

// ---------------- gather SpMM (layers 1/2): H = relu(H + sum w*Q[src]) ------
__global__ __launch_bounds__(256)
void spmm_kernel(const uint32_t* __restrict__ Q, uint32_t* __restrict__ H) {
    int gw   = (blockIdx.x * blockDim.x + threadIdx.x) >> 5;
    int lane = threadIdx.x & 31;
    if (gw >= NN) return;
    int beg = g_row_start[gw];
    int end = beg + g_cnt[gw];

    const uint4* Q4 = (const uint4*)Q;
    float acc[8];
#pragma unroll
    for (int i = 0; i < 8; i++) acc[i] = 0.f;

#define ACCUM(u, w, o) { float2 f = unpack_h2(u); acc[o] += (w) * f.x; acc[o+1] += (w) * f.y; }

    int j = beg;
    for (; j + 4 <= end; j += 4) {
        int   s0 = g_csr_src[j],     s1 = g_csr_src[j + 1];
        int   s2 = g_csr_src[j + 2], s3 = g_csr_src[j + 3];
        float w0 = g_csr_w[j],       w1 = g_csr_w[j + 1];
        float w2 = g_csr_w[j + 2],   w3 = g_csr_w[j + 3];
        uint4 a = Q4[(size_t)s0 * 32 + lane];
        uint4 b = Q4[(size_t)s1 * 32 + lane];
        uint4 c = Q4[(size_t)s2 * 32 + lane];
        uint4 d = Q4[(size_t)s3 * 32 + lane];
        ACCUM(a.x, w0, 0) ACCUM(a.y, w0, 2) ACCUM(a.z, w0, 4) ACCUM(a.w, w0, 6)
        ACCUM(b.x, w1, 0) ACCUM(b.y, w1, 2) ACCUM(b.z, w1, 4) ACCUM(b.w, w1, 6)
        ACCUM(c.x, w2, 0) ACCUM(c.y, w2, 2) ACCUM(c.z, w2, 4) ACCUM(c.w, w2, 6)
        ACCUM(d.x, w3, 0) ACCUM(d.y, w3, 2) ACCUM(d.z, w3, 4) ACCUM(d.w, w3, 6)
    }
    for (; j < end; j++) {
        int   s0 = g_csr_src[j];
        float w0 = g_csr_w[j];
        uint4 a = Q4[(size_t)s0 * 32 + lane];
        ACCUM(a.x, w0, 0) ACCUM(a.y, w0, 2) ACCUM(a.z, w0, 4) ACCUM(a.w, w0, 6)
    }

    uint4* H4 = (uint4*)H;
    size_t base = (size_t)gw * 32 + lane;
    uint4 hv = H4[base];
    float2 f0 = unpack_h2(hv.x), f1 = unpack_h2(hv.y);
    float2 f2 = unpack_h2(hv.z), f3 = unpack_h2(hv.w);
    hv.x = pack_h2(fmaxf(f0.x + acc[0], 0.f), fmaxf(f0.y + acc[1], 0.f));
    hv.y = pack_h2(fmaxf(f1.x + acc[2], 0.f), fmaxf(f1.y + acc[3], 0.f));
    hv.z = pack_h2(fmaxf(f2.x + acc[4], 0.f), fmaxf(f2.y + acc[5], 0.f));
    hv.w = pack_h2(fmaxf(f3.x + acc[6], 0.f), fmaxf(f3.y + acc[7], 0.f));
    H4[base] = hv;
}

// ---------------- fused spmm3 + head ----------------------------------------
__global__ __launch_bounds__(256)
void spmm3_head(const uint32_t* __restrict__ Q, const uint32_t* __restrict__ P3,
                const float* __restrict__ Wl, const float* __restrict__ bl,
                float* __restrict__ out) {
    __shared__ float sW[768 * NC];
    int tid = threadIdx.x;
    for (int i = tid; i < 768 * NC; i += blockDim.x) sW[i] = Wl[i];
    __syncthreads();

    int gw   = (blockIdx.x * blockDim.x + tid) >> 5;
    int lane = tid & 31;
    if (gw >= NN) return;
    int beg = g_row_start[gw];
    int end = beg + g_cnt[gw];

    const uint4* Q4 = (const uint4*)Q;
    float acc[8];
#pragma unroll
    for (int i = 0; i < 8; i++) acc[i] = 0.f;

    int j = beg;
    for (; j + 4 <= end; j += 4) {
        int   s0 = g_csr_src[j],     s1 = g_csr_src[j + 1];
        int   s2 = g_csr_src[j + 2], s3 = g_csr_src[j + 3];
        float w0 = g_csr_w[j],       w1 = g_csr_w[j + 1];
        float w2 = g_csr_w[j + 2],   w3 = g_csr_w[j + 3];
        uint4 a = Q4[(size_t)s0 * 32 + lane];
        uint4 b = Q4[(size_t)s1 * 32 + lane];
        uint4 c = Q4[(size_t)s2 * 32 + lane];
        uint4 d = Q4[(size_t)s3 * 32 + lane];
        ACCUM(a.x, w0, 0) ACCUM(a.y, w0, 2) ACCUM(a.z, w0, 4) ACCUM(a.w, w0, 6)
        ACCUM(b.x, w1, 0) ACCUM(b.y, w1, 2) ACCUM(b.z, w1, 4) ACCUM(b.w, w1, 6)
        ACCUM(c.x, w2, 0) ACCUM(c.y, w2, 2) ACCUM(c.z, w2, 4) ACCUM(c.w, w2, 6)
        ACCUM(d.x, w3, 0) ACCUM(d.y, w3, 2) ACCUM(d.z, w3, 4) ACCUM(d.w, w3, 6)
    }
    for (; j < end; j++) {
        int   s0 = g_csr_src[j];
        float w0 = g_csr_w[j];
        uint4 a = Q4[(size_t)s0 * 32 + lane];
        ACCUM(a.x, w0, 0) ACCUM(a.y, w0, 2) ACCUM(a.z, w0, 4) ACCUM(a.w, w0, 6)
    }
#undef ACCUM

    const uint4* P34 = (const uint4*)P3;
    size_t base = (size_t)gw * 32 + lane;
    uint4 pv = P34[base];
    float h3v[8];
    {
        float2 f0 = unpack_h2(pv.x), f1 = unpack_h2(pv.y);
        float2 f2 = unpack_h2(pv.z), f3 = unpack_h2(pv.w);
        h3v[0] = fmaxf(f0.x + acc[0], 0.f); h3v[1] = fmaxf(f0.y + acc[1], 0.f);
        h3v[2] = fmaxf(f1.x + acc[2], 0.f); h3v[3] = fmaxf(f1.y + acc[3], 0.f);
        h3v[4] = fmaxf(f2.x + acc[4], 0.f); h3v[5] = fmaxf(f2.y + acc[5], 0.f);
        h3v[6] = fmaxf(f3.x + acc[6], 0.f); h3v[7] = fmaxf(f3.y + acc[7], 0.f);
    }

    uint4 h1v = ((const uint4*)g_h1)[base];
    uint4 h2v = ((const uint4*)g_h2)[base];
    float lacc[NC];
#pragma unroll
    for (int c = 0; c < NC; c++) lacc[c] = 0.f;

    int k0 = lane * 8;
    const uint32_t u1[4] = {h1v.x, h1v.y, h1v.z, h1v.w};
    const uint32_t u2[4] = {h2v.x, h2v.y, h2v.z, h2v.w};
#pragma unroll
    for (int p = 0; p < 4; p++) {
        float2 v1 = unpack_h2(u1[p]);
        float2 v2 = unpack_h2(u2[p]);
        int k = k0 + p * 2;
#pragma unroll
        for (int c = 0; c < NC; c++) {
            lacc[c] += v1.x * sW[k * NC + c]         + v1.y * sW[(k + 1) * NC + c]
                     + v2.x * sW[(256 + k) * NC + c] + v2.y * sW[(257 + k) * NC + c]
                     + h3v[p * 2]     * sW[(512 + k) * NC + c]
                     + h3v[p * 2 + 1] * sW[(513 + k) * NC + c];
        }
    }
#pragma unroll
    for (int c = 0; c < NC; c++)
        for (int off = 16; off > 0; off >>= 1)
            lacc[c] += __shfl_down_sync(0xffffffffu, lacc[c], off);

    if (lane == 0) {
        float lg[NC], mx = -1e30f;
#pragma unroll
        for (int c = 0; c < NC; c++) { lg[c] = lacc[c] + bl[c]; mx = fmaxf(mx, lg[c]); }
        float s = 0.f;
#pragma unroll
        for (int c = 0; c < NC; c++) s += expf(lg[c] - mx);
        float lse = mx + logf(s);
#pragma unroll
        for (int c = 0; c < NC; c++) out[(size_t)gw * NC + c] = lg[c] - lse;
    }
}

// ---------------------------------------------------------------------------
extern "C" void kernel_launch(void* const* d_in, const int* in_sizes, int n_in,
                              void* d_out, int out_size) {
    const float* x  = (const float*)d_in[0];
    const int*   ei = (const int*)d_in[1];
    const float* ew = (const float*)d_in[2];
    const float* W1 = (const float*)d_in[3];
    const float* b1 = (const float*)d_in[4];
    const float* W2 = (const float*)d_in[5];
    const float* b2 = (const float*)d_in[6];
    const float* W3 = (const float*)d_in[7];
    const float* b3 = (const float*)d_in[8];
    const float* Wl = (const float*)d_in[9];
    const float* bl = (const float*)d_in[10];
    float* out = (float*)d_out;

    const int* src = ei;
    const int* dst = ei + NE;

    uint32_t *h1, *h2, *p3, *q;
    __half *w1t, *w2t, *w3t;
    cudaGetSymbolAddress((void**)&h1,  g_h1);
    cudaGetSymbolAddress((void**)&h2,  g_h2);
    cudaGetSymbolAddress((void**)&p3,  g_p3);
    cudaGetSymbolAddress((void**)&q,   g_q);
    cudaGetSymbolAddress((void**)&w1t, g_w1t);
    cudaGetSymbolAddress((void**)&w2t, g_w2t);
    cudaGetSymbolAddress((void**)&w3t, g_w3t);

    cudaFuncSetAttribute(gemm_f32A, cudaFuncAttributeMaxDynamicSharedMemorySize, SMEM_F32A);
    cudaFuncSetAttribute(gemm_f16A, cudaFuncAttributeMaxDynamicSharedMemorySize, SMEM_F16A);

    // one-time side stream + fork/join events (created on first, non-captured call)
    static cudaStream_t s2 = nullptr;
    static cudaEvent_t evFork = nullptr, evJoin = nullptr;
    if (s2 == nullptr) {
        cudaStreamCreateWithFlags(&s2, cudaStreamNonBlocking);
        cudaEventCreateWithFlags(&evFork, cudaEventDisableTiming);
        cudaEventCreateWithFlags(&evJoin, cudaEventDisableTiming);
    }

    const int T = 256;
    dim3 gemm_grid(2, (NN + 63) / 64);     // 2 x 1395
    const int node_warps = (NN + 7) / 8;

    // ---- fork: CSR build + w2/w3 conversion run concurrently with gemm1 ----
    cudaEventRecord(evFork, 0);
    cudaStreamWaitEvent(s2, evFork, 0);

    zero_cnt<<<NBLK, SCAN_T, 0, s2>>>();                               // k0 (s2)
    count_kernel<<<(NE + T - 1) / T, T, 0, s2>>>(dst);                 // k1 (s2)

    cvt_w1<<<(W1TN + T - 1) / T, T>>>(W1);                             // k2 (main)
    gemm_f32A<<<gemm_grid, T, SMEM_F32A>>>(x, F0, F0, KP1, w1t, b1, h1, q); // k3 (main)

    scanA<<<NBLK, SCAN_T, 0, s2>>>();                                  // (s2)
    scanB<<<1, 512, 0, s2>>>();                                        // (s2)
    scanC<<<NBLK, SCAN_T, 0, s2>>>();                                  // (s2)
    place_kernel<<<(NE + T - 1) / T, T, 0, s2>>>(src, dst, ew);        // (s2)
    cvt_w23<<<(2 * W2TN + T - 1) / T, T, 0, s2>>>(W2, W3);             // (s2)
    cudaEventRecord(evJoin, s2);

    // ---- join: everything below needs CSR (+ w2t/w3t) ----
    cudaStreamWaitEvent(0, evJoin, 0);

    spmm_kernel<<<node_warps, T>>>(q, h1);

    gemm_f16A<<<gemm_grid, T, SMEM_F16A>>>((const __half*)h1, w2t, b2, h2, q);
    spmm_kernel<<<node_warps, T>>>(q, h2);

    gemm_f16A<<<gemm_grid, T, SMEM_F16A>>>((const __half*)h2, w3t, b3, p3, q);
    spmm3_head<<<node_warps, T>>>(q, p3, Wl, bl, out);
}